// round 1
// baseline (speedup 1.0000x reference)
#include <cuda_runtime.h>
#include <math_constants.h>

// Problem constants
#define NTOK 2048
#define BSZ  2
#define EMB  1024
#define NH   16
#define HD   64
#define MROWS (NTOK*BSZ)      // 4096
#define F3   (3*EMB)          // 3072

// Scratch (device globals: allocation-free per harness rules)
__device__ float g_qkv[(size_t)MROWS * F3];   // (t*BSZ+b) x 3072, f = comp*1024 + h*64 + d
__device__ float g_ctx[(size_t)MROWS * EMB];  // attention output, (t*BSZ+b) x 1024

// ---------------------------------------------------------------------------
// GEMM: C[M][N] = A[M][K] * B[N][K]^T + bias[N]; columns < qcols scaled 0.125
// A, B both K-contiguous (row-major). 128x128x16 tiles, 8x8 per thread.
// ---------------------------------------------------------------------------
#define BM 128
#define BN 128
#define BK 16

__global__ void __launch_bounds__(256, 2) gemm_nt_kernel(
    const float* __restrict__ A, const float* __restrict__ B,
    const float* __restrict__ bias, float* __restrict__ C,
    int M, int N, int K, int qcols)
{
    __shared__ float As[BK][BM + 4];
    __shared__ float Bs[BK][BN + 4];

    const int tid = threadIdx.x;
    const int tx = tid & 15;
    const int ty = tid >> 4;
    const int row0 = blockIdx.y * BM;
    const int col0 = blockIdx.x * BN;

    float acc[8][8];
    #pragma unroll
    for (int i = 0; i < 8; i++)
        #pragma unroll
        for (int j = 0; j < 8; j++) acc[i][j] = 0.f;

    for (int k0 = 0; k0 < K; k0 += BK) {
        // Load A tile (128x16) transposed into As[k][row]
        #pragma unroll
        for (int it = 0; it < 2; it++) {
            int f  = tid + it * 256;        // float4 index, 0..511
            int r  = f >> 2;                // 0..127
            int cv = (f & 3) << 2;          // 0,4,8,12
            float4 v = *(const float4*)(A + (size_t)(row0 + r) * K + k0 + cv);
            As[cv + 0][r] = v.x; As[cv + 1][r] = v.y;
            As[cv + 2][r] = v.z; As[cv + 3][r] = v.w;
        }
        // Load B tile (128x16) transposed into Bs[k][col]
        #pragma unroll
        for (int it = 0; it < 2; it++) {
            int f  = tid + it * 256;
            int r  = f >> 2;
            int cv = (f & 3) << 2;
            float4 v = *(const float4*)(B + (size_t)(col0 + r) * K + k0 + cv);
            Bs[cv + 0][r] = v.x; Bs[cv + 1][r] = v.y;
            Bs[cv + 2][r] = v.z; Bs[cv + 3][r] = v.w;
        }
        __syncthreads();

        #pragma unroll
        for (int k = 0; k < BK; k++) {
            float4 a0 = *(const float4*)(&As[k][ty * 8]);
            float4 a1 = *(const float4*)(&As[k][ty * 8 + 4]);
            float4 b0 = *(const float4*)(&Bs[k][tx * 8]);
            float4 b1 = *(const float4*)(&Bs[k][tx * 8 + 4]);
            float av[8] = {a0.x, a0.y, a0.z, a0.w, a1.x, a1.y, a1.z, a1.w};
            float bv[8] = {b0.x, b0.y, b0.z, b0.w, b1.x, b1.y, b1.z, b1.w};
            #pragma unroll
            for (int i = 0; i < 8; i++)
                #pragma unroll
                for (int j = 0; j < 8; j++)
                    acc[i][j] += av[i] * bv[j];
        }
        __syncthreads();
    }

    // Epilogue: bias + optional q-scale, float4 stores
    #pragma unroll
    for (int i = 0; i < 8; i++) {
        int r = row0 + ty * 8 + i;
        #pragma unroll
        for (int jv = 0; jv < 2; jv++) {
            int c = col0 + tx * 8 + jv * 4;
            float4 o;
            o.x = acc[i][jv * 4 + 0] + bias[c + 0];
            o.y = acc[i][jv * 4 + 1] + bias[c + 1];
            o.z = acc[i][jv * 4 + 2] + bias[c + 2];
            o.w = acc[i][jv * 4 + 3] + bias[c + 3];
            if (c + 3 < qcols) { o.x *= 0.125f; o.y *= 0.125f; o.z *= 0.125f; o.w *= 0.125f; }
            *(float4*)(C + (size_t)r * N + c) = o;
        }
    }
}

// ---------------------------------------------------------------------------
// Fused attention: per (b,h), 64-query tiles, online softmax over 64-key tiles.
// Smem: Qt[64][68] (d-major), KP[64][68] (K^T, later aliased as P^T), Vs[64][64].
// 16x16 threads, 4x4 S-tile + 4x4 O-tile per thread.
// ---------------------------------------------------------------------------
#define QT_LD 68
#define ATTN_SMEM ((2 * 64 * QT_LD + 64 * 64) * 4)

__global__ void __launch_bounds__(256) attn_kernel()
{
    extern __shared__ float sm[];
    float* Qt = sm;                       // [d][row], ld QT_LD
    float* KP = sm + 64 * QT_LD;          // K^T [d][col] then P^T [col][row]
    float* Vs = sm + 2 * 64 * QT_LD;      // [key][d], ld 64

    const int tid = threadIdx.x;
    const int tx = tid & 15;
    const int ty = tid >> 4;
    const int qt = blockIdx.x;            // query tile 0..31
    const int bh = blockIdx.y;            // 0..31
    const int b  = bh & (BSZ - 1);
    const int h  = bh >> 1;

    const float* qbase = g_qkv + (size_t)b * F3 + h * HD;
    const float* kbase = qbase + EMB;
    const float* vbase = qbase + 2 * EMB;
    const int rstride = BSZ * F3;         // 6144 floats between tokens

    // Load Q tile (64x64) transposed into Qt[d][row]
    #pragma unroll
    for (int it = 0; it < 4; it++) {
        int f  = tid + it * 256;          // float4 index 0..1023
        int r  = f >> 4;                  // 0..63
        int dv = (f & 15) << 2;           // 0..60
        float4 v = *(const float4*)(qbase + (size_t)(qt * 64 + r) * rstride + dv);
        Qt[(dv + 0) * QT_LD + r] = v.x;
        Qt[(dv + 1) * QT_LD + r] = v.y;
        Qt[(dv + 2) * QT_LD + r] = v.z;
        Qt[(dv + 3) * QT_LD + r] = v.w;
    }

    float m[4], l[4], acc_o[4][4];
    #pragma unroll
    for (int i = 0; i < 4; i++) {
        m[i] = -CUDART_INF_F; l[i] = 0.f;
        #pragma unroll
        for (int j = 0; j < 4; j++) acc_o[i][j] = 0.f;
    }

    for (int kt = 0; kt < NTOK / 64; kt++) {
        // Load K tile transposed into KP[d][col], V tile natural into Vs[key][d]
        #pragma unroll
        for (int it = 0; it < 4; it++) {
            int f  = tid + it * 256;
            int r  = f >> 4;
            int dv = (f & 15) << 2;
            size_t g = (size_t)(kt * 64 + r) * rstride + dv;
            float4 kv = *(const float4*)(kbase + g);
            KP[(dv + 0) * QT_LD + r] = kv.x;
            KP[(dv + 1) * QT_LD + r] = kv.y;
            KP[(dv + 2) * QT_LD + r] = kv.z;
            KP[(dv + 3) * QT_LD + r] = kv.w;
            float4 vv = *(const float4*)(vbase + g);
            *(float4*)(Vs + r * 64 + dv) = vv;
        }
        __syncthreads();

        // S = Q K^T (64x64x64), 4x4 per thread
        float s[4][4];
        #pragma unroll
        for (int i = 0; i < 4; i++)
            #pragma unroll
            for (int j = 0; j < 4; j++) s[i][j] = 0.f;

        #pragma unroll 8
        for (int d = 0; d < 64; d++) {
            float4 a = *(const float4*)(Qt + d * QT_LD + ty * 4);
            float4 c = *(const float4*)(KP + d * QT_LD + tx * 4);
            float av[4] = {a.x, a.y, a.z, a.w};
            float cv[4] = {c.x, c.y, c.z, c.w};
            #pragma unroll
            for (int i = 0; i < 4; i++)
                #pragma unroll
                for (int j = 0; j < 4; j++)
                    s[i][j] += av[i] * cv[j];
        }

        // Online softmax (row-wise across the 16 tx lanes)
        #pragma unroll
        for (int i = 0; i < 4; i++) {
            float rm = fmaxf(fmaxf(s[i][0], s[i][1]), fmaxf(s[i][2], s[i][3]));
            #pragma unroll
            for (int off = 8; off >= 1; off >>= 1)
                rm = fmaxf(rm, __shfl_xor_sync(0xffffffffu, rm, off));
            float mn = fmaxf(m[i], rm);
            float alpha = __expf(m[i] - mn);
            float rs = 0.f;
            #pragma unroll
            for (int j = 0; j < 4; j++) {
                s[i][j] = __expf(s[i][j] - mn);
                rs += s[i][j];
            }
            #pragma unroll
            for (int off = 8; off >= 1; off >>= 1)
                rs += __shfl_xor_sync(0xffffffffu, rs, off);
            l[i] = l[i] * alpha + rs;
            m[i] = mn;
            #pragma unroll
            for (int j = 0; j < 4; j++) acc_o[i][j] *= alpha;
        }
        __syncthreads();   // everyone done reading KP as K^T

        // Write P^T into KP: KP[col][row]
        #pragma unroll
        for (int j = 0; j < 4; j++) {
            float4 pv = make_float4(s[0][j], s[1][j], s[2][j], s[3][j]);
            *(float4*)(KP + (tx * 4 + j) * QT_LD + ty * 4) = pv;
        }
        __syncthreads();

        // O += P V (64x64x64)
        #pragma unroll 8
        for (int j = 0; j < 64; j++) {
            float4 p = *(const float4*)(KP + j * QT_LD + ty * 4);
            float4 v = *(const float4*)(Vs + j * 64 + tx * 4);
            float pv4[4] = {p.x, p.y, p.z, p.w};
            float vv4[4] = {v.x, v.y, v.z, v.w};
            #pragma unroll
            for (int i = 0; i < 4; i++)
                #pragma unroll
                for (int jd = 0; jd < 4; jd++)
                    acc_o[i][jd] += pv4[i] * vv4[jd];
        }
        __syncthreads();   // before next tile overwrites KP/Vs
    }

    // Epilogue: normalize and store to g_ctx at (t*BSZ+b)*EMB + h*HD + d
    float* obase = g_ctx + (size_t)b * EMB + h * HD;
    #pragma unroll
    for (int i = 0; i < 4; i++) {
        float inv = 1.0f / l[i];
        int row = qt * 64 + ty * 4 + i;
        float4 o = make_float4(acc_o[i][0] * inv, acc_o[i][1] * inv,
                               acc_o[i][2] * inv, acc_o[i][3] * inv);
        *(float4*)(obase + (size_t)row * (BSZ * EMB) + tx * 4) = o;
    }
}

// ---------------------------------------------------------------------------
// Launch
// ---------------------------------------------------------------------------
extern "C" void kernel_launch(void* const* d_in, const int* in_sizes, int n_in,
                              void* d_out, int out_size)
{
    const float* seq   = (const float*)d_in[0];
    const float* w_qkv = (const float*)d_in[1];
    const float* b_qkv = (const float*)d_in[2];
    const float* w_out = (const float*)d_in[3];
    const float* b_out = (const float*)d_in[4];
    float* out = (float*)d_out;

    float *qkv, *ctx;
    cudaGetSymbolAddress((void**)&qkv, g_qkv);
    cudaGetSymbolAddress((void**)&ctx, g_ctx);

    cudaFuncSetAttribute(attn_kernel,
                         cudaFuncAttributeMaxDynamicSharedMemorySize, ATTN_SMEM);

    // 1) QKV projection: [4096,3072] = seq[4096,1024] @ w_qkv^T + b_qkv, q scaled
    gemm_nt_kernel<<<dim3(F3 / BN, MROWS / BM), 256>>>(
        seq, w_qkv, b_qkv, qkv, MROWS, F3, EMB, EMB);

    // 2) Fused attention -> g_ctx
    attn_kernel<<<dim3(NTOK / 64, BSZ * NH), 256, ATTN_SMEM>>>();

    // 3) Output projection: out = ctx @ w_out^T + b_out
    gemm_nt_kernel<<<dim3(EMB / BN, MROWS / BM), 256>>>(
        ctx, w_out, b_out, out, MROWS, EMB, EMB, 0);
}

// round 3
// speedup vs baseline: 1.2842x; 1.2842x over previous
#include <cuda_runtime.h>
#include <cuda_bf16.h>
#include <math_constants.h>
#include <cstdint>

// Problem constants
#define NTOK 2048
#define BSZ  2
#define EMB  1024
#define NH   16
#define HD   64
#define MROWS (NTOK*BSZ)      // 4096
#define F3   (3*EMB)          // 3072

// -------------------- device scratch (allocation-free) ----------------------
__device__ float         g_qkv[(size_t)MROWS * F3];  // fp32 QKV for attention
__device__ __nv_bfloat16 g_sh[(size_t)MROWS * EMB];  // seq hi
__device__ __nv_bfloat16 g_sl[(size_t)MROWS * EMB];  // seq lo
__device__ __nv_bfloat16 g_wqh[(size_t)F3 * EMB];
__device__ __nv_bfloat16 g_wql[(size_t)F3 * EMB];
__device__ __nv_bfloat16 g_woh[(size_t)EMB * EMB];
__device__ __nv_bfloat16 g_wol[(size_t)EMB * EMB];
__device__ __nv_bfloat16 g_ch[(size_t)MROWS * EMB];  // attn out hi
__device__ __nv_bfloat16 g_cl[(size_t)MROWS * EMB];  // attn out lo

// -------------------- PTX helpers (non-'a' ISA only) ------------------------
__device__ __forceinline__ uint32_t s2u(const void* p) {
    uint32_t a;
    asm("{ .reg .u64 t; cvta.to.shared.u64 t, %1; cvt.u32.u64 %0, t; }"
        : "=r"(a) : "l"(p));
    return a;
}

__device__ __forceinline__ void cp16(uint32_t dst, const void* src) {
    asm volatile("cp.async.cg.shared.global [%0], [%1], 16;"
                 :: "r"(dst), "l"(src) : "memory");
}
#define CP_COMMIT() asm volatile("cp.async.commit_group;" ::: "memory")

__device__ __forceinline__ void ldsm4(uint32_t* r, uint32_t a) {
    asm volatile("ldmatrix.sync.aligned.m8n8.x4.shared.b16 {%0,%1,%2,%3}, [%4];"
                 : "=r"(r[0]), "=r"(r[1]), "=r"(r[2]), "=r"(r[3]) : "r"(a));
}

__device__ __forceinline__ void mma16816(float* c, const uint32_t* a,
                                          const uint32_t* b) {
    asm volatile(
        "mma.sync.aligned.m16n8k16.row.col.f32.bf16.bf16.f32 "
        "{%0,%1,%2,%3}, {%4,%5,%6,%7}, {%8,%9}, {%0,%1,%2,%3};"
        : "+f"(c[0]), "+f"(c[1]), "+f"(c[2]), "+f"(c[3])
        : "r"(a[0]), "r"(a[1]), "r"(a[2]), "r"(a[3]), "r"(b[0]), "r"(b[1]));
}

// -------------------- convert: fp32 -> (hi, lo) bf16 pair -------------------
__global__ void convert_kernel(const float4* __restrict__ in,
                               uint2* __restrict__ hi4,
                               uint2* __restrict__ lo4, int n4) {
    int i = blockIdx.x * blockDim.x + threadIdx.x;
    if (i >= n4) return;
    float4 x = in[i];
    float xs[4] = {x.x, x.y, x.z, x.w};
    uint32_t h[4], l[4];
    #pragma unroll
    for (int j = 0; j < 4; j++) {
        __nv_bfloat16 hb = __float2bfloat16(xs[j]);
        float res = xs[j] - __bfloat162float(hb);
        __nv_bfloat16 lb = __float2bfloat16(res);
        h[j] = (uint32_t)__bfloat16_as_ushort(hb);
        l[j] = (uint32_t)__bfloat16_as_ushort(lb);
    }
    uint2 hv, lv;
    hv.x = h[0] | (h[1] << 16); hv.y = h[2] | (h[3] << 16);
    lv.x = l[0] | (l[1] << 16); lv.y = l[2] | (l[3] << 16);
    hi4[i] = hv;
    lo4[i] = lv;
}

// -------------------- bf16 3-term split GEMM (mma.sync / HMMA) --------------
// C[M][N] = (Ah+Al)[M][K] * (Bh+Bl)[N][K]^T + bias[N]; cols < qcols scaled 1/8
// CTA 128x128x32, 3-stage cp.async, 8 warps (4m x 2n), warp tile 32x64.
#define PITCH  80                  // bytes per 32-bf16 row (64B data + 16B pad)
#define TILEB  (128 * PITCH)       // 10240 B per operand tile
#define STAGEB (4 * TILEB)         // Ah, Al, Bh, Bl
#define GSTG   3
#define GSMEM  (GSTG * STAGEB)     // 122880 B

#define ARR_AH 0
#define ARR_AL TILEB
#define ARR_BH (2 * TILEB)
#define ARR_BL (3 * TILEB)

__global__ void __launch_bounds__(256) gemm_mma_kernel(
    const __nv_bfloat16* __restrict__ Ah, const __nv_bfloat16* __restrict__ Al,
    const __nv_bfloat16* __restrict__ Bh, const __nv_bfloat16* __restrict__ Bl,
    const float* __restrict__ bias, float* __restrict__ C,
    int N, int K, int qcols)
{
    extern __shared__ char smem[];
    const uint32_t sb = s2u(smem);
    const int tid  = threadIdx.x;
    const int lane = tid & 31;
    const int warp = tid >> 5;
    const int wm   = warp & 3;     // m group (32 rows)
    const int wn   = warp >> 2;    // n group (64 cols)
    const int row0 = blockIdx.y * 128;
    const int col0 = blockIdx.x * 128;

    float acc[2][8][4];
    #pragma unroll
    for (int i = 0; i < 2; i++)
        #pragma unroll
        for (int j = 0; j < 8; j++)
            #pragma unroll
            for (int v = 0; v < 4; v++) acc[i][j][v] = 0.f;

    // ldmatrix lane-address components
    const uint32_t a_off = (uint32_t)(lane & 15) * PITCH + ((lane >> 4) & 1) * 16;
    const uint32_t b_off = (uint32_t)((lane & 7) + ((lane >> 4) & 1) * 8) * PITCH
                         + ((lane >> 3) & 1) * 16;

    // producer mapping: 2 x 16B segments per thread per operand array
    const int pr   = tid >> 1;          // row 0..127
    const int pseg = (tid & 1) * 2;     // segments {0,1} or {2,3}

    const int nch = K / 32;

    #define PRODUCE(c)                                                        \
    do {                                                                      \
        uint32_t base = sb + (uint32_t)((c) % GSTG) * STAGEB;                 \
        size_t gA = (size_t)(row0 + pr) * K + (c) * 32 + pseg * 8;            \
        size_t gB = (size_t)(col0 + pr) * K + (c) * 32 + pseg * 8;            \
        uint32_t so = (uint32_t)pr * PITCH + pseg * 16;                       \
        cp16(base + ARR_AH + so,      Ah + gA);                               \
        cp16(base + ARR_AH + so + 16, Ah + gA + 8);                           \
        cp16(base + ARR_AL + so,      Al + gA);                               \
        cp16(base + ARR_AL + so + 16, Al + gA + 8);                           \
        cp16(base + ARR_BH + so,      Bh + gB);                               \
        cp16(base + ARR_BH + so + 16, Bh + gB + 8);                           \
        cp16(base + ARR_BL + so,      Bl + gB);                               \
        cp16(base + ARR_BL + so + 16, Bl + gB + 8);                           \
    } while (0)

    PRODUCE(0); CP_COMMIT();
    PRODUCE(1); CP_COMMIT();

    for (int c = 0; c < nch; c++) {
        asm volatile("cp.async.wait_group 1;" ::: "memory");
        __syncthreads();

        if (c + 2 < nch) PRODUCE(c + 2);
        CP_COMMIT();

        const uint32_t st = sb + (uint32_t)(c % GSTG) * STAGEB;

        #pragma unroll
        for (int ks = 0; ks < 2; ks++) {
            uint32_t ah[2][4], al[2][4];
            #pragma unroll
            for (int mt = 0; mt < 2; mt++) {
                uint32_t ra = (uint32_t)(wm * 32 + mt * 16) * PITCH + ks * 32 + a_off;
                ldsm4(ah[mt], st + ARR_AH + ra);
                ldsm4(al[mt], st + ARR_AL + ra);
            }
            #pragma unroll
            for (int nt = 0; nt < 4; nt++) {
                uint32_t bh[4], bl[4];
                uint32_t rb = (uint32_t)(wn * 64 + nt * 16) * PITCH + ks * 32 + b_off;
                ldsm4(bh, st + ARR_BH + rb);
                ldsm4(bl, st + ARR_BL + rb);
                #pragma unroll
                for (int mt = 0; mt < 2; mt++) {
                    mma16816(acc[mt][2 * nt],     ah[mt], bh);
                    mma16816(acc[mt][2 * nt],     ah[mt], bl);
                    mma16816(acc[mt][2 * nt],     al[mt], bh);
                    mma16816(acc[mt][2 * nt + 1], ah[mt], bh + 2);
                    mma16816(acc[mt][2 * nt + 1], ah[mt], bl + 2);
                    mma16816(acc[mt][2 * nt + 1], al[mt], bh + 2);
                }
            }
        }
    }

    // epilogue: bias + optional q-scale
    const float scale = (col0 < qcols) ? 0.125f : 1.0f;
    const int tr = lane >> 2;
    const int tc = (lane & 3) * 2;
    #pragma unroll
    for (int mt = 0; mt < 2; mt++) {
        #pragma unroll
        for (int n8 = 0; n8 < 8; n8++) {
            int r  = row0 + wm * 32 + mt * 16 + tr;
            int cc = col0 + wn * 64 + n8 * 8 + tc;
            float b0 = bias[cc], b1 = bias[cc + 1];
            float2 o0 = make_float2((acc[mt][n8][0] + b0) * scale,
                                    (acc[mt][n8][1] + b1) * scale);
            float2 o1 = make_float2((acc[mt][n8][2] + b0) * scale,
                                    (acc[mt][n8][3] + b1) * scale);
            *(float2*)(C + (size_t)r * N + cc)       = o0;
            *(float2*)(C + (size_t)(r + 8) * N + cc) = o1;
        }
    }
}

// ---------------------------------------------------------------------------
// Fused attention (FFMA): per (b,h), 64-query tiles, online softmax over
// 64-key tiles. Epilogue writes the bf16 hi/lo split for the output GEMM.
// ---------------------------------------------------------------------------
#define QT_LD 68
#define ATTN_SMEM ((2 * 64 * QT_LD + 64 * 64) * 4)

__global__ void __launch_bounds__(256) attn_kernel()
{
    extern __shared__ float sm[];
    float* Qt = sm;
    float* KP = sm + 64 * QT_LD;
    float* Vs = sm + 2 * 64 * QT_LD;

    const int tid = threadIdx.x;
    const int tx = tid & 15;
    const int ty = tid >> 4;
    const int qt = blockIdx.x;
    const int bh = blockIdx.y;
    const int b  = bh & (BSZ - 1);
    const int h  = bh >> 1;

    const float* qbase = g_qkv + (size_t)b * F3 + h * HD;
    const float* kbase = qbase + EMB;
    const float* vbase = qbase + 2 * EMB;
    const int rstride = BSZ * F3;

    #pragma unroll
    for (int it = 0; it < 4; it++) {
        int f  = tid + it * 256;
        int r  = f >> 4;
        int dv = (f & 15) << 2;
        float4 v = *(const float4*)(qbase + (size_t)(qt * 64 + r) * rstride + dv);
        Qt[(dv + 0) * QT_LD + r] = v.x;
        Qt[(dv + 1) * QT_LD + r] = v.y;
        Qt[(dv + 2) * QT_LD + r] = v.z;
        Qt[(dv + 3) * QT_LD + r] = v.w;
    }

    float m[4], l[4], acc_o[4][4];
    #pragma unroll
    for (int i = 0; i < 4; i++) {
        m[i] = -CUDART_INF_F; l[i] = 0.f;
        #pragma unroll
        for (int j = 0; j < 4; j++) acc_o[i][j] = 0.f;
    }

    for (int kt = 0; kt < NTOK / 64; kt++) {
        #pragma unroll
        for (int it = 0; it < 4; it++) {
            int f  = tid + it * 256;
            int r  = f >> 4;
            int dv = (f & 15) << 2;
            size_t g = (size_t)(kt * 64 + r) * rstride + dv;
            float4 kv = *(const float4*)(kbase + g);
            KP[(dv + 0) * QT_LD + r] = kv.x;
            KP[(dv + 1) * QT_LD + r] = kv.y;
            KP[(dv + 2) * QT_LD + r] = kv.z;
            KP[(dv + 3) * QT_LD + r] = kv.w;
            float4 vv = *(const float4*)(vbase + g);
            *(float4*)(Vs + r * 64 + dv) = vv;
        }
        __syncthreads();

        float s[4][4];
        #pragma unroll
        for (int i = 0; i < 4; i++)
            #pragma unroll
            for (int j = 0; j < 4; j++) s[i][j] = 0.f;

        #pragma unroll 8
        for (int d = 0; d < 64; d++) {
            float4 a = *(const float4*)(Qt + d * QT_LD + ty * 4);
            float4 c = *(const float4*)(KP + d * QT_LD + tx * 4);
            float av[4] = {a.x, a.y, a.z, a.w};
            float cv[4] = {c.x, c.y, c.z, c.w};
            #pragma unroll
            for (int i = 0; i < 4; i++)
                #pragma unroll
                for (int j = 0; j < 4; j++)
                    s[i][j] += av[i] * cv[j];
        }

        #pragma unroll
        for (int i = 0; i < 4; i++) {
            float rm = fmaxf(fmaxf(s[i][0], s[i][1]), fmaxf(s[i][2], s[i][3]));
            #pragma unroll
            for (int off = 8; off >= 1; off >>= 1)
                rm = fmaxf(rm, __shfl_xor_sync(0xffffffffu, rm, off));
            float mn = fmaxf(m[i], rm);
            float alpha = __expf(m[i] - mn);
            float rs = 0.f;
            #pragma unroll
            for (int j = 0; j < 4; j++) {
                s[i][j] = __expf(s[i][j] - mn);
                rs += s[i][j];
            }
            #pragma unroll
            for (int off = 8; off >= 1; off >>= 1)
                rs += __shfl_xor_sync(0xffffffffu, rs, off);
            l[i] = l[i] * alpha + rs;
            m[i] = mn;
            #pragma unroll
            for (int j = 0; j < 4; j++) acc_o[i][j] *= alpha;
        }
        __syncthreads();

        #pragma unroll
        for (int j = 0; j < 4; j++) {
            float4 pv = make_float4(s[0][j], s[1][j], s[2][j], s[3][j]);
            *(float4*)(KP + (tx * 4 + j) * QT_LD + ty * 4) = pv;
        }
        __syncthreads();

        #pragma unroll 8
        for (int j = 0; j < 64; j++) {
            float4 p = *(const float4*)(KP + j * QT_LD + ty * 4);
            float4 v = *(const float4*)(Vs + j * 64 + tx * 4);
            float pv4[4] = {p.x, p.y, p.z, p.w};
            float vv4[4] = {v.x, v.y, v.z, v.w};
            #pragma unroll
            for (int i = 0; i < 4; i++)
                #pragma unroll
                for (int jd = 0; jd < 4; jd++)
                    acc_o[i][jd] += pv4[i] * vv4[jd];
        }
        __syncthreads();
    }

    // Epilogue: normalize, split into bf16 hi/lo, store to g_ch / g_cl
    #pragma unroll
    for (int i = 0; i < 4; i++) {
        float inv = 1.0f / l[i];
        int row = qt * 64 + ty * 4 + i;
        size_t off = (size_t)row * (BSZ * EMB) + (size_t)b * EMB + h * HD + tx * 4;
        uint32_t hb[4], lb[4];
        #pragma unroll
        for (int j = 0; j < 4; j++) {
            float o = acc_o[i][j] * inv;
            __nv_bfloat16 hv = __float2bfloat16(o);
            float res = o - __bfloat162float(hv);
            __nv_bfloat16 lv = __float2bfloat16(res);
            hb[j] = (uint32_t)__bfloat16_as_ushort(hv);
            lb[j] = (uint32_t)__bfloat16_as_ushort(lv);
        }
        uint2 hv2, lv2;
        hv2.x = hb[0] | (hb[1] << 16); hv2.y = hb[2] | (hb[3] << 16);
        lv2.x = lb[0] | (lb[1] << 16); lv2.y = lb[2] | (lb[3] << 16);
        *(uint2*)(g_ch + off) = hv2;
        *(uint2*)(g_cl + off) = lv2;
    }
}

// ---------------------------------------------------------------------------
// Launch
// ---------------------------------------------------------------------------
extern "C" void kernel_launch(void* const* d_in, const int* in_sizes, int n_in,
                              void* d_out, int out_size)
{
    const float* seq   = (const float*)d_in[0];
    const float* w_qkv = (const float*)d_in[1];
    const float* b_qkv = (const float*)d_in[2];
    const float* w_out = (const float*)d_in[3];
    const float* b_out = (const float*)d_in[4];
    float* out = (float*)d_out;

    float* qkv;
    __nv_bfloat16 *sh, *sl, *wqh, *wql, *woh, *wol, *ch, *cl;
    cudaGetSymbolAddress((void**)&qkv, g_qkv);
    cudaGetSymbolAddress((void**)&sh,  g_sh);
    cudaGetSymbolAddress((void**)&sl,  g_sl);
    cudaGetSymbolAddress((void**)&wqh, g_wqh);
    cudaGetSymbolAddress((void**)&wql, g_wql);
    cudaGetSymbolAddress((void**)&woh, g_woh);
    cudaGetSymbolAddress((void**)&wol, g_wol);
    cudaGetSymbolAddress((void**)&ch,  g_ch);
    cudaGetSymbolAddress((void**)&cl,  g_cl);

    cudaFuncSetAttribute(attn_kernel,
                         cudaFuncAttributeMaxDynamicSharedMemorySize, ATTN_SMEM);
    cudaFuncSetAttribute(gemm_mma_kernel,
                         cudaFuncAttributeMaxDynamicSharedMemorySize, GSMEM);

    // 0) split inputs into bf16 hi/lo pairs
    {
        int n4 = MROWS * EMB / 4;
        convert_kernel<<<(n4 + 255) / 256, 256>>>((const float4*)seq,
                                                  (uint2*)sh, (uint2*)sl, n4);
        n4 = F3 * EMB / 4;
        convert_kernel<<<(n4 + 255) / 256, 256>>>((const float4*)w_qkv,
                                                  (uint2*)wqh, (uint2*)wql, n4);
        n4 = EMB * EMB / 4;
        convert_kernel<<<(n4 + 255) / 256, 256>>>((const float4*)w_out,
                                                  (uint2*)woh, (uint2*)wol, n4);
    }

    // 1) QKV projection (HMMA bf16 3-term): qkv = seq @ w_qkv^T + b, q/8
    gemm_mma_kernel<<<dim3(F3 / 128, MROWS / 128), 256, GSMEM>>>(
        sh, sl, wqh, wql, b_qkv, qkv, F3, EMB, EMB);

    // 2) fused attention -> bf16 hi/lo context
    attn_kernel<<<dim3(NTOK / 64, BSZ * NH), 256, ATTN_SMEM>>>();

    // 3) output projection (HMMA bf16 3-term)
    gemm_mma_kernel<<<dim3(EMB / 128, MROWS / 128), 256, GSMEM>>>(
        ch, cl, woh, wol, b_out, out, EMB, EMB, 0);
}

// round 4
// speedup vs baseline: 2.5596x; 1.9931x over previous
#include <cuda_runtime.h>
#include <cuda_bf16.h>
#include <math_constants.h>
#include <cstdint>

// Problem constants
#define NTOK 2048
#define BSZ  2
#define EMB  1024
#define NH   16
#define HD   64
#define MROWS (NTOK*BSZ)      // 4096
#define F3   (3*EMB)          // 3072
#define QSCALE 0.1803368801111204f   // 0.125 * log2(e)

// -------------------- device scratch (allocation-free) ----------------------
__device__ __nv_bfloat16 g_sh[(size_t)MROWS * EMB];
__device__ __nv_bfloat16 g_sl[(size_t)MROWS * EMB];
__device__ __nv_bfloat16 g_wqh[(size_t)F3 * EMB];
__device__ __nv_bfloat16 g_wql[(size_t)F3 * EMB];
__device__ __nv_bfloat16 g_woh[(size_t)EMB * EMB];
__device__ __nv_bfloat16 g_wol[(size_t)EMB * EMB];
__device__ __nv_bfloat16 g_qkvh[(size_t)MROWS * F3];  // qkv hi (q pre-scaled)
__device__ __nv_bfloat16 g_qkvl[(size_t)MROWS * F3];  // qkv lo
__device__ __nv_bfloat16 g_vth[(size_t)BSZ * NH * HD * NTOK]; // V^T [bh][d][tok]
__device__ __nv_bfloat16 g_vtl[(size_t)BSZ * NH * HD * NTOK];
__device__ __nv_bfloat16 g_ch[(size_t)MROWS * EMB];   // attn out hi
__device__ __nv_bfloat16 g_cl[(size_t)MROWS * EMB];   // attn out lo

// -------------------- PTX helpers -------------------------------------------
__device__ __forceinline__ uint32_t s2u(const void* p) {
    uint32_t a;
    asm("{ .reg .u64 t; cvta.to.shared.u64 t, %1; cvt.u32.u64 %0, t; }"
        : "=r"(a) : "l"(p));
    return a;
}

__device__ __forceinline__ void cp16(uint32_t dst, const void* src) {
    asm volatile("cp.async.cg.shared.global [%0], [%1], 16;"
                 :: "r"(dst), "l"(src) : "memory");
}
#define CP_COMMIT() asm volatile("cp.async.commit_group;" ::: "memory")

__device__ __forceinline__ void ldsm4(uint32_t* r, uint32_t a) {
    asm volatile("ldmatrix.sync.aligned.m8n8.x4.shared.b16 {%0,%1,%2,%3}, [%4];"
                 : "=r"(r[0]), "=r"(r[1]), "=r"(r[2]), "=r"(r[3]) : "r"(a));
}

__device__ __forceinline__ void mma16816(float* c, const uint32_t* a,
                                          const uint32_t* b) {
    asm volatile(
        "mma.sync.aligned.m16n8k16.row.col.f32.bf16.bf16.f32 "
        "{%0,%1,%2,%3}, {%4,%5,%6,%7}, {%8,%9}, {%0,%1,%2,%3};"
        : "+f"(c[0]), "+f"(c[1]), "+f"(c[2]), "+f"(c[3])
        : "r"(a[0]), "r"(a[1]), "r"(a[2]), "r"(a[3]), "r"(b[0]), "r"(b[1]));
}

__device__ __forceinline__ float ex2(float x) {
    float y;
    asm("ex2.approx.f32 %0, %1;" : "=f"(y) : "f"(x));
    return y;
}

// split two floats into packed bf16 hi / lo-residual pairs (low = first arg)
__device__ __forceinline__ void split2(float a, float b, uint32_t& h, uint32_t& l) {
    __nv_bfloat162 t = __floats2bfloat162_rn(a, b);
    h = *reinterpret_cast<uint32_t*>(&t);
    float ra = a - __bfloat162float(t.x);
    float rb = b - __bfloat162float(t.y);
    __nv_bfloat162 t2 = __floats2bfloat162_rn(ra, rb);
    l = *reinterpret_cast<uint32_t*>(&t2);
}

// -------------------- convert: fp32 -> (hi, lo) bf16 pair -------------------
__global__ void convert_kernel(const float4* __restrict__ in,
                               uint2* __restrict__ hi4,
                               uint2* __restrict__ lo4, int n4) {
    int i = blockIdx.x * blockDim.x + threadIdx.x;
    if (i >= n4) return;
    float4 x = in[i];
    uint32_t h0, l0, h1, l1;
    split2(x.x, x.y, h0, l0);
    split2(x.z, x.w, h1, l1);
    uint2 hv, lv;
    hv.x = h0; hv.y = h1;
    lv.x = l0; lv.y = l1;
    hi4[i] = hv;
    lo4[i] = lv;
}

// -------------------- bf16 3-term split GEMM (mma.sync / HMMA) --------------
// C = (Ah+Al)[M][K] * (Bh+Bl)[N][K]^T + bias[N]
// If Ch != null: write bf16 hi/lo split (cols < qcols scaled by qscale).
// Else: write fp32 to C.
// CTA 128x128x32, 2-stage cp.async (produce-after-consume), 8 warps.
#define PITCH  80
#define TILEB  (128 * PITCH)
#define STAGEB (4 * TILEB)
#define GSTG   2
#define GSMEM  (GSTG * STAGEB)    // 81920 B -> 2 CTAs/SM

#define ARR_AH 0
#define ARR_AL TILEB
#define ARR_BH (2 * TILEB)
#define ARR_BL (3 * TILEB)

__global__ void __launch_bounds__(256, 2) gemm_mma_kernel(
    const __nv_bfloat16* __restrict__ Ah, const __nv_bfloat16* __restrict__ Al,
    const __nv_bfloat16* __restrict__ Bh, const __nv_bfloat16* __restrict__ Bl,
    const float* __restrict__ bias, float* __restrict__ C,
    __nv_bfloat16* __restrict__ Ch, __nv_bfloat16* __restrict__ Cl,
    int N, int K, int qcols, float qscale)
{
    extern __shared__ char smem[];
    const uint32_t sb = s2u(smem);
    const int tid  = threadIdx.x;
    const int lane = tid & 31;
    const int warp = tid >> 5;
    const int wm   = warp & 3;
    const int wn   = warp >> 2;
    const int row0 = blockIdx.y * 128;
    const int col0 = blockIdx.x * 128;

    float acc[2][8][4];
    #pragma unroll
    for (int i = 0; i < 2; i++)
        #pragma unroll
        for (int j = 0; j < 8; j++)
            #pragma unroll
            for (int v = 0; v < 4; v++) acc[i][j][v] = 0.f;

    const uint32_t a_off = (uint32_t)(lane & 15) * PITCH + ((lane >> 4) & 1) * 16;
    const uint32_t b_off = (uint32_t)((lane & 7) + ((lane >> 4) & 1) * 8) * PITCH
                         + ((lane >> 3) & 1) * 16;

    const int pr   = tid >> 1;
    const int pseg = (tid & 1) * 2;
    const int nch = K / 32;

    #define PRODUCE(c)                                                        \
    do {                                                                      \
        uint32_t base = sb + (uint32_t)((c) % GSTG) * STAGEB;                 \
        size_t gA = (size_t)(row0 + pr) * K + (c) * 32 + pseg * 8;            \
        size_t gB = (size_t)(col0 + pr) * K + (c) * 32 + pseg * 8;            \
        uint32_t so = (uint32_t)pr * PITCH + pseg * 16;                       \
        cp16(base + ARR_AH + so,      Ah + gA);                               \
        cp16(base + ARR_AH + so + 16, Ah + gA + 8);                           \
        cp16(base + ARR_AL + so,      Al + gA);                               \
        cp16(base + ARR_AL + so + 16, Al + gA + 8);                           \
        cp16(base + ARR_BH + so,      Bh + gB);                               \
        cp16(base + ARR_BH + so + 16, Bh + gB + 8);                           \
        cp16(base + ARR_BL + so,      Bl + gB);                               \
        cp16(base + ARR_BL + so + 16, Bl + gB + 8);                           \
    } while (0)

    PRODUCE(0); CP_COMMIT();
    PRODUCE(1); CP_COMMIT();

    for (int c = 0; c < nch; c++) {
        asm volatile("cp.async.wait_group 1;" ::: "memory");
        __syncthreads();

        const uint32_t st = sb + (uint32_t)(c % GSTG) * STAGEB;

        #pragma unroll
        for (int ks = 0; ks < 2; ks++) {
            uint32_t ah[2][4], al[2][4];
            #pragma unroll
            for (int mt = 0; mt < 2; mt++) {
                uint32_t ra = (uint32_t)(wm * 32 + mt * 16) * PITCH + ks * 32 + a_off;
                ldsm4(ah[mt], st + ARR_AH + ra);
                ldsm4(al[mt], st + ARR_AL + ra);
            }
            #pragma unroll
            for (int nt = 0; nt < 4; nt++) {
                uint32_t bh[4], bl[4];
                uint32_t rb = (uint32_t)(wn * 64 + nt * 16) * PITCH + ks * 32 + b_off;
                ldsm4(bh, st + ARR_BH + rb);
                ldsm4(bl, st + ARR_BL + rb);
                #pragma unroll
                for (int mt = 0; mt < 2; mt++) {
                    mma16816(acc[mt][2 * nt],     ah[mt], bh);
                    mma16816(acc[mt][2 * nt],     ah[mt], bl);
                    mma16816(acc[mt][2 * nt],     al[mt], bh);
                    mma16816(acc[mt][2 * nt + 1], ah[mt], bh + 2);
                    mma16816(acc[mt][2 * nt + 1], ah[mt], bl + 2);
                    mma16816(acc[mt][2 * nt + 1], al[mt], bh + 2);
                }
            }
        }
        __syncthreads();
        if (c + 2 < nch) PRODUCE(c + 2);
        CP_COMMIT();
    }

    const float scale = (col0 < qcols) ? qscale : 1.0f;
    const int tr = lane >> 2;
    const int tc = (lane & 3) * 2;
    #pragma unroll
    for (int mt = 0; mt < 2; mt++) {
        #pragma unroll
        for (int n8 = 0; n8 < 8; n8++) {
            int r  = row0 + wm * 32 + mt * 16 + tr;
            int cc = col0 + wn * 64 + n8 * 8 + tc;
            float b0 = bias[cc], b1 = bias[cc + 1];
            float v0 = (acc[mt][n8][0] + b0) * scale;
            float v1 = (acc[mt][n8][1] + b1) * scale;
            float v2 = (acc[mt][n8][2] + b0) * scale;
            float v3 = (acc[mt][n8][3] + b1) * scale;
            if (Ch) {
                uint32_t h, l;
                split2(v0, v1, h, l);
                *(uint32_t*)(Ch + (size_t)r * N + cc) = h;
                *(uint32_t*)(Cl + (size_t)r * N + cc) = l;
                split2(v2, v3, h, l);
                *(uint32_t*)(Ch + (size_t)(r + 8) * N + cc) = h;
                *(uint32_t*)(Cl + (size_t)(r + 8) * N + cc) = l;
            } else {
                *(float2*)(C + (size_t)r * N + cc)       = make_float2(v0, v1);
                *(float2*)(C + (size_t)(r + 8) * N + cc) = make_float2(v2, v3);
            }
        }
    }
}

// -------------------- V transpose: qkv V region -> vt[bh][d][tok] -----------
__global__ void __launch_bounds__(128) vtrans_kernel()
{
    __shared__ ushort sh[64][72];
    __shared__ ushort sl[64][72];
    const int tid = threadIdx.x;
    const int bh  = blockIdx.y;
    const int b   = bh & 1;
    const int h   = bh >> 1;
    const int tok0 = blockIdx.x * 64;

    // load 64 toks x 64 d (coalesced 16B chunks)
    {
        int tl = tid >> 1;
        int row = (tok0 + tl) * 2 + b;
        size_t base = (size_t)row * F3 + 2 * EMB + h * HD;
        #pragma unroll
        for (int j = 0; j < 4; j++) {
            int seg = (tid & 1) * 4 + j;
            uint4 vh = *(const uint4*)(g_qkvh + base + seg * 8);
            uint4 vl = *(const uint4*)(g_qkvl + base + seg * 8);
            *(uint4*)(&sh[tl][seg * 8]) = vh;
            *(uint4*)(&sl[tl][seg * 8]) = vl;
        }
    }
    __syncthreads();
    // write 64 d rows x 64 toks (coalesced)
    {
        int d = tid >> 1;
        int th = (tid & 1) * 32;
        size_t obase = ((size_t)bh * 64 + d) * NTOK + tok0 + th;
        #pragma unroll
        for (int q = 0; q < 4; q++) {
            ushort th8[8], tl8[8];
            #pragma unroll
            for (int i = 0; i < 8; i++) {
                th8[i] = sh[th + q * 8 + i][d];
                tl8[i] = sl[th + q * 8 + i][d];
            }
            *(uint4*)(g_vth + obase + q * 8) = *(uint4*)th8;
            *(uint4*)(g_vtl + obase + q * 8) = *(uint4*)tl8;
        }
    }
}

// -------------------- flash attention (mma.sync, hi/lo split) ---------------
// CTA: 64 queries x one (b,h); 4 warps, 16 query rows each; 32 key tiles of 64.
// Smem: Qh/Ql (16KB) + 2 stages x (Kh,Kl,Vh,Vl) (64KB) = 80KB. Swizzled 128B rows.
#define AQ_H  0
#define AQ_L  8192
#define ABUF  16384
#define ASTG  32768
#define A_KH  0
#define A_KL  8192
#define A_VH  16384
#define A_VL  24576
#define ATTN_SMEM (ABUF + 2 * ASTG)   // 81920

#define ASWZ(row, seg) ((uint32_t)(row) * 128 + ((uint32_t)((seg) ^ ((row) & 7)) * 16))

__global__ void __launch_bounds__(128, 2) attn_mma_kernel()
{
    extern __shared__ char smem[];
    const uint32_t sb = s2u(smem);
    const int tid  = threadIdx.x;
    const int lane = tid & 31;
    const int warp = tid >> 5;
    const int qt = blockIdx.x;
    const int bh = blockIdx.y;
    const int b  = bh & 1;
    const int h  = bh >> 1;

    const int prow = tid >> 1;
    const int psb  = (tid & 1) * 4;

    // prologue: Q tiles (hi/lo)
    {
        int qtok = qt * 64 + prow;
        size_t gq = (size_t)(qtok * 2 + b) * F3 + h * HD + psb * 8;
        #pragma unroll
        for (int j = 0; j < 4; j++) {
            uint32_t o = ASWZ(prow, psb + j);
            cp16(sb + AQ_H + o, g_qkvh + gq + j * 8);
            cp16(sb + AQ_L + o, g_qkvl + gq + j * 8);
        }
    }

    #define APROD(kt)                                                         \
    do {                                                                      \
        uint32_t bufb = sb + ABUF + (uint32_t)((kt) & 1) * ASTG;              \
        int tok = (kt) * 64 + prow;                                           \
        size_t gk = (size_t)(tok * 2 + b) * F3 + EMB + h * HD + psb * 8;      \
        size_t gv = ((size_t)bh * 64 + prow) * NTOK + (kt) * 64 + psb * 8;    \
        _Pragma("unroll")                                                     \
        for (int j = 0; j < 4; j++) {                                         \
            uint32_t o = ASWZ(prow, psb + j);                                 \
            cp16(bufb + A_KH + o, g_qkvh + gk + j * 8);                       \
            cp16(bufb + A_KL + o, g_qkvl + gk + j * 8);                       \
            cp16(bufb + A_VH + o, g_vth + gv + j * 8);                        \
            cp16(bufb + A_VL + o, g_vtl + gv + j * 8);                        \
        }                                                                     \
    } while (0)

    APROD(0); CP_COMMIT();
    APROD(1); CP_COMMIT();

    float o[8][4];
    #pragma unroll
    for (int j = 0; j < 8; j++)
        #pragma unroll
        for (int v = 0; v < 4; v++) o[j][v] = 0.f;
    float m0 = -CUDART_INF_F, m1 = -CUDART_INF_F, l0 = 0.f, l1 = 0.f;
    uint32_t qh[4][4], ql[4][4];

    const int NKT = NTOK / 64;
    for (int kt = 0; kt < NKT; kt++) {
        asm volatile("cp.async.wait_group 1;" ::: "memory");
        __syncthreads();
        const uint32_t kb = sb + ABUF + (uint32_t)(kt & 1) * ASTG;

        if (kt == 0) {
            #pragma unroll
            for (int ks = 0; ks < 4; ks++) {
                int row = warp * 16 + (lane & 15);
                int seg = ks * 2 + (lane >> 4);
                uint32_t ad = ASWZ(row, seg);
                ldsm4(qh[ks], sb + AQ_H + ad);
                ldsm4(ql[ks], sb + AQ_L + ad);
            }
        }

        // S = Q K^T (3-term split), m16 x n64 per warp
        float s[8][4];
        #pragma unroll
        for (int j = 0; j < 8; j++)
            #pragma unroll
            for (int v = 0; v < 4; v++) s[j][v] = 0.f;

        #pragma unroll
        for (int ks = 0; ks < 4; ks++) {
            #pragma unroll
            for (int nt = 0; nt < 4; nt++) {
                int row = nt * 16 + (lane & 7) + ((lane >> 4) & 1) * 8;
                int seg = ks * 2 + ((lane >> 3) & 1);
                uint32_t ad = ASWZ(row, seg);
                uint32_t kh4[4], kl4[4];
                ldsm4(kh4, kb + A_KH + ad);
                ldsm4(kl4, kb + A_KL + ad);
                mma16816(s[2 * nt],     qh[ks], kh4);
                mma16816(s[2 * nt],     ql[ks], kh4);
                mma16816(s[2 * nt],     qh[ks], kl4);
                mma16816(s[2 * nt + 1], qh[ks], kh4 + 2);
                mma16816(s[2 * nt + 1], ql[ks], kh4 + 2);
                mma16816(s[2 * nt + 1], qh[ks], kl4 + 2);
            }
        }

        // online softmax (logits pre-scaled by log2e; rows r and r+8 per thread)
        float cm0 = -CUDART_INF_F, cm1 = -CUDART_INF_F;
        #pragma unroll
        for (int j = 0; j < 8; j++) {
            cm0 = fmaxf(cm0, fmaxf(s[j][0], s[j][1]));
            cm1 = fmaxf(cm1, fmaxf(s[j][2], s[j][3]));
        }
        cm0 = fmaxf(cm0, __shfl_xor_sync(0xffffffffu, cm0, 1));
        cm0 = fmaxf(cm0, __shfl_xor_sync(0xffffffffu, cm0, 2));
        cm1 = fmaxf(cm1, __shfl_xor_sync(0xffffffffu, cm1, 1));
        cm1 = fmaxf(cm1, __shfl_xor_sync(0xffffffffu, cm1, 2));
        float nm0 = fmaxf(m0, cm0), nm1 = fmaxf(m1, cm1);
        float al0 = ex2(m0 - nm0),  al1 = ex2(m1 - nm1);
        float rs0 = 0.f, rs1 = 0.f;
        #pragma unroll
        for (int j = 0; j < 8; j++) {
            s[j][0] = ex2(s[j][0] - nm0);
            s[j][1] = ex2(s[j][1] - nm0);
            s[j][2] = ex2(s[j][2] - nm1);
            s[j][3] = ex2(s[j][3] - nm1);
            rs0 += s[j][0] + s[j][1];
            rs1 += s[j][2] + s[j][3];
        }
        rs0 += __shfl_xor_sync(0xffffffffu, rs0, 1);
        rs0 += __shfl_xor_sync(0xffffffffu, rs0, 2);
        rs1 += __shfl_xor_sync(0xffffffffu, rs1, 1);
        rs1 += __shfl_xor_sync(0xffffffffu, rs1, 2);
        l0 = l0 * al0 + rs0; m0 = nm0;
        l1 = l1 * al1 + rs1; m1 = nm1;
        #pragma unroll
        for (int j = 0; j < 8; j++) {
            o[j][0] *= al0; o[j][1] *= al0;
            o[j][2] *= al1; o[j][3] *= al1;
        }

        // P fragments (hi/lo) straight from S accumulators
        uint32_t ph[4][4], pl[4][4];
        #pragma unroll
        for (int ks = 0; ks < 4; ks++) {
            split2(s[2 * ks][0],     s[2 * ks][1],     ph[ks][0], pl[ks][0]);
            split2(s[2 * ks][2],     s[2 * ks][3],     ph[ks][1], pl[ks][1]);
            split2(s[2 * ks + 1][0], s[2 * ks + 1][1], ph[ks][2], pl[ks][2]);
            split2(s[2 * ks + 1][2], s[2 * ks + 1][3], ph[ks][3], pl[ks][3]);
        }

        // O += P V (3-term split), B = V^T tile [d][tok]
        #pragma unroll
        for (int ks = 0; ks < 4; ks++) {
            #pragma unroll
            for (int nt = 0; nt < 4; nt++) {
                int row = nt * 16 + (lane & 7) + ((lane >> 4) & 1) * 8;
                int seg = ks * 2 + ((lane >> 3) & 1);
                uint32_t ad = ASWZ(row, seg);
                uint32_t vh4[4], vl4[4];
                ldsm4(vh4, kb + A_VH + ad);
                ldsm4(vl4, kb + A_VL + ad);
                mma16816(o[2 * nt],     ph[ks], vh4);
                mma16816(o[2 * nt],     pl[ks], vh4);
                mma16816(o[2 * nt],     ph[ks], vl4);
                mma16816(o[2 * nt + 1], ph[ks], vh4 + 2);
                mma16816(o[2 * nt + 1], pl[ks], vh4 + 2);
                mma16816(o[2 * nt + 1], ph[ks], vl4 + 2);
            }
        }
        __syncthreads();
        if (kt + 2 < NKT) APROD(kt + 2);
        CP_COMMIT();
    }

    // epilogue: normalize, split to bf16 hi/lo ctx
    float inv0 = 1.0f / l0, inv1 = 1.0f / l1;
    int r0   = warp * 16 + (lane >> 2);
    int tok0 = qt * 64 + r0;
    int colb = h * HD + (lane & 3) * 2;
    size_t row0a = (size_t)(tok0 * 2 + b) * EMB;
    size_t row1a = (size_t)((tok0 + 8) * 2 + b) * EMB;
    #pragma unroll
    for (int j = 0; j < 8; j++) {
        int col = colb + 8 * j;
        uint32_t hu, lu;
        split2(o[j][0] * inv0, o[j][1] * inv0, hu, lu);
        *(uint32_t*)(g_ch + row0a + col) = hu;
        *(uint32_t*)(g_cl + row0a + col) = lu;
        split2(o[j][2] * inv1, o[j][3] * inv1, hu, lu);
        *(uint32_t*)(g_ch + row1a + col) = hu;
        *(uint32_t*)(g_cl + row1a + col) = lu;
    }
}

// ---------------------------------------------------------------------------
// Launch
// ---------------------------------------------------------------------------
extern "C" void kernel_launch(void* const* d_in, const int* in_sizes, int n_in,
                              void* d_out, int out_size)
{
    const float* seq   = (const float*)d_in[0];
    const float* w_qkv = (const float*)d_in[1];
    const float* b_qkv = (const float*)d_in[2];
    const float* w_out = (const float*)d_in[3];
    const float* b_out = (const float*)d_in[4];
    float* out = (float*)d_out;

    __nv_bfloat16 *sh, *sl, *wqh, *wql, *woh, *wol, *qkvh, *qkvl, *ch, *cl;
    cudaGetSymbolAddress((void**)&sh,   g_sh);
    cudaGetSymbolAddress((void**)&sl,   g_sl);
    cudaGetSymbolAddress((void**)&wqh,  g_wqh);
    cudaGetSymbolAddress((void**)&wql,  g_wql);
    cudaGetSymbolAddress((void**)&woh,  g_woh);
    cudaGetSymbolAddress((void**)&wol,  g_wol);
    cudaGetSymbolAddress((void**)&qkvh, g_qkvh);
    cudaGetSymbolAddress((void**)&qkvl, g_qkvl);
    cudaGetSymbolAddress((void**)&ch,   g_ch);
    cudaGetSymbolAddress((void**)&cl,   g_cl);

    cudaFuncSetAttribute(gemm_mma_kernel,
                         cudaFuncAttributeMaxDynamicSharedMemorySize, GSMEM);
    cudaFuncSetAttribute(attn_mma_kernel,
                         cudaFuncAttributeMaxDynamicSharedMemorySize, ATTN_SMEM);

    // 0) split inputs into bf16 hi/lo pairs
    {
        int n4 = MROWS * EMB / 4;
        convert_kernel<<<(n4 + 255) / 256, 256>>>((const float4*)seq,
                                                  (uint2*)sh, (uint2*)sl, n4);
        n4 = F3 * EMB / 4;
        convert_kernel<<<(n4 + 255) / 256, 256>>>((const float4*)w_qkv,
                                                  (uint2*)wqh, (uint2*)wql, n4);
        n4 = EMB * EMB / 4;
        convert_kernel<<<(n4 + 255) / 256, 256>>>((const float4*)w_out,
                                                  (uint2*)woh, (uint2*)wol, n4);
    }

    // 1) QKV projection -> bf16 hi/lo split, q pre-scaled by 0.125*log2(e)
    gemm_mma_kernel<<<dim3(F3 / 128, MROWS / 128), 256, GSMEM>>>(
        sh, sl, wqh, wql, b_qkv, nullptr, qkvh, qkvl, F3, EMB, EMB, QSCALE);

    // 2) transpose V region into [bh][d][tok]
    vtrans_kernel<<<dim3(NTOK / 64, BSZ * NH), 128>>>();

    // 3) fused flash attention (mma.sync) -> bf16 hi/lo ctx
    attn_mma_kernel<<<dim3(NTOK / 64, BSZ * NH), 128, ATTN_SMEM>>>();

    // 4) output projection -> fp32 out
    gemm_mma_kernel<<<dim3(EMB / 128, MROWS / 128), 256, GSMEM>>>(
        ch, cl, woh, wol, b_out, out, nullptr, nullptr, EMB, EMB, 0, 1.0f);
}

// round 5
// speedup vs baseline: 2.6127x; 1.0207x over previous
#include <cuda_runtime.h>
#include <cuda_bf16.h>
#include <math_constants.h>
#include <cstdint>

// Problem constants
#define NTOK 2048
#define BSZ  2
#define EMB  1024
#define NH   16
#define HD   64
#define MROWS (NTOK*BSZ)      // 4096
#define F3   (3*EMB)          // 3072
#define QSCALE 0.1803368801111204f   // 0.125 * log2(e)

// -------------------- device scratch (allocation-free) ----------------------
__device__ __nv_bfloat16 g_sh[(size_t)MROWS * EMB];
__device__ __nv_bfloat16 g_sl[(size_t)MROWS * EMB];
__device__ __nv_bfloat16 g_wqh[(size_t)F3 * EMB];
__device__ __nv_bfloat16 g_wql[(size_t)F3 * EMB];
__device__ __nv_bfloat16 g_woh[(size_t)EMB * EMB];
__device__ __nv_bfloat16 g_wol[(size_t)EMB * EMB];
__device__ __nv_bfloat16 g_qkvh[(size_t)MROWS * F3];  // qkv hi (q pre-scaled)
__device__ __nv_bfloat16 g_qkvl[(size_t)MROWS * F3];  // qkv lo
__device__ __nv_bfloat16 g_vth[(size_t)BSZ * NH * HD * NTOK]; // V^T [bh][d][tok]
__device__ __nv_bfloat16 g_vtl[(size_t)BSZ * NH * HD * NTOK];
__device__ __nv_bfloat16 g_ch[(size_t)MROWS * EMB];   // attn out hi
__device__ __nv_bfloat16 g_cl[(size_t)MROWS * EMB];   // attn out lo

// -------------------- PTX helpers -------------------------------------------
__device__ __forceinline__ uint32_t s2u(const void* p) {
    uint32_t a;
    asm("{ .reg .u64 t; cvta.to.shared.u64 t, %1; cvt.u32.u64 %0, t; }"
        : "=r"(a) : "l"(p));
    return a;
}

__device__ __forceinline__ void cp16(uint32_t dst, const void* src) {
    asm volatile("cp.async.cg.shared.global [%0], [%1], 16;"
                 :: "r"(dst), "l"(src) : "memory");
}
#define CP_COMMIT() asm volatile("cp.async.commit_group;" ::: "memory")

__device__ __forceinline__ void ldsm4(uint32_t* r, uint32_t a) {
    asm volatile("ldmatrix.sync.aligned.m8n8.x4.shared.b16 {%0,%1,%2,%3}, [%4];"
                 : "=r"(r[0]), "=r"(r[1]), "=r"(r[2]), "=r"(r[3]) : "r"(a));
}

__device__ __forceinline__ void mma16816(float* c, const uint32_t* a,
                                          const uint32_t* b) {
    asm volatile(
        "mma.sync.aligned.m16n8k16.row.col.f32.bf16.bf16.f32 "
        "{%0,%1,%2,%3}, {%4,%5,%6,%7}, {%8,%9}, {%0,%1,%2,%3};"
        : "+f"(c[0]), "+f"(c[1]), "+f"(c[2]), "+f"(c[3])
        : "r"(a[0]), "r"(a[1]), "r"(a[2]), "r"(a[3]), "r"(b[0]), "r"(b[1]));
}

__device__ __forceinline__ float ex2(float x) {
    float y;
    asm("ex2.approx.f32 %0, %1;" : "=f"(y) : "f"(x));
    return y;
}

__device__ __forceinline__ void split2(float a, float b, uint32_t& h, uint32_t& l) {
    __nv_bfloat162 t = __floats2bfloat162_rn(a, b);
    h = *reinterpret_cast<uint32_t*>(&t);
    float ra = a - __bfloat162float(t.x);
    float rb = b - __bfloat162float(t.y);
    __nv_bfloat162 t2 = __floats2bfloat162_rn(ra, rb);
    l = *reinterpret_cast<uint32_t*>(&t2);
}

// -------------------- convert: fp32 -> (hi, lo) bf16 pair -------------------
__global__ void convert_kernel(const float4* __restrict__ in,
                               uint2* __restrict__ hi4,
                               uint2* __restrict__ lo4, int n4) {
    int i = blockIdx.x * blockDim.x + threadIdx.x;
    if (i >= n4) return;
    float4 x = in[i];
    uint32_t h0, l0, h1, l1;
    split2(x.x, x.y, h0, l0);
    split2(x.z, x.w, h1, l1);
    uint2 hv, lv;
    hv.x = h0; hv.y = h1;
    lv.x = l0; lv.y = l1;
    hi4[i] = hv;
    lo4[i] = lv;
}

// -------------------- bf16 3-term split GEMM (mma.sync / HMMA) --------------
// CTA 128x128x16-chunk, 4-stage cp.async, single sync per chunk, 8 warps.
#define PITCH  48                  // bytes per 16-bf16 row (32B data + 16B pad)
#define TILEB  (128 * PITCH)       // 6144
#define STAGEB (4 * TILEB)         // 24576: Ah, Al, Bh, Bl
#define GSTG   4
#define GSMEM  (GSTG * STAGEB)     // 98304 -> 2 CTAs/SM

#define ARR_AH 0
#define ARR_AL TILEB
#define ARR_BH (2 * TILEB)
#define ARR_BL (3 * TILEB)

__global__ void __launch_bounds__(256, 2) gemm_mma_kernel(
    const __nv_bfloat16* __restrict__ Ah, const __nv_bfloat16* __restrict__ Al,
    const __nv_bfloat16* __restrict__ Bh, const __nv_bfloat16* __restrict__ Bl,
    const float* __restrict__ bias, float* __restrict__ C,
    __nv_bfloat16* __restrict__ Ch, __nv_bfloat16* __restrict__ Cl,
    int N, int K, int qcols, float qscale)
{
    extern __shared__ char smem[];
    const uint32_t sb = s2u(smem);
    const int tid  = threadIdx.x;
    const int lane = tid & 31;
    const int warp = tid >> 5;
    const int wm   = warp & 3;
    const int wn   = warp >> 2;
    const int row0 = blockIdx.y * 128;
    const int col0 = blockIdx.x * 128;

    float acc[2][8][4];
    #pragma unroll
    for (int i = 0; i < 2; i++)
        #pragma unroll
        for (int j = 0; j < 8; j++)
            #pragma unroll
            for (int v = 0; v < 4; v++) acc[i][j][v] = 0.f;

    const uint32_t a_off = (uint32_t)(lane & 15) * PITCH + (lane >> 4) * 16;
    const uint32_t b_off = (uint32_t)((lane & 7) + ((lane >> 4) & 1) * 8) * PITCH
                         + ((lane >> 3) & 1) * 16;

    const int pr   = tid >> 1;          // row 0..127
    const int pseg = tid & 1;           // 16B segment 0/1
    const int nch  = K / 16;

    #define PRODUCE(c)                                                        \
    do {                                                                      \
        uint32_t base = sb + (uint32_t)((c) & 3) * STAGEB;                    \
        size_t gA = (size_t)(row0 + pr) * K + (c) * 16 + pseg * 8;            \
        size_t gB = (size_t)(col0 + pr) * K + (c) * 16 + pseg * 8;            \
        uint32_t so = (uint32_t)pr * PITCH + pseg * 16;                       \
        cp16(base + ARR_AH + so, Ah + gA);                                    \
        cp16(base + ARR_AL + so, Al + gA);                                    \
        cp16(base + ARR_BH + so, Bh + gB);                                    \
        cp16(base + ARR_BL + so, Bl + gB);                                    \
    } while (0)

    PRODUCE(0); CP_COMMIT();
    PRODUCE(1); CP_COMMIT();
    PRODUCE(2); CP_COMMIT();

    for (int c = 0; c < nch; c++) {
        asm volatile("cp.async.wait_group 2;" ::: "memory");
        __syncthreads();

        if (c + 3 < nch) PRODUCE(c + 3);
        CP_COMMIT();

        const uint32_t st = sb + (uint32_t)(c & 3) * STAGEB;

        uint32_t ah[2][4], al[2][4];
        #pragma unroll
        for (int mt = 0; mt < 2; mt++) {
            uint32_t ra = (uint32_t)(wm * 32 + mt * 16) * PITCH + a_off;
            ldsm4(ah[mt], st + ARR_AH + ra);
            ldsm4(al[mt], st + ARR_AL + ra);
        }
        #pragma unroll
        for (int nt = 0; nt < 4; nt++) {
            uint32_t bh[4], bl[4];
            uint32_t rb = (uint32_t)(wn * 64 + nt * 16) * PITCH + b_off;
            ldsm4(bh, st + ARR_BH + rb);
            ldsm4(bl, st + ARR_BL + rb);
            #pragma unroll
            for (int mt = 0; mt < 2; mt++) {
                mma16816(acc[mt][2 * nt],     ah[mt], bh);
                mma16816(acc[mt][2 * nt],     ah[mt], bl);
                mma16816(acc[mt][2 * nt],     al[mt], bh);
                mma16816(acc[mt][2 * nt + 1], ah[mt], bh + 2);
                mma16816(acc[mt][2 * nt + 1], ah[mt], bl + 2);
                mma16816(acc[mt][2 * nt + 1], al[mt], bh + 2);
            }
        }
    }

    const float scale = (col0 < qcols) ? qscale : 1.0f;
    const int tr = lane >> 2;
    const int tc = (lane & 3) * 2;
    #pragma unroll
    for (int mt = 0; mt < 2; mt++) {
        #pragma unroll
        for (int n8 = 0; n8 < 8; n8++) {
            int r  = row0 + wm * 32 + mt * 16 + tr;
            int cc = col0 + wn * 64 + n8 * 8 + tc;
            float b0 = bias[cc], b1 = bias[cc + 1];
            float v0 = (acc[mt][n8][0] + b0) * scale;
            float v1 = (acc[mt][n8][1] + b1) * scale;
            float v2 = (acc[mt][n8][2] + b0) * scale;
            float v3 = (acc[mt][n8][3] + b1) * scale;
            if (Ch) {
                uint32_t h, l;
                split2(v0, v1, h, l);
                *(uint32_t*)(Ch + (size_t)r * N + cc) = h;
                *(uint32_t*)(Cl + (size_t)r * N + cc) = l;
                split2(v2, v3, h, l);
                *(uint32_t*)(Ch + (size_t)(r + 8) * N + cc) = h;
                *(uint32_t*)(Cl + (size_t)(r + 8) * N + cc) = l;
            } else {
                *(float2*)(C + (size_t)r * N + cc)       = make_float2(v0, v1);
                *(float2*)(C + (size_t)(r + 8) * N + cc) = make_float2(v2, v3);
            }
        }
    }
}

// -------------------- V transpose: qkv V region -> vt[bh][d][tok] -----------
__global__ void __launch_bounds__(128) vtrans_kernel()
{
    __shared__ ushort sh[64][72];
    __shared__ ushort sl[64][72];
    const int tid = threadIdx.x;
    const int bh  = blockIdx.y;
    const int b   = bh & 1;
    const int h   = bh >> 1;
    const int tok0 = blockIdx.x * 64;

    {
        int tl = tid >> 1;
        int row = (tok0 + tl) * 2 + b;
        size_t base = (size_t)row * F3 + 2 * EMB + h * HD;
        #pragma unroll
        for (int j = 0; j < 4; j++) {
            int seg = (tid & 1) * 4 + j;
            uint4 vh = *(const uint4*)(g_qkvh + base + seg * 8);
            uint4 vl = *(const uint4*)(g_qkvl + base + seg * 8);
            *(uint4*)(&sh[tl][seg * 8]) = vh;
            *(uint4*)(&sl[tl][seg * 8]) = vl;
        }
    }
    __syncthreads();
    {
        int d = tid >> 1;
        int th = (tid & 1) * 32;
        size_t obase = ((size_t)bh * 64 + d) * NTOK + tok0 + th;
        #pragma unroll
        for (int q = 0; q < 4; q++) {
            ushort th8[8], tl8[8];
            #pragma unroll
            for (int i = 0; i < 8; i++) {
                th8[i] = sh[th + q * 8 + i][d];
                tl8[i] = sl[th + q * 8 + i][d];
            }
            *(uint4*)(g_vth + obase + q * 8) = *(uint4*)th8;
            *(uint4*)(g_vtl + obase + q * 8) = *(uint4*)tl8;
        }
    }
}

// -------------------- flash attention (mma.sync, hi/lo split) ---------------
// 64 queries x (b,h) per CTA; 4 warps; 3-stage pipeline, single sync per tile.
#define AQ_H  0
#define AQ_L  8192
#define ABUF  16384
#define ASTG  32768
#define A_KH  0
#define A_KL  8192
#define A_VH  16384
#define A_VL  24576
#define ASTAGES 3
#define ATTN_SMEM (ABUF + ASTAGES * ASTG)   // 114688 -> 2 CTAs/SM

#define ASWZ(row, seg) ((uint32_t)(row) * 128 + ((uint32_t)((seg) ^ ((row) & 7)) * 16))

__global__ void __launch_bounds__(128, 2) attn_mma_kernel()
{
    extern __shared__ char smem[];
    const uint32_t sb = s2u(smem);
    const int tid  = threadIdx.x;
    const int lane = tid & 31;
    const int warp = tid >> 5;
    const int qt = blockIdx.x;
    const int bh = blockIdx.y;
    const int b  = bh & 1;
    const int h  = bh >> 1;

    const int prow = tid >> 1;
    const int psb  = (tid & 1) * 4;

    // prologue: Q tiles (hi/lo), committed with stage 0
    {
        int qtok = qt * 64 + prow;
        size_t gq = (size_t)(qtok * 2 + b) * F3 + h * HD + psb * 8;
        #pragma unroll
        for (int j = 0; j < 4; j++) {
            uint32_t o = ASWZ(prow, psb + j);
            cp16(sb + AQ_H + o, g_qkvh + gq + j * 8);
            cp16(sb + AQ_L + o, g_qkvl + gq + j * 8);
        }
    }

    #define APROD(kt)                                                         \
    do {                                                                      \
        uint32_t bufb = sb + ABUF + (uint32_t)((kt) % ASTAGES) * ASTG;        \
        int tok = (kt) * 64 + prow;                                           \
        size_t gk = (size_t)(tok * 2 + b) * F3 + EMB + h * HD + psb * 8;      \
        size_t gv = ((size_t)bh * 64 + prow) * NTOK + (kt) * 64 + psb * 8;    \
        _Pragma("unroll")                                                     \
        for (int j = 0; j < 4; j++) {                                         \
            uint32_t o = ASWZ(prow, psb + j);                                 \
            cp16(bufb + A_KH + o, g_qkvh + gk + j * 8);                       \
            cp16(bufb + A_KL + o, g_qkvl + gk + j * 8);                       \
            cp16(bufb + A_VH + o, g_vth + gv + j * 8);                        \
            cp16(bufb + A_VL + o, g_vtl + gv + j * 8);                        \
        }                                                                     \
    } while (0)

    APROD(0); CP_COMMIT();
    APROD(1); CP_COMMIT();

    float o[8][4];
    #pragma unroll
    for (int j = 0; j < 8; j++)
        #pragma unroll
        for (int v = 0; v < 4; v++) o[j][v] = 0.f;
    float m0 = -CUDART_INF_F, m1 = -CUDART_INF_F, l0 = 0.f, l1 = 0.f;
    uint32_t qh[4][4], ql[4][4];

    const int NKT = NTOK / 64;
    for (int kt = 0; kt < NKT; kt++) {
        asm volatile("cp.async.wait_group 1;" ::: "memory");
        __syncthreads();

        if (kt + 2 < NKT) APROD(kt + 2);
        CP_COMMIT();

        const uint32_t kb = sb + ABUF + (uint32_t)(kt % ASTAGES) * ASTG;

        if (kt == 0) {
            #pragma unroll
            for (int ks = 0; ks < 4; ks++) {
                int row = warp * 16 + (lane & 15);
                int seg = ks * 2 + (lane >> 4);
                uint32_t ad = ASWZ(row, seg);
                ldsm4(qh[ks], sb + AQ_H + ad);
                ldsm4(ql[ks], sb + AQ_L + ad);
            }
        }

        // S = Q K^T (3-term split), m16 x n64 per warp
        float s[8][4];
        #pragma unroll
        for (int j = 0; j < 8; j++)
            #pragma unroll
            for (int v = 0; v < 4; v++) s[j][v] = 0.f;

        #pragma unroll
        for (int ks = 0; ks < 4; ks++) {
            #pragma unroll
            for (int nt = 0; nt < 4; nt++) {
                int row = nt * 16 + (lane & 7) + ((lane >> 4) & 1) * 8;
                int seg = ks * 2 + ((lane >> 3) & 1);
                uint32_t ad = ASWZ(row, seg);
                uint32_t kh4[4], kl4[4];
                ldsm4(kh4, kb + A_KH + ad);
                ldsm4(kl4, kb + A_KL + ad);
                mma16816(s[2 * nt],     qh[ks], kh4);
                mma16816(s[2 * nt],     ql[ks], kh4);
                mma16816(s[2 * nt],     qh[ks], kl4);
                mma16816(s[2 * nt + 1], qh[ks], kh4 + 2);
                mma16816(s[2 * nt + 1], ql[ks], kh4 + 2);
                mma16816(s[2 * nt + 1], qh[ks], kl4 + 2);
            }
        }

        // online softmax (logits pre-scaled by log2e)
        float cm0 = -CUDART_INF_F, cm1 = -CUDART_INF_F;
        #pragma unroll
        for (int j = 0; j < 8; j++) {
            cm0 = fmaxf(cm0, fmaxf(s[j][0], s[j][1]));
            cm1 = fmaxf(cm1, fmaxf(s[j][2], s[j][3]));
        }
        cm0 = fmaxf(cm0, __shfl_xor_sync(0xffffffffu, cm0, 1));
        cm0 = fmaxf(cm0, __shfl_xor_sync(0xffffffffu, cm0, 2));
        cm1 = fmaxf(cm1, __shfl_xor_sync(0xffffffffu, cm1, 1));
        cm1 = fmaxf(cm1, __shfl_xor_sync(0xffffffffu, cm1, 2));
        float nm0 = fmaxf(m0, cm0), nm1 = fmaxf(m1, cm1);
        float al0 = ex2(m0 - nm0),  al1 = ex2(m1 - nm1);
        float rs0 = 0.f, rs1 = 0.f;
        #pragma unroll
        for (int j = 0; j < 8; j++) {
            s[j][0] = ex2(s[j][0] - nm0);
            s[j][1] = ex2(s[j][1] - nm0);
            s[j][2] = ex2(s[j][2] - nm1);
            s[j][3] = ex2(s[j][3] - nm1);
            rs0 += s[j][0] + s[j][1];
            rs1 += s[j][2] + s[j][3];
        }
        rs0 += __shfl_xor_sync(0xffffffffu, rs0, 1);
        rs0 += __shfl_xor_sync(0xffffffffu, rs0, 2);
        rs1 += __shfl_xor_sync(0xffffffffu, rs1, 1);
        rs1 += __shfl_xor_sync(0xffffffffu, rs1, 2);
        l0 = l0 * al0 + rs0; m0 = nm0;
        l1 = l1 * al1 + rs1; m1 = nm1;
        #pragma unroll
        for (int j = 0; j < 8; j++) {
            o[j][0] *= al0; o[j][1] *= al0;
            o[j][2] *= al1; o[j][3] *= al1;
        }

        // P fragments (hi/lo)
        uint32_t ph[4][4], pl[4][4];
        #pragma unroll
        for (int ks = 0; ks < 4; ks++) {
            split2(s[2 * ks][0],     s[2 * ks][1],     ph[ks][0], pl[ks][0]);
            split2(s[2 * ks][2],     s[2 * ks][3],     ph[ks][1], pl[ks][1]);
            split2(s[2 * ks + 1][0], s[2 * ks + 1][1], ph[ks][2], pl[ks][2]);
            split2(s[2 * ks + 1][2], s[2 * ks + 1][3], ph[ks][3], pl[ks][3]);
        }

        // O += P V (3-term split), B = V^T tile [d][tok]
        #pragma unroll
        for (int ks = 0; ks < 4; ks++) {
            #pragma unroll
            for (int nt = 0; nt < 4; nt++) {
                int row = nt * 16 + (lane & 7) + ((lane >> 4) & 1) * 8;
                int seg = ks * 2 + ((lane >> 3) & 1);
                uint32_t ad = ASWZ(row, seg);
                uint32_t vh4[4], vl4[4];
                ldsm4(vh4, kb + A_VH + ad);
                ldsm4(vl4, kb + A_VL + ad);
                mma16816(o[2 * nt],     ph[ks], vh4);
                mma16816(o[2 * nt],     pl[ks], vh4);
                mma16816(o[2 * nt],     ph[ks], vl4);
                mma16816(o[2 * nt + 1], ph[ks], vh4 + 2);
                mma16816(o[2 * nt + 1], pl[ks], vh4 + 2);
                mma16816(o[2 * nt + 1], ph[ks], vl4 + 2);
            }
        }
    }

    // epilogue: normalize, split to bf16 hi/lo ctx
    float inv0 = 1.0f / l0, inv1 = 1.0f / l1;
    int r0   = warp * 16 + (lane >> 2);
    int tok0 = qt * 64 + r0;
    int colb = h * HD + (lane & 3) * 2;
    size_t row0a = (size_t)(tok0 * 2 + b) * EMB;
    size_t row1a = (size_t)((tok0 + 8) * 2 + b) * EMB;
    #pragma unroll
    for (int j = 0; j < 8; j++) {
        int col = colb + 8 * j;
        uint32_t hu, lu;
        split2(o[j][0] * inv0, o[j][1] * inv0, hu, lu);
        *(uint32_t*)(g_ch + row0a + col) = hu;
        *(uint32_t*)(g_cl + row0a + col) = lu;
        split2(o[j][2] * inv1, o[j][3] * inv1, hu, lu);
        *(uint32_t*)(g_ch + row1a + col) = hu;
        *(uint32_t*)(g_cl + row1a + col) = lu;
    }
}

// ---------------------------------------------------------------------------
// Launch
// ---------------------------------------------------------------------------
extern "C" void kernel_launch(void* const* d_in, const int* in_sizes, int n_in,
                              void* d_out, int out_size)
{
    const float* seq   = (const float*)d_in[0];
    const float* w_qkv = (const float*)d_in[1];
    const float* b_qkv = (const float*)d_in[2];
    const float* w_out = (const float*)d_in[3];
    const float* b_out = (const float*)d_in[4];
    float* out = (float*)d_out;

    __nv_bfloat16 *sh, *sl, *wqh, *wql, *woh, *wol, *qkvh, *qkvl, *ch, *cl;
    cudaGetSymbolAddress((void**)&sh,   g_sh);
    cudaGetSymbolAddress((void**)&sl,   g_sl);
    cudaGetSymbolAddress((void**)&wqh,  g_wqh);
    cudaGetSymbolAddress((void**)&wql,  g_wql);
    cudaGetSymbolAddress((void**)&woh,  g_woh);
    cudaGetSymbolAddress((void**)&wol,  g_wol);
    cudaGetSymbolAddress((void**)&qkvh, g_qkvh);
    cudaGetSymbolAddress((void**)&qkvl, g_qkvl);
    cudaGetSymbolAddress((void**)&ch,   g_ch);
    cudaGetSymbolAddress((void**)&cl,   g_cl);

    cudaFuncSetAttribute(gemm_mma_kernel,
                         cudaFuncAttributeMaxDynamicSharedMemorySize, GSMEM);
    cudaFuncSetAttribute(attn_mma_kernel,
                         cudaFuncAttributeMaxDynamicSharedMemorySize, ATTN_SMEM);

    // 0) split inputs into bf16 hi/lo pairs
    {
        int n4 = MROWS * EMB / 4;
        convert_kernel<<<(n4 + 255) / 256, 256>>>((const float4*)seq,
                                                  (uint2*)sh, (uint2*)sl, n4);
        n4 = F3 * EMB / 4;
        convert_kernel<<<(n4 + 255) / 256, 256>>>((const float4*)w_qkv,
                                                  (uint2*)wqh, (uint2*)wql, n4);
        n4 = EMB * EMB / 4;
        convert_kernel<<<(n4 + 255) / 256, 256>>>((const float4*)w_out,
                                                  (uint2*)woh, (uint2*)wol, n4);
    }

    // 1) QKV projection -> bf16 hi/lo split, q pre-scaled by 0.125*log2(e)
    gemm_mma_kernel<<<dim3(F3 / 128, MROWS / 128), 256, GSMEM>>>(
        sh, sl, wqh, wql, b_qkv, nullptr, qkvh, qkvl, F3, EMB, EMB, QSCALE);

    // 2) transpose V region into [bh][d][tok]
    vtrans_kernel<<<dim3(NTOK / 64, BSZ * NH), 128>>>();

    // 3) fused flash attention (mma.sync) -> bf16 hi/lo ctx
    attn_mma_kernel<<<dim3(NTOK / 64, BSZ * NH), 128, ATTN_SMEM>>>();

    // 4) output projection -> fp32 out
    gemm_mma_kernel<<<dim3(EMB / 128, MROWS / 128), 256, GSMEM>>>(
        ch, cl, woh, wol, b_out, out, nullptr, nullptr, EMB, EMB, 0, 1.0f);
}

// round 6
// speedup vs baseline: 3.4250x; 1.3109x over previous
#include <cuda_runtime.h>
#include <cuda_bf16.h>
#include <cuda_fp16.h>
#include <math_constants.h>
#include <cstdint>

// Problem constants
#define NTOK 2048
#define BSZ  2
#define EMB  1024
#define NH   16
#define HD   64
#define MROWS (NTOK*BSZ)      // 4096
#define F3   (3*EMB)          // 3072
#define QSCALE 0.1803368801111204f   // 0.125 * log2(e)

// -------------------- device scratch (allocation-free) ----------------------
__device__ __nv_bfloat16 g_sh[(size_t)MROWS * EMB];
__device__ __nv_bfloat16 g_sl[(size_t)MROWS * EMB];
__device__ __nv_bfloat16 g_wqh[(size_t)F3 * EMB];
__device__ __nv_bfloat16 g_wql[(size_t)F3 * EMB];
__device__ __nv_bfloat16 g_woh[(size_t)EMB * EMB];
__device__ __nv_bfloat16 g_wol[(size_t)EMB * EMB];
__device__ __half g_qf[(size_t)MROWS * EMB];   // Q fp16 (pre-scaled)
__device__ __half g_kf[(size_t)MROWS * EMB];   // K fp16
__device__ __half g_vh0[(size_t)MROWS * EMB];  // V hi fp16 (token-major)
__device__ __half g_vl0[(size_t)MROWS * EMB];  // V lo fp16
__device__ __half g_vthf[(size_t)BSZ * NH * HD * NTOK]; // V^T hi [bh][d][tok]
__device__ __half g_vtlf[(size_t)BSZ * NH * HD * NTOK]; // V^T lo
__device__ __nv_bfloat16 g_ch[(size_t)MROWS * EMB];   // attn out hi (bf16)
__device__ __nv_bfloat16 g_cl[(size_t)MROWS * EMB];   // attn out lo

// -------------------- PTX helpers -------------------------------------------
__device__ __forceinline__ uint32_t s2u(const void* p) {
    uint32_t a;
    asm("{ .reg .u64 t; cvta.to.shared.u64 t, %1; cvt.u32.u64 %0, t; }"
        : "=r"(a) : "l"(p));
    return a;
}

__device__ __forceinline__ void cp16(uint32_t dst, const void* src) {
    asm volatile("cp.async.cg.shared.global [%0], [%1], 16;"
                 :: "r"(dst), "l"(src) : "memory");
}
#define CP_COMMIT() asm volatile("cp.async.commit_group;" ::: "memory")

__device__ __forceinline__ void ldsm4(uint32_t* r, uint32_t a) {
    asm volatile("ldmatrix.sync.aligned.m8n8.x4.shared.b16 {%0,%1,%2,%3}, [%4];"
                 : "=r"(r[0]), "=r"(r[1]), "=r"(r[2]), "=r"(r[3]) : "r"(a));
}

__device__ __forceinline__ void mma16816(float* c, const uint32_t* a,
                                          const uint32_t* b) {
    asm volatile(
        "mma.sync.aligned.m16n8k16.row.col.f32.bf16.bf16.f32 "
        "{%0,%1,%2,%3}, {%4,%5,%6,%7}, {%8,%9}, {%0,%1,%2,%3};"
        : "+f"(c[0]), "+f"(c[1]), "+f"(c[2]), "+f"(c[3])
        : "r"(a[0]), "r"(a[1]), "r"(a[2]), "r"(a[3]), "r"(b[0]), "r"(b[1]));
}

__device__ __forceinline__ void mma16816h(float* c, const uint32_t* a,
                                           const uint32_t* b) {
    asm volatile(
        "mma.sync.aligned.m16n8k16.row.col.f32.f16.f16.f32 "
        "{%0,%1,%2,%3}, {%4,%5,%6,%7}, {%8,%9}, {%0,%1,%2,%3};"
        : "+f"(c[0]), "+f"(c[1]), "+f"(c[2]), "+f"(c[3])
        : "r"(a[0]), "r"(a[1]), "r"(a[2]), "r"(a[3]), "r"(b[0]), "r"(b[1]));
}

__device__ __forceinline__ float ex2(float x) {
    float y;
    asm("ex2.approx.f32 %0, %1;" : "=f"(y) : "f"(x));
    return y;
}

__device__ __forceinline__ void split2(float a, float b, uint32_t& h, uint32_t& l) {
    __nv_bfloat162 t = __floats2bfloat162_rn(a, b);
    h = *reinterpret_cast<uint32_t*>(&t);
    float ra = a - __bfloat162float(t.x);
    float rb = b - __bfloat162float(t.y);
    __nv_bfloat162 t2 = __floats2bfloat162_rn(ra, rb);
    l = *reinterpret_cast<uint32_t*>(&t2);
}

__device__ __forceinline__ uint32_t pack2h(float a, float b) {
    __half2 t = __floats2half2_rn(a, b);
    return *reinterpret_cast<uint32_t*>(&t);
}

__device__ __forceinline__ void split2h(float a, float b, uint32_t& h, uint32_t& l) {
    __half2 t = __floats2half2_rn(a, b);
    h = *reinterpret_cast<uint32_t*>(&t);
    float ra = a - __half2float(__low2half(t));
    float rb = b - __half2float(__high2half(t));
    __half2 t2 = __floats2half2_rn(ra, rb);
    l = *reinterpret_cast<uint32_t*>(&t2);
}

// -------------------- convert: fp32 -> (hi, lo) bf16 pair -------------------
__global__ void convert_kernel(const float4* __restrict__ in,
                               uint2* __restrict__ hi4,
                               uint2* __restrict__ lo4, int n4) {
    int i = blockIdx.x * blockDim.x + threadIdx.x;
    if (i >= n4) return;
    float4 x = in[i];
    uint32_t h0, l0, h1, l1;
    split2(x.x, x.y, h0, l0);
    split2(x.z, x.w, h1, l1);
    uint2 hv, lv;
    hv.x = h0; hv.y = h1;
    lv.x = l0; lv.y = l1;
    hi4[i] = hv;
    lo4[i] = lv;
}

// -------------------- bf16 3-term split GEMM (mma.sync / HMMA) --------------
// qkvmode=0: C fp32 = A*B^T + bias
// qkvmode=1: N=3072; comp0 -> g_qf (x QSCALE), comp1 -> g_kf, comp2 -> g_vh0/g_vl0
#define PITCH  48
#define TILEB  (128 * PITCH)
#define STAGEB (4 * TILEB)
#define GSTG   4
#define GSMEM  (GSTG * STAGEB)     // 98304 -> 2 CTAs/SM

#define ARR_AH 0
#define ARR_AL TILEB
#define ARR_BH (2 * TILEB)
#define ARR_BL (3 * TILEB)

__global__ void __launch_bounds__(256, 2) gemm_mma_kernel(
    const __nv_bfloat16* __restrict__ Ah, const __nv_bfloat16* __restrict__ Al,
    const __nv_bfloat16* __restrict__ Bh, const __nv_bfloat16* __restrict__ Bl,
    const float* __restrict__ bias, float* __restrict__ C,
    int N, int K, int qkvmode)
{
    extern __shared__ char smem[];
    const uint32_t sb = s2u(smem);
    const int tid  = threadIdx.x;
    const int lane = tid & 31;
    const int warp = tid >> 5;
    const int wm   = warp & 3;
    const int wn   = warp >> 2;
    const int row0 = blockIdx.y * 128;
    const int col0 = blockIdx.x * 128;

    float acc[2][8][4];
    #pragma unroll
    for (int i = 0; i < 2; i++)
        #pragma unroll
        for (int j = 0; j < 8; j++)
            #pragma unroll
            for (int v = 0; v < 4; v++) acc[i][j][v] = 0.f;

    const uint32_t a_off = (uint32_t)(lane & 15) * PITCH + (lane >> 4) * 16;
    const uint32_t b_off = (uint32_t)((lane & 7) + ((lane >> 4) & 1) * 8) * PITCH
                         + ((lane >> 3) & 1) * 16;

    const int pr   = tid >> 1;
    const int pseg = tid & 1;
    const int nch  = K / 16;

    #define PRODUCE(c)                                                        \
    do {                                                                      \
        uint32_t base = sb + (uint32_t)((c) & 3) * STAGEB;                    \
        size_t gA = (size_t)(row0 + pr) * K + (c) * 16 + pseg * 8;            \
        size_t gB = (size_t)(col0 + pr) * K + (c) * 16 + pseg * 8;            \
        uint32_t so = (uint32_t)pr * PITCH + pseg * 16;                       \
        cp16(base + ARR_AH + so, Ah + gA);                                    \
        cp16(base + ARR_AL + so, Al + gA);                                    \
        cp16(base + ARR_BH + so, Bh + gB);                                    \
        cp16(base + ARR_BL + so, Bl + gB);                                    \
    } while (0)

    PRODUCE(0); CP_COMMIT();
    PRODUCE(1); CP_COMMIT();
    PRODUCE(2); CP_COMMIT();

    for (int c = 0; c < nch; c++) {
        asm volatile("cp.async.wait_group 2;" ::: "memory");
        __syncthreads();

        if (c + 3 < nch) PRODUCE(c + 3);
        CP_COMMIT();

        const uint32_t st = sb + (uint32_t)(c & 3) * STAGEB;

        uint32_t ah[2][4], al[2][4];
        #pragma unroll
        for (int mt = 0; mt < 2; mt++) {
            uint32_t ra = (uint32_t)(wm * 32 + mt * 16) * PITCH + a_off;
            ldsm4(ah[mt], st + ARR_AH + ra);
            ldsm4(al[mt], st + ARR_AL + ra);
        }
        #pragma unroll
        for (int nt = 0; nt < 4; nt++) {
            uint32_t bh[4], bl[4];
            uint32_t rb = (uint32_t)(wn * 64 + nt * 16) * PITCH + b_off;
            ldsm4(bh, st + ARR_BH + rb);
            ldsm4(bl, st + ARR_BL + rb);
            #pragma unroll
            for (int mt = 0; mt < 2; mt++) {
                mma16816(acc[mt][2 * nt],     ah[mt], bh);
                mma16816(acc[mt][2 * nt],     ah[mt], bl);
                mma16816(acc[mt][2 * nt],     al[mt], bh);
                mma16816(acc[mt][2 * nt + 1], ah[mt], bh + 2);
                mma16816(acc[mt][2 * nt + 1], ah[mt], bl + 2);
                mma16816(acc[mt][2 * nt + 1], al[mt], bh + 2);
            }
        }
    }

    const int tr = lane >> 2;
    const int tc = (lane & 3) * 2;
    const int comp = col0 >> 10;   // valid in qkvmode (128-col tiles never straddle)
    #pragma unroll
    for (int mt = 0; mt < 2; mt++) {
        #pragma unroll
        for (int n8 = 0; n8 < 8; n8++) {
            int r  = row0 + wm * 32 + mt * 16 + tr;
            int cc = col0 + wn * 64 + n8 * 8 + tc;
            float b0 = bias[cc], b1 = bias[cc + 1];
            float v0 = acc[mt][n8][0] + b0;
            float v1 = acc[mt][n8][1] + b1;
            float v2 = acc[mt][n8][2] + b0;
            float v3 = acc[mt][n8][3] + b1;
            if (qkvmode) {
                int ccl = cc - (comp << 10);
                size_t o0 = (size_t)r * EMB + ccl;
                size_t o1 = (size_t)(r + 8) * EMB + ccl;
                if (comp == 0) {
                    *(uint32_t*)(g_qf + o0) = pack2h(v0 * QSCALE, v1 * QSCALE);
                    *(uint32_t*)(g_qf + o1) = pack2h(v2 * QSCALE, v3 * QSCALE);
                } else if (comp == 1) {
                    *(uint32_t*)(g_kf + o0) = pack2h(v0, v1);
                    *(uint32_t*)(g_kf + o1) = pack2h(v2, v3);
                } else {
                    uint32_t h, l;
                    split2h(v0, v1, h, l);
                    *(uint32_t*)(g_vh0 + o0) = h;
                    *(uint32_t*)(g_vl0 + o0) = l;
                    split2h(v2, v3, h, l);
                    *(uint32_t*)(g_vh0 + o1) = h;
                    *(uint32_t*)(g_vl0 + o1) = l;
                }
            } else {
                *(float2*)(C + (size_t)r * N + cc)       = make_float2(v0, v1);
                *(float2*)(C + (size_t)(r + 8) * N + cc) = make_float2(v2, v3);
            }
        }
    }
}

// -------------------- V transpose: g_vh0/g_vl0 -> vt[bh][d][tok] -------------
__global__ void __launch_bounds__(128) vtrans_kernel()
{
    __shared__ ushort sh[64][72];
    __shared__ ushort sl[64][72];
    const int tid = threadIdx.x;
    const int bh  = blockIdx.y;
    const int b   = bh & 1;
    const int h   = bh >> 1;
    const int tok0 = blockIdx.x * 64;

    {
        int tl = tid >> 1;
        int row = (tok0 + tl) * 2 + b;
        size_t base = (size_t)row * EMB + h * HD;
        #pragma unroll
        for (int j = 0; j < 4; j++) {
            int seg = (tid & 1) * 4 + j;
            uint4 vh = *(const uint4*)((const ushort*)g_vh0 + base + seg * 8);
            uint4 vl = *(const uint4*)((const ushort*)g_vl0 + base + seg * 8);
            *(uint4*)(&sh[tl][seg * 8]) = vh;
            *(uint4*)(&sl[tl][seg * 8]) = vl;
        }
    }
    __syncthreads();
    {
        int d = tid >> 1;
        int th = (tid & 1) * 32;
        size_t obase = ((size_t)bh * 64 + d) * NTOK + tok0 + th;
        #pragma unroll
        for (int q = 0; q < 4; q++) {
            ushort th8[8], tl8[8];
            #pragma unroll
            for (int i = 0; i < 8; i++) {
                th8[i] = sh[th + q * 8 + i][d];
                tl8[i] = sl[th + q * 8 + i][d];
            }
            *(uint4*)((ushort*)g_vthf + obase + q * 8) = *(uint4*)th8;
            *(uint4*)((ushort*)g_vtlf + obase + q * 8) = *(uint4*)tl8;
        }
    }
}

// -------------------- flash attention (fp16 mma, split V) -------------------
// 128 queries x (b,h) per CTA; 8 warps (16 q-rows each); 3-stage pipeline.
// QK: 1-pass fp16. PV: P fp16 1-pass, V 2-term fp16 (hi+lo).
#define AQ    0
#define ABUF  16384                 // Q: 128 x 128B
#define ASTG  24576                 // K 8KB + Vh 8KB + Vl 8KB
#define A_K   0
#define A_VH  8192
#define A_VL  16384
#define ASTAGES 3
#define ATTN_SMEM (ABUF + ASTAGES * ASTG)   // 90112 -> 2 CTAs/SM

#define ASWZ(row, seg) ((uint32_t)(row) * 128 + ((uint32_t)((seg) ^ ((row) & 7)) * 16))

__global__ void __launch_bounds__(256, 2) attn_mma_kernel()
{
    extern __shared__ char smem[];
    const uint32_t sb = s2u(smem);
    const int tid  = threadIdx.x;
    const int lane = tid & 31;
    const int warp = tid >> 5;          // 0..7
    const int qt = blockIdx.x;          // 0..15 (128 queries each)
    const int bh = blockIdx.y;
    const int b  = bh & 1;
    const int h  = bh >> 1;

    // prologue: Q tile (128 rows x 64 d, fp16)
    {
        int prow = tid >> 1;
        int psb  = (tid & 1) * 4;
        int qtok = qt * 128 + prow;
        size_t gq = (size_t)(qtok * 2 + b) * EMB + h * HD + psb * 8;
        #pragma unroll
        for (int j = 0; j < 4; j++)
            cp16(sb + AQ + ASWZ(prow, psb + j), g_qf + gq + j * 8);
    }

    const int prow = tid >> 2;          // 0..63
    const int ps2  = (tid & 3) * 2;     // seg base 0,2,4,6

    #define APROD(kt)                                                         \
    do {                                                                      \
        uint32_t bufb = sb + ABUF + (uint32_t)((kt) % ASTAGES) * ASTG;        \
        int tok = (kt) * 64 + prow;                                           \
        size_t gk = (size_t)(tok * 2 + b) * EMB + h * HD;                     \
        size_t gv = ((size_t)bh * 64 + prow) * NTOK + (kt) * 64;              \
        _Pragma("unroll")                                                     \
        for (int j = 0; j < 2; j++) {                                         \
            int seg = ps2 + j;                                                \
            uint32_t o = ASWZ(prow, seg);                                     \
            cp16(bufb + A_K  + o, g_kf   + gk + seg * 8);                     \
            cp16(bufb + A_VH + o, g_vthf + gv + seg * 8);                     \
            cp16(bufb + A_VL + o, g_vtlf + gv + seg * 8);                     \
        }                                                                     \
    } while (0)

    APROD(0); CP_COMMIT();
    APROD(1); CP_COMMIT();

    float o[8][4];
    #pragma unroll
    for (int j = 0; j < 8; j++)
        #pragma unroll
        for (int v = 0; v < 4; v++) o[j][v] = 0.f;
    float m0 = -CUDART_INF_F, m1 = -CUDART_INF_F, l0 = 0.f, l1 = 0.f;
    uint32_t qf[4][4];

    const int NKT = NTOK / 64;
    for (int kt = 0; kt < NKT; kt++) {
        asm volatile("cp.async.wait_group 1;" ::: "memory");
        __syncthreads();

        if (kt + 2 < NKT) APROD(kt + 2);
        CP_COMMIT();

        const uint32_t kb = sb + ABUF + (uint32_t)(kt % ASTAGES) * ASTG;

        if (kt == 0) {
            #pragma unroll
            for (int ks = 0; ks < 4; ks++) {
                int row = warp * 16 + (lane & 15);
                int seg = ks * 2 + (lane >> 4);
                ldsm4(qf[ks], sb + AQ + ASWZ(row, seg));
            }
        }

        // S = Q K^T (1-pass fp16), m16 x n64 per warp
        float s[8][4];
        #pragma unroll
        for (int j = 0; j < 8; j++)
            #pragma unroll
            for (int v = 0; v < 4; v++) s[j][v] = 0.f;

        #pragma unroll
        for (int ks = 0; ks < 4; ks++) {
            #pragma unroll
            for (int nt = 0; nt < 4; nt++) {
                int row = nt * 16 + (lane & 7) + ((lane >> 4) & 1) * 8;
                int seg = ks * 2 + ((lane >> 3) & 1);
                uint32_t kf4[4];
                ldsm4(kf4, kb + A_K + ASWZ(row, seg));
                mma16816h(s[2 * nt],     qf[ks], kf4);
                mma16816h(s[2 * nt + 1], qf[ks], kf4 + 2);
            }
        }

        // online softmax (logits pre-scaled by log2e)
        float cm0 = -CUDART_INF_F, cm1 = -CUDART_INF_F;
        #pragma unroll
        for (int j = 0; j < 8; j++) {
            cm0 = fmaxf(cm0, fmaxf(s[j][0], s[j][1]));
            cm1 = fmaxf(cm1, fmaxf(s[j][2], s[j][3]));
        }
        cm0 = fmaxf(cm0, __shfl_xor_sync(0xffffffffu, cm0, 1));
        cm0 = fmaxf(cm0, __shfl_xor_sync(0xffffffffu, cm0, 2));
        cm1 = fmaxf(cm1, __shfl_xor_sync(0xffffffffu, cm1, 1));
        cm1 = fmaxf(cm1, __shfl_xor_sync(0xffffffffu, cm1, 2));
        float nm0 = fmaxf(m0, cm0), nm1 = fmaxf(m1, cm1);
        float al0 = ex2(m0 - nm0),  al1 = ex2(m1 - nm1);
        float rs0 = 0.f, rs1 = 0.f;
        #pragma unroll
        for (int j = 0; j < 8; j++) {
            s[j][0] = ex2(s[j][0] - nm0);
            s[j][1] = ex2(s[j][1] - nm0);
            s[j][2] = ex2(s[j][2] - nm1);
            s[j][3] = ex2(s[j][3] - nm1);
            rs0 += s[j][0] + s[j][1];
            rs1 += s[j][2] + s[j][3];
        }
        rs0 += __shfl_xor_sync(0xffffffffu, rs0, 1);
        rs0 += __shfl_xor_sync(0xffffffffu, rs0, 2);
        rs1 += __shfl_xor_sync(0xffffffffu, rs1, 1);
        rs1 += __shfl_xor_sync(0xffffffffu, rs1, 2);
        l0 = l0 * al0 + rs0; m0 = nm0;
        l1 = l1 * al1 + rs1; m1 = nm1;
        #pragma unroll
        for (int j = 0; j < 8; j++) {
            o[j][0] *= al0; o[j][1] *= al0;
            o[j][2] *= al1; o[j][3] *= al1;
        }

        // P fragments (fp16, 1-pass)
        uint32_t pf[4][4];
        #pragma unroll
        for (int ks = 0; ks < 4; ks++) {
            pf[ks][0] = pack2h(s[2 * ks][0],     s[2 * ks][1]);
            pf[ks][1] = pack2h(s[2 * ks][2],     s[2 * ks][3]);
            pf[ks][2] = pack2h(s[2 * ks + 1][0], s[2 * ks + 1][1]);
            pf[ks][3] = pack2h(s[2 * ks + 1][2], s[2 * ks + 1][3]);
        }

        // O += P (Vh + Vl)
        #pragma unroll
        for (int ks = 0; ks < 4; ks++) {
            #pragma unroll
            for (int nt = 0; nt < 4; nt++) {
                int row = nt * 16 + (lane & 7) + ((lane >> 4) & 1) * 8;
                int seg = ks * 2 + ((lane >> 3) & 1);
                uint32_t ad = ASWZ(row, seg);
                uint32_t vh4[4], vl4[4];
                ldsm4(vh4, kb + A_VH + ad);
                ldsm4(vl4, kb + A_VL + ad);
                mma16816h(o[2 * nt],     pf[ks], vh4);
                mma16816h(o[2 * nt],     pf[ks], vl4);
                mma16816h(o[2 * nt + 1], pf[ks], vh4 + 2);
                mma16816h(o[2 * nt + 1], pf[ks], vl4 + 2);
            }
        }
    }

    // epilogue: normalize, split to bf16 hi/lo ctx
    float inv0 = 1.0f / l0, inv1 = 1.0f / l1;
    int r0   = warp * 16 + (lane >> 2);
    int tok0 = qt * 128 + r0;
    int colb = h * HD + (lane & 3) * 2;
    size_t row0a = (size_t)(tok0 * 2 + b) * EMB;
    size_t row1a = (size_t)((tok0 + 8) * 2 + b) * EMB;
    #pragma unroll
    for (int j = 0; j < 8; j++) {
        int col = colb + 8 * j;
        uint32_t hu, lu;
        split2(o[j][0] * inv0, o[j][1] * inv0, hu, lu);
        *(uint32_t*)(g_ch + row0a + col) = hu;
        *(uint32_t*)(g_cl + row0a + col) = lu;
        split2(o[j][2] * inv1, o[j][3] * inv1, hu, lu);
        *(uint32_t*)(g_ch + row1a + col) = hu;
        *(uint32_t*)(g_cl + row1a + col) = lu;
    }
}

// ---------------------------------------------------------------------------
// Launch
// ---------------------------------------------------------------------------
extern "C" void kernel_launch(void* const* d_in, const int* in_sizes, int n_in,
                              void* d_out, int out_size)
{
    const float* seq   = (const float*)d_in[0];
    const float* w_qkv = (const float*)d_in[1];
    const float* b_qkv = (const float*)d_in[2];
    const float* w_out = (const float*)d_in[3];
    const float* b_out = (const float*)d_in[4];
    float* out = (float*)d_out;

    __nv_bfloat16 *sh, *sl, *wqh, *wql, *woh, *wol, *ch, *cl;
    cudaGetSymbolAddress((void**)&sh,   g_sh);
    cudaGetSymbolAddress((void**)&sl,   g_sl);
    cudaGetSymbolAddress((void**)&wqh,  g_wqh);
    cudaGetSymbolAddress((void**)&wql,  g_wql);
    cudaGetSymbolAddress((void**)&woh,  g_woh);
    cudaGetSymbolAddress((void**)&wol,  g_wol);
    cudaGetSymbolAddress((void**)&ch,   g_ch);
    cudaGetSymbolAddress((void**)&cl,   g_cl);

    cudaFuncSetAttribute(gemm_mma_kernel,
                         cudaFuncAttributeMaxDynamicSharedMemorySize, GSMEM);
    cudaFuncSetAttribute(attn_mma_kernel,
                         cudaFuncAttributeMaxDynamicSharedMemorySize, ATTN_SMEM);

    // 0) split inputs into bf16 hi/lo pairs
    {
        int n4 = MROWS * EMB / 4;
        convert_kernel<<<(n4 + 255) / 256, 256>>>((const float4*)seq,
                                                  (uint2*)sh, (uint2*)sl, n4);
        n4 = F3 * EMB / 4;
        convert_kernel<<<(n4 + 255) / 256, 256>>>((const float4*)w_qkv,
                                                  (uint2*)wqh, (uint2*)wql, n4);
        n4 = EMB * EMB / 4;
        convert_kernel<<<(n4 + 255) / 256, 256>>>((const float4*)w_out,
                                                  (uint2*)woh, (uint2*)wol, n4);
    }

    // 1) QKV projection -> fp16 Q (scaled), fp16 K, fp16 hi/lo V
    gemm_mma_kernel<<<dim3(F3 / 128, MROWS / 128), 256, GSMEM>>>(
        sh, sl, wqh, wql, b_qkv, nullptr, F3, EMB, 1);

    // 2) transpose V into [bh][d][tok]
    vtrans_kernel<<<dim3(NTOK / 64, BSZ * NH), 128>>>();

    // 3) fused flash attention (fp16 mma) -> bf16 hi/lo ctx
    attn_mma_kernel<<<dim3(NTOK / 128, BSZ * NH), 256, ATTN_SMEM>>>();

    // 4) output projection -> fp32 out
    gemm_mma_kernel<<<dim3(EMB / 128, MROWS / 128), 256, GSMEM>>>(
        ch, cl, woh, wol, b_out, out, EMB, EMB, 0);
}

// round 7
// speedup vs baseline: 4.3767x; 1.2779x over previous
#include <cuda_runtime.h>
#include <cuda_bf16.h>
#include <cuda_fp16.h>
#include <math_constants.h>
#include <cstdint>

// Problem constants
#define NTOK 2048
#define BSZ  2
#define EMB  1024
#define NH   16
#define HD   64
#define MROWS (NTOK*BSZ)      // 4096
#define F3   (3*EMB)          // 3072
#define QSCALE 0.1803368801111204f   // 0.125 * log2(e)

// -------------------- device scratch (allocation-free) ----------------------
__device__ __half g_sh[(size_t)MROWS * EMB];   // seq hi (fp16)
__device__ __half g_sl[(size_t)MROWS * EMB];   // seq lo
__device__ __half g_wq[(size_t)F3 * EMB];      // w_qkv fp16 (1-pass)
__device__ __half g_wo[(size_t)EMB * EMB];     // w_out fp16 (1-pass)
__device__ __half g_qf[(size_t)MROWS * EMB];   // Q fp16 (pre-scaled)
__device__ __half g_kf[(size_t)MROWS * EMB];   // K fp16
__device__ __half g_vh0[(size_t)MROWS * EMB];  // V hi fp16 (token-major)
__device__ __half g_vl0[(size_t)MROWS * EMB];  // V lo fp16
__device__ __half g_vthf[(size_t)BSZ * NH * HD * NTOK]; // V^T hi [bh][d][tok]
__device__ __half g_vtlf[(size_t)BSZ * NH * HD * NTOK]; // V^T lo
__device__ __half g_ch[(size_t)MROWS * EMB];   // attn out hi (fp16)
__device__ __half g_cl[(size_t)MROWS * EMB];   // attn out lo

// -------------------- PTX helpers -------------------------------------------
__device__ __forceinline__ uint32_t s2u(const void* p) {
    uint32_t a;
    asm("{ .reg .u64 t; cvta.to.shared.u64 t, %1; cvt.u32.u64 %0, t; }"
        : "=r"(a) : "l"(p));
    return a;
}

__device__ __forceinline__ void cp16(uint32_t dst, const void* src) {
    asm volatile("cp.async.cg.shared.global [%0], [%1], 16;"
                 :: "r"(dst), "l"(src) : "memory");
}
#define CP_COMMIT() asm volatile("cp.async.commit_group;" ::: "memory")

__device__ __forceinline__ void ldsm4(uint32_t* r, uint32_t a) {
    asm volatile("ldmatrix.sync.aligned.m8n8.x4.shared.b16 {%0,%1,%2,%3}, [%4];"
                 : "=r"(r[0]), "=r"(r[1]), "=r"(r[2]), "=r"(r[3]) : "r"(a));
}

__device__ __forceinline__ void mma16816h(float* c, const uint32_t* a,
                                           const uint32_t* b) {
    asm volatile(
        "mma.sync.aligned.m16n8k16.row.col.f32.f16.f16.f32 "
        "{%0,%1,%2,%3}, {%4,%5,%6,%7}, {%8,%9}, {%0,%1,%2,%3};"
        : "+f"(c[0]), "+f"(c[1]), "+f"(c[2]), "+f"(c[3])
        : "r"(a[0]), "r"(a[1]), "r"(a[2]), "r"(a[3]), "r"(b[0]), "r"(b[1]));
}

__device__ __forceinline__ float ex2(float x) {
    float y;
    asm("ex2.approx.f32 %0, %1;" : "=f"(y) : "f"(x));
    return y;
}

__device__ __forceinline__ uint32_t pack2h(float a, float b) {
    __half2 t = __floats2half2_rn(a, b);
    return *reinterpret_cast<uint32_t*>(&t);
}

__device__ __forceinline__ void split2h(float a, float b, uint32_t& h, uint32_t& l) {
    __half2 t = __floats2half2_rn(a, b);
    h = *reinterpret_cast<uint32_t*>(&t);
    float ra = a - __half2float(__low2half(t));
    float rb = b - __half2float(__high2half(t));
    __half2 t2 = __floats2half2_rn(ra, rb);
    l = *reinterpret_cast<uint32_t*>(&t2);
}

// -------------------- converts ----------------------------------------------
__global__ void convert_split_kernel(const float4* __restrict__ in,
                                     uint2* __restrict__ hi4,
                                     uint2* __restrict__ lo4, int n4) {
    int i = blockIdx.x * blockDim.x + threadIdx.x;
    if (i >= n4) return;
    float4 x = in[i];
    uint32_t h0, l0, h1, l1;
    split2h(x.x, x.y, h0, l0);
    split2h(x.z, x.w, h1, l1);
    uint2 hv, lv;
    hv.x = h0; hv.y = h1;
    lv.x = l0; lv.y = l1;
    hi4[i] = hv;
    lo4[i] = lv;
}

__global__ void convert_h_kernel(const float4* __restrict__ in,
                                 uint2* __restrict__ out4, int n4) {
    int i = blockIdx.x * blockDim.x + threadIdx.x;
    if (i >= n4) return;
    float4 x = in[i];
    uint2 o;
    o.x = pack2h(x.x, x.y);
    o.y = pack2h(x.z, x.w);
    out4[i] = o;
}

// -------------------- fp16 2-term split GEMM (mma.sync) ---------------------
// C = (Ah+Al)[M][K] * B[N][K]^T + bias[N]
// qkvmode=0: C fp32.  qkvmode=1: N=3072; comp0->g_qf(xQSCALE), comp1->g_kf,
// comp2->g_vh0/g_vl0 (fp16 split).
#define PITCH  48
#define TILEB  (128 * PITCH)       // 6144
#define STAGEB (3 * TILEB)         // 18432: Ah, Al, B
#define GSTG   4
#define GSMEM  (GSTG * STAGEB)     // 73728 -> 2 CTAs/SM

#define ARR_AH 0
#define ARR_AL TILEB
#define ARR_B  (2 * TILEB)

__global__ void __launch_bounds__(256, 2) gemm_mma_kernel(
    const __half* __restrict__ Ah, const __half* __restrict__ Al,
    const __half* __restrict__ B,
    const float* __restrict__ bias, float* __restrict__ C,
    int N, int K, int qkvmode)
{
    extern __shared__ char smem[];
    const uint32_t sb = s2u(smem);
    const int tid  = threadIdx.x;
    const int lane = tid & 31;
    const int warp = tid >> 5;
    const int wm   = warp & 3;
    const int wn   = warp >> 2;
    const int row0 = blockIdx.y * 128;
    const int col0 = blockIdx.x * 128;

    float acc[2][8][4];
    #pragma unroll
    for (int i = 0; i < 2; i++)
        #pragma unroll
        for (int j = 0; j < 8; j++)
            #pragma unroll
            for (int v = 0; v < 4; v++) acc[i][j][v] = 0.f;

    const uint32_t a_off = (uint32_t)(lane & 15) * PITCH + (lane >> 4) * 16;
    const uint32_t b_off = (uint32_t)((lane & 7) + ((lane >> 4) & 1) * 8) * PITCH
                         + ((lane >> 3) & 1) * 16;

    const int pr   = tid >> 1;
    const int pseg = tid & 1;
    const int nch  = K / 16;

    #define PRODUCE(c)                                                        \
    do {                                                                      \
        uint32_t base = sb + (uint32_t)((c) & 3) * STAGEB;                    \
        size_t gA = (size_t)(row0 + pr) * K + (c) * 16 + pseg * 8;            \
        size_t gB = (size_t)(col0 + pr) * K + (c) * 16 + pseg * 8;            \
        uint32_t so = (uint32_t)pr * PITCH + pseg * 16;                       \
        cp16(base + ARR_AH + so, Ah + gA);                                    \
        cp16(base + ARR_AL + so, Al + gA);                                    \
        cp16(base + ARR_B  + so, B  + gB);                                    \
    } while (0)

    PRODUCE(0); CP_COMMIT();
    PRODUCE(1); CP_COMMIT();
    PRODUCE(2); CP_COMMIT();

    for (int c = 0; c < nch; c++) {
        asm volatile("cp.async.wait_group 2;" ::: "memory");
        __syncthreads();

        if (c + 3 < nch) PRODUCE(c + 3);
        CP_COMMIT();

        const uint32_t st = sb + (uint32_t)(c & 3) * STAGEB;

        uint32_t ah[2][4], al[2][4];
        #pragma unroll
        for (int mt = 0; mt < 2; mt++) {
            uint32_t ra = (uint32_t)(wm * 32 + mt * 16) * PITCH + a_off;
            ldsm4(ah[mt], st + ARR_AH + ra);
            ldsm4(al[mt], st + ARR_AL + ra);
        }
        #pragma unroll
        for (int nt = 0; nt < 4; nt++) {
            uint32_t b4[4];
            uint32_t rb = (uint32_t)(wn * 64 + nt * 16) * PITCH + b_off;
            ldsm4(b4, st + ARR_B + rb);
            // hi pass: 4 independent MMAs, then lo pass (RAW distance = 4)
            mma16816h(acc[0][2 * nt],     ah[0], b4);
            mma16816h(acc[1][2 * nt],     ah[1], b4);
            mma16816h(acc[0][2 * nt + 1], ah[0], b4 + 2);
            mma16816h(acc[1][2 * nt + 1], ah[1], b4 + 2);
            mma16816h(acc[0][2 * nt],     al[0], b4);
            mma16816h(acc[1][2 * nt],     al[1], b4);
            mma16816h(acc[0][2 * nt + 1], al[0], b4 + 2);
            mma16816h(acc[1][2 * nt + 1], al[1], b4 + 2);
        }
    }

    const int tr = lane >> 2;
    const int tc = (lane & 3) * 2;
    const int comp = col0 >> 10;
    #pragma unroll
    for (int mt = 0; mt < 2; mt++) {
        #pragma unroll
        for (int n8 = 0; n8 < 8; n8++) {
            int r  = row0 + wm * 32 + mt * 16 + tr;
            int cc = col0 + wn * 64 + n8 * 8 + tc;
            float b0 = bias[cc], b1 = bias[cc + 1];
            float v0 = acc[mt][n8][0] + b0;
            float v1 = acc[mt][n8][1] + b1;
            float v2 = acc[mt][n8][2] + b0;
            float v3 = acc[mt][n8][3] + b1;
            if (qkvmode) {
                int ccl = cc - (comp << 10);
                size_t o0 = (size_t)r * EMB + ccl;
                size_t o1 = (size_t)(r + 8) * EMB + ccl;
                if (comp == 0) {
                    *(uint32_t*)(g_qf + o0) = pack2h(v0 * QSCALE, v1 * QSCALE);
                    *(uint32_t*)(g_qf + o1) = pack2h(v2 * QSCALE, v3 * QSCALE);
                } else if (comp == 1) {
                    *(uint32_t*)(g_kf + o0) = pack2h(v0, v1);
                    *(uint32_t*)(g_kf + o1) = pack2h(v2, v3);
                } else {
                    uint32_t h, l;
                    split2h(v0, v1, h, l);
                    *(uint32_t*)(g_vh0 + o0) = h;
                    *(uint32_t*)(g_vl0 + o0) = l;
                    split2h(v2, v3, h, l);
                    *(uint32_t*)(g_vh0 + o1) = h;
                    *(uint32_t*)(g_vl0 + o1) = l;
                }
            } else {
                *(float2*)(C + (size_t)r * N + cc)       = make_float2(v0, v1);
                *(float2*)(C + (size_t)(r + 8) * N + cc) = make_float2(v2, v3);
            }
        }
    }
}

// -------------------- V transpose: g_vh0/g_vl0 -> vt[bh][d][tok] -------------
__global__ void __launch_bounds__(128) vtrans_kernel()
{
    __shared__ ushort sh[64][72];
    __shared__ ushort sl[64][72];
    const int tid = threadIdx.x;
    const int bh  = blockIdx.y;
    const int b   = bh & 1;
    const int h   = bh >> 1;
    const int tok0 = blockIdx.x * 64;

    {
        int tl = tid >> 1;
        int row = (tok0 + tl) * 2 + b;
        size_t base = (size_t)row * EMB + h * HD;
        #pragma unroll
        for (int j = 0; j < 4; j++) {
            int seg = (tid & 1) * 4 + j;
            uint4 vh = *(const uint4*)((const ushort*)g_vh0 + base + seg * 8);
            uint4 vl = *(const uint4*)((const ushort*)g_vl0 + base + seg * 8);
            *(uint4*)(&sh[tl][seg * 8]) = vh;
            *(uint4*)(&sl[tl][seg * 8]) = vl;
        }
    }
    __syncthreads();
    {
        int d = tid >> 1;
        int th = (tid & 1) * 32;
        size_t obase = ((size_t)bh * 64 + d) * NTOK + tok0 + th;
        #pragma unroll
        for (int q = 0; q < 4; q++) {
            ushort th8[8], tl8[8];
            #pragma unroll
            for (int i = 0; i < 8; i++) {
                th8[i] = sh[th + q * 8 + i][d];
                tl8[i] = sl[th + q * 8 + i][d];
            }
            *(uint4*)((ushort*)g_vthf + obase + q * 8) = *(uint4*)th8;
            *(uint4*)((ushort*)g_vtlf + obase + q * 8) = *(uint4*)tl8;
        }
    }
}

// -------------------- flash attention (fp16 mma, split V) -------------------
#define AQ    0
#define ABUF  16384
#define ASTG  24576
#define A_K   0
#define A_VH  8192
#define A_VL  16384
#define ASTAGES 3
#define ATTN_SMEM (ABUF + ASTAGES * ASTG)   // 90112 -> 2 CTAs/SM

#define ASWZ(row, seg) ((uint32_t)(row) * 128 + ((uint32_t)((seg) ^ ((row) & 7)) * 16))

__global__ void __launch_bounds__(256, 2) attn_mma_kernel()
{
    extern __shared__ char smem[];
    const uint32_t sb = s2u(smem);
    const int tid  = threadIdx.x;
    const int lane = tid & 31;
    const int warp = tid >> 5;
    const int qt = blockIdx.x;
    const int bh = blockIdx.y;
    const int b  = bh & 1;
    const int h  = bh >> 1;

    {
        int prow = tid >> 1;
        int psb  = (tid & 1) * 4;
        int qtok = qt * 128 + prow;
        size_t gq = (size_t)(qtok * 2 + b) * EMB + h * HD + psb * 8;
        #pragma unroll
        for (int j = 0; j < 4; j++)
            cp16(sb + AQ + ASWZ(prow, psb + j), g_qf + gq + j * 8);
    }

    const int prow = tid >> 2;
    const int ps2  = (tid & 3) * 2;

    #define APROD(kt)                                                         \
    do {                                                                      \
        uint32_t bufb = sb + ABUF + (uint32_t)((kt) % ASTAGES) * ASTG;        \
        int tok = (kt) * 64 + prow;                                           \
        size_t gk = (size_t)(tok * 2 + b) * EMB + h * HD;                     \
        size_t gv = ((size_t)bh * 64 + prow) * NTOK + (kt) * 64;              \
        _Pragma("unroll")                                                     \
        for (int j = 0; j < 2; j++) {                                         \
            int seg = ps2 + j;                                                \
            uint32_t o = ASWZ(prow, seg);                                     \
            cp16(bufb + A_K  + o, g_kf   + gk + seg * 8);                     \
            cp16(bufb + A_VH + o, g_vthf + gv + seg * 8);                     \
            cp16(bufb + A_VL + o, g_vtlf + gv + seg * 8);                     \
        }                                                                     \
    } while (0)

    APROD(0); CP_COMMIT();
    APROD(1); CP_COMMIT();

    float o[8][4];
    #pragma unroll
    for (int j = 0; j < 8; j++)
        #pragma unroll
        for (int v = 0; v < 4; v++) o[j][v] = 0.f;
    float m0 = -CUDART_INF_F, m1 = -CUDART_INF_F, l0 = 0.f, l1 = 0.f;
    uint32_t qf[4][4];

    const int NKT = NTOK / 64;
    for (int kt = 0; kt < NKT; kt++) {
        asm volatile("cp.async.wait_group 1;" ::: "memory");
        __syncthreads();

        if (kt + 2 < NKT) APROD(kt + 2);
        CP_COMMIT();

        const uint32_t kb = sb + ABUF + (uint32_t)(kt % ASTAGES) * ASTG;

        if (kt == 0) {
            #pragma unroll
            for (int ks = 0; ks < 4; ks++) {
                int row = warp * 16 + (lane & 15);
                int seg = ks * 2 + (lane >> 4);
                ldsm4(qf[ks], sb + AQ + ASWZ(row, seg));
            }
        }

        float s[8][4];
        #pragma unroll
        for (int j = 0; j < 8; j++)
            #pragma unroll
            for (int v = 0; v < 4; v++) s[j][v] = 0.f;

        #pragma unroll
        for (int ks = 0; ks < 4; ks++) {
            #pragma unroll
            for (int nt = 0; nt < 4; nt++) {
                int row = nt * 16 + (lane & 7) + ((lane >> 4) & 1) * 8;
                int seg = ks * 2 + ((lane >> 3) & 1);
                uint32_t kf4[4];
                ldsm4(kf4, kb + A_K + ASWZ(row, seg));
                mma16816h(s[2 * nt],     qf[ks], kf4);
                mma16816h(s[2 * nt + 1], qf[ks], kf4 + 2);
            }
        }

        float cm0 = -CUDART_INF_F, cm1 = -CUDART_INF_F;
        #pragma unroll
        for (int j = 0; j < 8; j++) {
            cm0 = fmaxf(cm0, fmaxf(s[j][0], s[j][1]));
            cm1 = fmaxf(cm1, fmaxf(s[j][2], s[j][3]));
        }
        cm0 = fmaxf(cm0, __shfl_xor_sync(0xffffffffu, cm0, 1));
        cm0 = fmaxf(cm0, __shfl_xor_sync(0xffffffffu, cm0, 2));
        cm1 = fmaxf(cm1, __shfl_xor_sync(0xffffffffu, cm1, 1));
        cm1 = fmaxf(cm1, __shfl_xor_sync(0xffffffffu, cm1, 2));
        float nm0 = fmaxf(m0, cm0), nm1 = fmaxf(m1, cm1);
        float al0 = ex2(m0 - nm0),  al1 = ex2(m1 - nm1);
        float rs0 = 0.f, rs1 = 0.f;
        #pragma unroll
        for (int j = 0; j < 8; j++) {
            s[j][0] = ex2(s[j][0] - nm0);
            s[j][1] = ex2(s[j][1] - nm0);
            s[j][2] = ex2(s[j][2] - nm1);
            s[j][3] = ex2(s[j][3] - nm1);
            rs0 += s[j][0] + s[j][1];
            rs1 += s[j][2] + s[j][3];
        }
        rs0 += __shfl_xor_sync(0xffffffffu, rs0, 1);
        rs0 += __shfl_xor_sync(0xffffffffu, rs0, 2);
        rs1 += __shfl_xor_sync(0xffffffffu, rs1, 1);
        rs1 += __shfl_xor_sync(0xffffffffu, rs1, 2);
        l0 = l0 * al0 + rs0; m0 = nm0;
        l1 = l1 * al1 + rs1; m1 = nm1;
        #pragma unroll
        for (int j = 0; j < 8; j++) {
            o[j][0] *= al0; o[j][1] *= al0;
            o[j][2] *= al1; o[j][3] *= al1;
        }

        uint32_t pf[4][4];
        #pragma unroll
        for (int ks = 0; ks < 4; ks++) {
            pf[ks][0] = pack2h(s[2 * ks][0],     s[2 * ks][1]);
            pf[ks][1] = pack2h(s[2 * ks][2],     s[2 * ks][3]);
            pf[ks][2] = pack2h(s[2 * ks + 1][0], s[2 * ks + 1][1]);
            pf[ks][3] = pack2h(s[2 * ks + 1][2], s[2 * ks + 1][3]);
        }

        #pragma unroll
        for (int ks = 0; ks < 4; ks++) {
            #pragma unroll
            for (int nt = 0; nt < 4; nt++) {
                int row = nt * 16 + (lane & 7) + ((lane >> 4) & 1) * 8;
                int seg = ks * 2 + ((lane >> 3) & 1);
                uint32_t ad = ASWZ(row, seg);
                uint32_t vh4[4], vl4[4];
                ldsm4(vh4, kb + A_VH + ad);
                ldsm4(vl4, kb + A_VL + ad);
                mma16816h(o[2 * nt],     pf[ks], vh4);
                mma16816h(o[2 * nt + 1], pf[ks], vh4 + 2);
                mma16816h(o[2 * nt],     pf[ks], vl4);
                mma16816h(o[2 * nt + 1], pf[ks], vl4 + 2);
            }
        }
    }

    float inv0 = 1.0f / l0, inv1 = 1.0f / l1;
    int r0   = warp * 16 + (lane >> 2);
    int tok0 = qt * 128 + r0;
    int colb = h * HD + (lane & 3) * 2;
    size_t row0a = (size_t)(tok0 * 2 + b) * EMB;
    size_t row1a = (size_t)((tok0 + 8) * 2 + b) * EMB;
    #pragma unroll
    for (int j = 0; j < 8; j++) {
        int col = colb + 8 * j;
        uint32_t hu, lu;
        split2h(o[j][0] * inv0, o[j][1] * inv0, hu, lu);
        *(uint32_t*)(g_ch + row0a + col) = hu;
        *(uint32_t*)(g_cl + row0a + col) = lu;
        split2h(o[j][2] * inv1, o[j][3] * inv1, hu, lu);
        *(uint32_t*)(g_ch + row1a + col) = hu;
        *(uint32_t*)(g_cl + row1a + col) = lu;
    }
}

// ---------------------------------------------------------------------------
// Launch
// ---------------------------------------------------------------------------
extern "C" void kernel_launch(void* const* d_in, const int* in_sizes, int n_in,
                              void* d_out, int out_size)
{
    const float* seq   = (const float*)d_in[0];
    const float* w_qkv = (const float*)d_in[1];
    const float* b_qkv = (const float*)d_in[2];
    const float* w_out = (const float*)d_in[3];
    const float* b_out = (const float*)d_in[4];
    float* out = (float*)d_out;

    __half *sh, *sl, *wq, *wo, *ch, *cl;
    cudaGetSymbolAddress((void**)&sh, g_sh);
    cudaGetSymbolAddress((void**)&sl, g_sl);
    cudaGetSymbolAddress((void**)&wq, g_wq);
    cudaGetSymbolAddress((void**)&wo, g_wo);
    cudaGetSymbolAddress((void**)&ch, g_ch);
    cudaGetSymbolAddress((void**)&cl, g_cl);

    cudaFuncSetAttribute(gemm_mma_kernel,
                         cudaFuncAttributeMaxDynamicSharedMemorySize, GSMEM);
    cudaFuncSetAttribute(attn_mma_kernel,
                         cudaFuncAttributeMaxDynamicSharedMemorySize, ATTN_SMEM);

    // 0) converts: seq -> fp16 hi/lo; weights -> fp16 1-pass
    {
        int n4 = MROWS * EMB / 4;
        convert_split_kernel<<<(n4 + 255) / 256, 256>>>((const float4*)seq,
                                                        (uint2*)sh, (uint2*)sl, n4);
        n4 = F3 * EMB / 4;
        convert_h_kernel<<<(n4 + 255) / 256, 256>>>((const float4*)w_qkv,
                                                    (uint2*)wq, n4);
        n4 = EMB * EMB / 4;
        convert_h_kernel<<<(n4 + 255) / 256, 256>>>((const float4*)w_out,
                                                    (uint2*)wo, n4);
    }

    // 1) QKV projection -> fp16 Q (scaled), fp16 K, fp16 hi/lo V
    gemm_mma_kernel<<<dim3(F3 / 128, MROWS / 128), 256, GSMEM>>>(
        sh, sl, wq, b_qkv, nullptr, F3, EMB, 1);

    // 2) transpose V into [bh][d][tok]
    vtrans_kernel<<<dim3(NTOK / 64, BSZ * NH), 128>>>();

    // 3) fused flash attention (fp16 mma) -> fp16 hi/lo ctx
    attn_mma_kernel<<<dim3(NTOK / 128, BSZ * NH), 256, ATTN_SMEM>>>();

    // 4) output projection -> fp32 out
    gemm_mma_kernel<<<dim3(EMB / 128, MROWS / 128), 256, GSMEM>>>(
        ch, cl, wo, b_out, out, EMB, EMB, 0);
}

// round 8
// speedup vs baseline: 4.3992x; 1.0051x over previous
#include <cuda_runtime.h>
#include <cuda_bf16.h>
#include <cuda_fp16.h>
#include <math_constants.h>
#include <cstdint>

// Problem constants
#define NTOK 2048
#define BSZ  2
#define EMB  1024
#define NH   16
#define HD   64
#define MROWS (NTOK*BSZ)      // 4096
#define F3   (3*EMB)          // 3072
#define QSCALE 0.1803368801111204f   // 0.125 * log2(e)

// -------------------- device scratch (allocation-free) ----------------------
__device__ __half g_sh[(size_t)MROWS * EMB];   // seq hi (fp16)
__device__ __half g_sl[(size_t)MROWS * EMB];   // seq lo
__device__ __half g_wq[(size_t)F3 * EMB];      // w_qkv fp16 (1-pass)
__device__ __half g_wo[(size_t)EMB * EMB];     // w_out fp16 (1-pass)
__device__ __half g_qf[(size_t)MROWS * EMB];   // Q fp16 (pre-scaled)
__device__ __half g_kf[(size_t)MROWS * EMB];   // K fp16
__device__ __half g_vh0[(size_t)MROWS * EMB];  // V hi fp16 (token-major)
__device__ __half g_vl0[(size_t)MROWS * EMB];  // V lo fp16
__device__ __half g_vthf[(size_t)BSZ * NH * HD * NTOK]; // V^T hi [bh][d][tok]
__device__ __half g_vtlf[(size_t)BSZ * NH * HD * NTOK]; // V^T lo
__device__ __half g_ch[(size_t)MROWS * EMB];   // attn out hi (fp16)
__device__ __half g_cl[(size_t)MROWS * EMB];   // attn out lo

// -------------------- PTX helpers -------------------------------------------
__device__ __forceinline__ uint32_t s2u(const void* p) {
    uint32_t a;
    asm("{ .reg .u64 t; cvta.to.shared.u64 t, %1; cvt.u32.u64 %0, t; }"
        : "=r"(a) : "l"(p));
    return a;
}

__device__ __forceinline__ void cp16(uint32_t dst, const void* src) {
    asm volatile("cp.async.cg.shared.global [%0], [%1], 16;"
                 :: "r"(dst), "l"(src) : "memory");
}
#define CP_COMMIT() asm volatile("cp.async.commit_group;" ::: "memory")

__device__ __forceinline__ void ldsm4(uint32_t* r, uint32_t a) {
    asm volatile("ldmatrix.sync.aligned.m8n8.x4.shared.b16 {%0,%1,%2,%3}, [%4];"
                 : "=r"(r[0]), "=r"(r[1]), "=r"(r[2]), "=r"(r[3]) : "r"(a));
}

__device__ __forceinline__ void mma16816h(float* c, const uint32_t* a,
                                           const uint32_t* b) {
    asm volatile(
        "mma.sync.aligned.m16n8k16.row.col.f32.f16.f16.f32 "
        "{%0,%1,%2,%3}, {%4,%5,%6,%7}, {%8,%9}, {%0,%1,%2,%3};"
        : "+f"(c[0]), "+f"(c[1]), "+f"(c[2]), "+f"(c[3])
        : "r"(a[0]), "r"(a[1]), "r"(a[2]), "r"(a[3]), "r"(b[0]), "r"(b[1]));
}

__device__ __forceinline__ float ex2(float x) {
    float y;
    asm("ex2.approx.f32 %0, %1;" : "=f"(y) : "f"(x));
    return y;
}

__device__ __forceinline__ uint32_t pack2h(float a, float b) {
    __half2 t = __floats2half2_rn(a, b);
    return *reinterpret_cast<uint32_t*>(&t);
}

__device__ __forceinline__ void split2h(float a, float b, uint32_t& h, uint32_t& l) {
    __half2 t = __floats2half2_rn(a, b);
    h = *reinterpret_cast<uint32_t*>(&t);
    float ra = a - __half2float(__low2half(t));
    float rb = b - __half2float(__high2half(t));
    __half2 t2 = __floats2half2_rn(ra, rb);
    l = *reinterpret_cast<uint32_t*>(&t2);
}

// -------------------- converts ----------------------------------------------
__global__ void convert_split_kernel(const float4* __restrict__ in,
                                     uint2* __restrict__ hi4,
                                     uint2* __restrict__ lo4, int n4) {
    int i = blockIdx.x * blockDim.x + threadIdx.x;
    if (i >= n4) return;
    float4 x = in[i];
    uint32_t h0, l0, h1, l1;
    split2h(x.x, x.y, h0, l0);
    split2h(x.z, x.w, h1, l1);
    uint2 hv, lv;
    hv.x = h0; hv.y = h1;
    lv.x = l0; lv.y = l1;
    hi4[i] = hv;
    lo4[i] = lv;
}

__global__ void convert_h_kernel(const float4* __restrict__ in,
                                 uint2* __restrict__ out4, int n4) {
    int i = blockIdx.x * blockDim.x + threadIdx.x;
    if (i >= n4) return;
    float4 x = in[i];
    uint2 o;
    o.x = pack2h(x.x, x.y);
    o.y = pack2h(x.z, x.w);
    out4[i] = o;
}

// -------------------- fp16 2-term split GEMM (mma.sync) ---------------------
// C = (Ah+Al)[M][K] * B[N][K]^T + bias[N]
// qkvmode=0: C fp32.  qkvmode=1: N=3072; comp0->g_qf(xQSCALE), comp1->g_kf,
// comp2->g_vh0/g_vl0 (fp16 split).
#define PITCH  48
#define TILEB  (128 * PITCH)       // 6144
#define STAGEB (3 * TILEB)         // 18432: Ah, Al, B
#define GSTG   4
#define GSMEM  (GSTG * STAGEB)     // 73728 -> 2 CTAs/SM

#define ARR_AH 0
#define ARR_AL TILEB
#define ARR_B  (2 * TILEB)

__global__ void __launch_bounds__(256, 2) gemm_mma_kernel(
    const __half* __restrict__ Ah, const __half* __restrict__ Al,
    const __half* __restrict__ B,
    const float* __restrict__ bias, float* __restrict__ C,
    int N, int K, int qkvmode)
{
    extern __shared__ char smem[];
    const uint32_t sb = s2u(smem);
    const int tid  = threadIdx.x;
    const int lane = tid & 31;
    const int warp = tid >> 5;
    const int wm   = warp & 3;
    const int wn   = warp >> 2;
    const int row0 = blockIdx.y * 128;
    const int col0 = blockIdx.x * 128;

    float acc[2][8][4];
    #pragma unroll
    for (int i = 0; i < 2; i++)
        #pragma unroll
        for (int j = 0; j < 8; j++)
            #pragma unroll
            for (int v = 0; v < 4; v++) acc[i][j][v] = 0.f;

    const uint32_t a_off = (uint32_t)(lane & 15) * PITCH + (lane >> 4) * 16;
    const uint32_t b_off = (uint32_t)((lane & 7) + ((lane >> 4) & 1) * 8) * PITCH
                         + ((lane >> 3) & 1) * 16;

    const int pr   = tid >> 1;
    const int pseg = tid & 1;
    const int nch  = K / 16;

    #define PRODUCE(c)                                                        \
    do {                                                                      \
        uint32_t base = sb + (uint32_t)((c) & 3) * STAGEB;                    \
        size_t gA = (size_t)(row0 + pr) * K + (c) * 16 + pseg * 8;            \
        size_t gB = (size_t)(col0 + pr) * K + (c) * 16 + pseg * 8;            \
        uint32_t so = (uint32_t)pr * PITCH + pseg * 16;                       \
        cp16(base + ARR_AH + so, Ah + gA);                                    \
        cp16(base + ARR_AL + so, Al + gA);                                    \
        cp16(base + ARR_B  + so, B  + gB);                                    \
    } while (0)

    PRODUCE(0); CP_COMMIT();
    PRODUCE(1); CP_COMMIT();
    PRODUCE(2); CP_COMMIT();

    for (int c = 0; c < nch; c++) {
        asm volatile("cp.async.wait_group 2;" ::: "memory");
        __syncthreads();

        if (c + 3 < nch) PRODUCE(c + 3);
        CP_COMMIT();

        const uint32_t st = sb + (uint32_t)(c & 3) * STAGEB;
        const uint32_t brow = (uint32_t)(wn * 64) * PITCH + b_off;

        // software pipeline: B-fragment double buffer, ldsm(nt+1) before MMA(nt)
        uint32_t ah[2][4], al[2][4], bfr[2][4];
        ldsm4(bfr[0], st + ARR_B + brow);
        #pragma unroll
        for (int mt = 0; mt < 2; mt++) {
            uint32_t ra = (uint32_t)(wm * 32 + mt * 16) * PITCH + a_off;
            ldsm4(ah[mt], st + ARR_AH + ra);
            ldsm4(al[mt], st + ARR_AL + ra);
        }
        #pragma unroll
        for (int nt = 0; nt < 4; nt++) {
            if (nt < 3)
                ldsm4(bfr[(nt + 1) & 1], st + ARR_B + brow + (uint32_t)((nt + 1) * 16) * PITCH);
            const uint32_t* b4 = bfr[nt & 1];
            mma16816h(acc[0][2 * nt],     ah[0], b4);
            mma16816h(acc[1][2 * nt],     ah[1], b4);
            mma16816h(acc[0][2 * nt + 1], ah[0], b4 + 2);
            mma16816h(acc[1][2 * nt + 1], ah[1], b4 + 2);
            mma16816h(acc[0][2 * nt],     al[0], b4);
            mma16816h(acc[1][2 * nt],     al[1], b4);
            mma16816h(acc[0][2 * nt + 1], al[0], b4 + 2);
            mma16816h(acc[1][2 * nt + 1], al[1], b4 + 2);
        }
    }

    const int tr = lane >> 2;
    const int tc = (lane & 3) * 2;
    const int comp = col0 >> 10;
    #pragma unroll
    for (int mt = 0; mt < 2; mt++) {
        #pragma unroll
        for (int n8 = 0; n8 < 8; n8++) {
            int r  = row0 + wm * 32 + mt * 16 + tr;
            int cc = col0 + wn * 64 + n8 * 8 + tc;
            float b0 = bias[cc], b1 = bias[cc + 1];
            float v0 = acc[mt][n8][0] + b0;
            float v1 = acc[mt][n8][1] + b1;
            float v2 = acc[mt][n8][2] + b0;
            float v3 = acc[mt][n8][3] + b1;
            if (qkvmode) {
                int ccl = cc - (comp << 10);
                size_t o0 = (size_t)r * EMB + ccl;
                size_t o1 = (size_t)(r + 8) * EMB + ccl;
                if (comp == 0) {
                    *(uint32_t*)(g_qf + o0) = pack2h(v0 * QSCALE, v1 * QSCALE);
                    *(uint32_t*)(g_qf + o1) = pack2h(v2 * QSCALE, v3 * QSCALE);
                } else if (comp == 1) {
                    *(uint32_t*)(g_kf + o0) = pack2h(v0, v1);
                    *(uint32_t*)(g_kf + o1) = pack2h(v2, v3);
                } else {
                    uint32_t h, l;
                    split2h(v0, v1, h, l);
                    *(uint32_t*)(g_vh0 + o0) = h;
                    *(uint32_t*)(g_vl0 + o0) = l;
                    split2h(v2, v3, h, l);
                    *(uint32_t*)(g_vh0 + o1) = h;
                    *(uint32_t*)(g_vl0 + o1) = l;
                }
            } else {
                *(float2*)(C + (size_t)r * N + cc)       = make_float2(v0, v1);
                *(float2*)(C + (size_t)(r + 8) * N + cc) = make_float2(v2, v3);
            }
        }
    }
}

// -------------------- V transpose: g_vh0/g_vl0 -> vt[bh][d][tok] -------------
__global__ void __launch_bounds__(128) vtrans_kernel()
{
    __shared__ ushort sh[64][72];
    __shared__ ushort sl[64][72];
    const int tid = threadIdx.x;
    const int bh  = blockIdx.y;
    const int b   = bh & 1;
    const int h   = bh >> 1;
    const int tok0 = blockIdx.x * 64;

    {
        int tl = tid >> 1;
        int row = (tok0 + tl) * 2 + b;
        size_t base = (size_t)row * EMB + h * HD;
        #pragma unroll
        for (int j = 0; j < 4; j++) {
            int seg = (tid & 1) * 4 + j;
            uint4 vh = *(const uint4*)((const ushort*)g_vh0 + base + seg * 8);
            uint4 vl = *(const uint4*)((const ushort*)g_vl0 + base + seg * 8);
            *(uint4*)(&sh[tl][seg * 8]) = vh;
            *(uint4*)(&sl[tl][seg * 8]) = vl;
        }
    }
    __syncthreads();
    {
        int d = tid >> 1;
        int th = (tid & 1) * 32;
        size_t obase = ((size_t)bh * 64 + d) * NTOK + tok0 + th;
        #pragma unroll
        for (int q = 0; q < 4; q++) {
            ushort th8[8], tl8[8];
            #pragma unroll
            for (int i = 0; i < 8; i++) {
                th8[i] = sh[th + q * 8 + i][d];
                tl8[i] = sl[th + q * 8 + i][d];
            }
            *(uint4*)((ushort*)g_vthf + obase + q * 8) = *(uint4*)th8;
            *(uint4*)((ushort*)g_vtlf + obase + q * 8) = *(uint4*)tl8;
        }
    }
}

// -------------------- flash attention (fp16 mma, split V) -------------------
#define AQ    0
#define ABUF  16384
#define ASTG  24576
#define A_K   0
#define A_VH  8192
#define A_VL  16384
#define ASTAGES 3
#define ATTN_SMEM (ABUF + ASTAGES * ASTG)   // 90112 -> 2 CTAs/SM

#define ASWZ(row, seg) ((uint32_t)(row) * 128 + ((uint32_t)((seg) ^ ((row) & 7)) * 16))

__global__ void __launch_bounds__(256, 2) attn_mma_kernel()
{
    extern __shared__ char smem[];
    const uint32_t sb = s2u(smem);
    const int tid  = threadIdx.x;
    const int lane = tid & 31;
    const int warp = tid >> 5;
    const int qt = blockIdx.x;
    const int bh = blockIdx.y;
    const int b  = bh & 1;
    const int h  = bh >> 1;

    {
        int prow = tid >> 1;
        int psb  = (tid & 1) * 4;
        int qtok = qt * 128 + prow;
        size_t gq = (size_t)(qtok * 2 + b) * EMB + h * HD + psb * 8;
        #pragma unroll
        for (int j = 0; j < 4; j++)
            cp16(sb + AQ + ASWZ(prow, psb + j), g_qf + gq + j * 8);
    }

    const int prow = tid >> 2;
    const int ps2  = (tid & 3) * 2;

    #define APROD(kt)                                                         \
    do {                                                                      \
        uint32_t bufb = sb + ABUF + (uint32_t)((kt) % ASTAGES) * ASTG;        \
        int tok = (kt) * 64 + prow;                                           \
        size_t gk = (size_t)(tok * 2 + b) * EMB + h * HD;                     \
        size_t gv = ((size_t)bh * 64 + prow) * NTOK + (kt) * 64;              \
        _Pragma("unroll")                                                     \
        for (int j = 0; j < 2; j++) {                                         \
            int seg = ps2 + j;                                                \
            uint32_t o = ASWZ(prow, seg);                                     \
            cp16(bufb + A_K  + o, g_kf   + gk + seg * 8);                     \
            cp16(bufb + A_VH + o, g_vthf + gv + seg * 8);                     \
            cp16(bufb + A_VL + o, g_vtlf + gv + seg * 8);                     \
        }                                                                     \
    } while (0)

    APROD(0); CP_COMMIT();
    APROD(1); CP_COMMIT();

    float o[8][4];
    #pragma unroll
    for (int j = 0; j < 8; j++)
        #pragma unroll
        for (int v = 0; v < 4; v++) o[j][v] = 0.f;
    float m0 = -CUDART_INF_F, m1 = -CUDART_INF_F, l0 = 0.f, l1 = 0.f;
    uint32_t qf[4][4];

    // per-lane ldmatrix row/seg components for B operands
    const int brow_l = (lane & 7) + ((lane >> 4) & 1) * 8;
    const int bseg_l = (lane >> 3) & 1;

    const int NKT = NTOK / 64;
    for (int kt = 0; kt < NKT; kt++) {
        asm volatile("cp.async.wait_group 1;" ::: "memory");
        __syncthreads();

        if (kt + 2 < NKT) APROD(kt + 2);
        CP_COMMIT();

        const uint32_t kb = sb + ABUF + (uint32_t)(kt % ASTAGES) * ASTG;

        if (kt == 0) {
            #pragma unroll
            for (int ks = 0; ks < 4; ks++) {
                int row = warp * 16 + (lane & 15);
                int seg = ks * 2 + (lane >> 4);
                ldsm4(qf[ks], sb + AQ + ASWZ(row, seg));
            }
        }

        // S = Q K^T, pipelined K-fragment double buffer (16 iter: ks*4+nt)
        float s[8][4];
        #pragma unroll
        for (int j = 0; j < 8; j++)
            #pragma unroll
            for (int v = 0; v < 4; v++) s[j][v] = 0.f;

        {
            uint32_t kbf[2][4];
            ldsm4(kbf[0], kb + A_K + ASWZ(brow_l, bseg_l));
            #pragma unroll
            for (int it = 0; it < 16; it++) {
                const int ks = it >> 2, nt = it & 3;
                if (it < 15) {
                    const int ks2 = (it + 1) >> 2, nt2 = (it + 1) & 3;
                    ldsm4(kbf[(it + 1) & 1],
                          kb + A_K + ASWZ(nt2 * 16 + brow_l, ks2 * 2 + bseg_l));
                }
                const uint32_t* k4 = kbf[it & 1];
                mma16816h(s[2 * nt],     qf[ks], k4);
                mma16816h(s[2 * nt + 1], qf[ks], k4 + 2);
            }
        }

        float cm0 = -CUDART_INF_F, cm1 = -CUDART_INF_F;
        #pragma unroll
        for (int j = 0; j < 8; j++) {
            cm0 = fmaxf(cm0, fmaxf(s[j][0], s[j][1]));
            cm1 = fmaxf(cm1, fmaxf(s[j][2], s[j][3]));
        }
        cm0 = fmaxf(cm0, __shfl_xor_sync(0xffffffffu, cm0, 1));
        cm0 = fmaxf(cm0, __shfl_xor_sync(0xffffffffu, cm0, 2));
        cm1 = fmaxf(cm1, __shfl_xor_sync(0xffffffffu, cm1, 1));
        cm1 = fmaxf(cm1, __shfl_xor_sync(0xffffffffu, cm1, 2));
        float nm0 = fmaxf(m0, cm0), nm1 = fmaxf(m1, cm1);
        float al0 = ex2(m0 - nm0),  al1 = ex2(m1 - nm1);
        float rs0 = 0.f, rs1 = 0.f;
        #pragma unroll
        for (int j = 0; j < 8; j++) {
            s[j][0] = ex2(s[j][0] - nm0);
            s[j][1] = ex2(s[j][1] - nm0);
            s[j][2] = ex2(s[j][2] - nm1);
            s[j][3] = ex2(s[j][3] - nm1);
            rs0 += s[j][0] + s[j][1];
            rs1 += s[j][2] + s[j][3];
        }
        rs0 += __shfl_xor_sync(0xffffffffu, rs0, 1);
        rs0 += __shfl_xor_sync(0xffffffffu, rs0, 2);
        rs1 += __shfl_xor_sync(0xffffffffu, rs1, 1);
        rs1 += __shfl_xor_sync(0xffffffffu, rs1, 2);
        l0 = l0 * al0 + rs0; m0 = nm0;
        l1 = l1 * al1 + rs1; m1 = nm1;
        #pragma unroll
        for (int j = 0; j < 8; j++) {
            o[j][0] *= al0; o[j][1] *= al0;
            o[j][2] *= al1; o[j][3] *= al1;
        }

        uint32_t pf[4][4];
        #pragma unroll
        for (int ks = 0; ks < 4; ks++) {
            pf[ks][0] = pack2h(s[2 * ks][0],     s[2 * ks][1]);
            pf[ks][1] = pack2h(s[2 * ks][2],     s[2 * ks][3]);
            pf[ks][2] = pack2h(s[2 * ks + 1][0], s[2 * ks + 1][1]);
            pf[ks][3] = pack2h(s[2 * ks + 1][2], s[2 * ks + 1][3]);
        }

        // O += P(Vh+Vl), pipelined V-fragment double buffers
        {
            uint32_t vhb[2][4], vlb[2][4];
            ldsm4(vhb[0], kb + A_VH + ASWZ(brow_l, bseg_l));
            ldsm4(vlb[0], kb + A_VL + ASWZ(brow_l, bseg_l));
            #pragma unroll
            for (int it = 0; it < 16; it++) {
                const int ks = it >> 2, nt = it & 3;
                if (it < 15) {
                    const int ks2 = (it + 1) >> 2, nt2 = (it + 1) & 3;
                    uint32_t ad = ASWZ(nt2 * 16 + brow_l, ks2 * 2 + bseg_l);
                    ldsm4(vhb[(it + 1) & 1], kb + A_VH + ad);
                    ldsm4(vlb[(it + 1) & 1], kb + A_VL + ad);
                }
                const uint32_t* vh4 = vhb[it & 1];
                const uint32_t* vl4 = vlb[it & 1];
                mma16816h(o[2 * nt],     pf[ks], vh4);
                mma16816h(o[2 * nt + 1], pf[ks], vh4 + 2);
                mma16816h(o[2 * nt],     pf[ks], vl4);
                mma16816h(o[2 * nt + 1], pf[ks], vl4 + 2);
            }
        }
    }

    float inv0 = 1.0f / l0, inv1 = 1.0f / l1;
    int r0   = warp * 16 + (lane >> 2);
    int tok0 = qt * 128 + r0;
    int colb = h * HD + (lane & 3) * 2;
    size_t row0a = (size_t)(tok0 * 2 + b) * EMB;
    size_t row1a = (size_t)((tok0 + 8) * 2 + b) * EMB;
    #pragma unroll
    for (int j = 0; j < 8; j++) {
        int col = colb + 8 * j;
        uint32_t hu, lu;
        split2h(o[j][0] * inv0, o[j][1] * inv0, hu, lu);
        *(uint32_t*)(g_ch + row0a + col) = hu;
        *(uint32_t*)(g_cl + row0a + col) = lu;
        split2h(o[j][2] * inv1, o[j][3] * inv1, hu, lu);
        *(uint32_t*)(g_ch + row1a + col) = hu;
        *(uint32_t*)(g_cl + row1a + col) = lu;
    }
}

// ---------------------------------------------------------------------------
// Launch
// ---------------------------------------------------------------------------
extern "C" void kernel_launch(void* const* d_in, const int* in_sizes, int n_in,
                              void* d_out, int out_size)
{
    const float* seq   = (const float*)d_in[0];
    const float* w_qkv = (const float*)d_in[1];
    const float* b_qkv = (const float*)d_in[2];
    const float* w_out = (const float*)d_in[3];
    const float* b_out = (const float*)d_in[4];
    float* out = (float*)d_out;

    __half *sh, *sl, *wq, *wo, *ch, *cl;
    cudaGetSymbolAddress((void**)&sh, g_sh);
    cudaGetSymbolAddress((void**)&sl, g_sl);
    cudaGetSymbolAddress((void**)&wq, g_wq);
    cudaGetSymbolAddress((void**)&wo, g_wo);
    cudaGetSymbolAddress((void**)&ch, g_ch);
    cudaGetSymbolAddress((void**)&cl, g_cl);

    cudaFuncSetAttribute(gemm_mma_kernel,
                         cudaFuncAttributeMaxDynamicSharedMemorySize, GSMEM);
    cudaFuncSetAttribute(attn_mma_kernel,
                         cudaFuncAttributeMaxDynamicSharedMemorySize, ATTN_SMEM);

    // 0) converts: seq -> fp16 hi/lo; weights -> fp16 1-pass
    {
        int n4 = MROWS * EMB / 4;
        convert_split_kernel<<<(n4 + 255) / 256, 256>>>((const float4*)seq,
                                                        (uint2*)sh, (uint2*)sl, n4);
        n4 = F3 * EMB / 4;
        convert_h_kernel<<<(n4 + 255) / 256, 256>>>((const float4*)w_qkv,
                                                    (uint2*)wq, n4);
        n4 = EMB * EMB / 4;
        convert_h_kernel<<<(n4 + 255) / 256, 256>>>((const float4*)w_out,
                                                    (uint2*)wo, n4);
    }

    // 1) QKV projection -> fp16 Q (scaled), fp16 K, fp16 hi/lo V
    gemm_mma_kernel<<<dim3(F3 / 128, MROWS / 128), 256, GSMEM>>>(
        sh, sl, wq, b_qkv, nullptr, F3, EMB, 1);

    // 2) transpose V into [bh][d][tok]
    vtrans_kernel<<<dim3(NTOK / 64, BSZ * NH), 128>>>();

    // 3) fused flash attention (fp16 mma) -> fp16 hi/lo ctx
    attn_mma_kernel<<<dim3(NTOK / 128, BSZ * NH), 256, ATTN_SMEM>>>();

    // 4) output projection -> fp32 out
    gemm_mma_kernel<<<dim3(EMB / 128, MROWS / 128), 256, GSMEM>>>(
        ch, cl, wo, b_out, out, EMB, EMB, 0);
}

// round 9
// speedup vs baseline: 5.4806x; 1.2458x over previous
#include <cuda_runtime.h>
#include <cuda_bf16.h>
#include <cuda_fp16.h>
#include <math_constants.h>
#include <cstdint>

// Problem constants
#define NTOK 2048
#define BSZ  2
#define EMB  1024
#define NH   16
#define HD   64
#define MROWS (NTOK*BSZ)      // 4096
#define F3   (3*EMB)          // 3072
#define QSCALE 0.1803368801111204f   // 0.125 * log2(e)

// -------------------- device scratch (allocation-free) ----------------------
__device__ __half g_sh[(size_t)MROWS * EMB];   // seq fp16 (1-pass)
__device__ __half g_wq[(size_t)F3 * EMB];      // w_qkv fp16 (1-pass)
__device__ __half g_wo[(size_t)EMB * EMB];     // w_out fp16 (1-pass)
__device__ __half g_qf[(size_t)MROWS * EMB];   // Q fp16 (pre-scaled)
__device__ __half g_kf[(size_t)MROWS * EMB];   // K fp16
__device__ __half g_vh0[(size_t)MROWS * EMB];  // V hi fp16 (token-major)
__device__ __half g_vl0[(size_t)MROWS * EMB];  // V lo fp16
__device__ __half g_vthf[(size_t)BSZ * NH * HD * NTOK]; // V^T hi [bh][d][tok]
__device__ __half g_vtlf[(size_t)BSZ * NH * HD * NTOK]; // V^T lo
__device__ __half g_ch[(size_t)MROWS * EMB];   // attn out fp16 (1-pass)

// -------------------- PTX helpers -------------------------------------------
__device__ __forceinline__ uint32_t s2u(const void* p) {
    uint32_t a;
    asm("{ .reg .u64 t; cvta.to.shared.u64 t, %1; cvt.u32.u64 %0, t; }"
        : "=r"(a) : "l"(p));
    return a;
}

__device__ __forceinline__ void cp16(uint32_t dst, const void* src) {
    asm volatile("cp.async.cg.shared.global [%0], [%1], 16;"
                 :: "r"(dst), "l"(src) : "memory");
}
#define CP_COMMIT() asm volatile("cp.async.commit_group;" ::: "memory")

__device__ __forceinline__ void ldsm4(uint32_t* r, uint32_t a) {
    asm volatile("ldmatrix.sync.aligned.m8n8.x4.shared.b16 {%0,%1,%2,%3}, [%4];"
                 : "=r"(r[0]), "=r"(r[1]), "=r"(r[2]), "=r"(r[3]) : "r"(a));
}

__device__ __forceinline__ void mma16816h(float* c, const uint32_t* a,
                                           const uint32_t* b) {
    asm volatile(
        "mma.sync.aligned.m16n8k16.row.col.f32.f16.f16.f32 "
        "{%0,%1,%2,%3}, {%4,%5,%6,%7}, {%8,%9}, {%0,%1,%2,%3};"
        : "+f"(c[0]), "+f"(c[1]), "+f"(c[2]), "+f"(c[3])
        : "r"(a[0]), "r"(a[1]), "r"(a[2]), "r"(a[3]), "r"(b[0]), "r"(b[1]));
}

__device__ __forceinline__ float ex2(float x) {
    float y;
    asm("ex2.approx.f32 %0, %1;" : "=f"(y) : "f"(x));
    return y;
}

__device__ __forceinline__ uint32_t pack2h(float a, float b) {
    __half2 t = __floats2half2_rn(a, b);
    return *reinterpret_cast<uint32_t*>(&t);
}

__device__ __forceinline__ void split2h(float a, float b, uint32_t& h, uint32_t& l) {
    __half2 t = __floats2half2_rn(a, b);
    h = *reinterpret_cast<uint32_t*>(&t);
    float ra = a - __half2float(__low2half(t));
    float rb = b - __half2float(__high2half(t));
    __half2 t2 = __floats2half2_rn(ra, rb);
    l = *reinterpret_cast<uint32_t*>(&t2);
}

// -------------------- converts ----------------------------------------------
__global__ void convert_h_kernel(const float4* __restrict__ in,
                                 uint2* __restrict__ out4, int n4) {
    int i = blockIdx.x * blockDim.x + threadIdx.x;
    if (i >= n4) return;
    float4 x = in[i];
    uint2 o;
    o.x = pack2h(x.x, x.y);
    o.y = pack2h(x.z, x.w);
    out4[i] = o;
}

// -------------------- fp16 1-pass GEMM (mma.sync) ----------------------------
// C = A[M][K] * B[N][K]^T + bias[N]
// qkvmode=0: C fp32.  qkvmode=1: N=3072; comp0->g_qf(xQSCALE), comp1->g_kf,
// comp2->g_vh0/g_vl0 (fp16 split).
#define PITCH  48
#define TILEB  (128 * PITCH)       // 6144
#define STAGEB (2 * TILEB)         // 12288: A, B
#define GSTG   4
#define GSMEM  (GSTG * STAGEB)     // 49152 -> 2 CTAs/SM (reg-limited)

#define ARR_A  0
#define ARR_B  TILEB

__global__ void __launch_bounds__(256, 2) gemm_mma_kernel(
    const __half* __restrict__ A, const __half* __restrict__ B,
    const float* __restrict__ bias, float* __restrict__ C,
    int N, int K, int qkvmode)
{
    extern __shared__ char smem[];
    const uint32_t sb = s2u(smem);
    const int tid  = threadIdx.x;
    const int lane = tid & 31;
    const int warp = tid >> 5;
    const int wm   = warp & 3;
    const int wn   = warp >> 2;
    const int row0 = blockIdx.y * 128;
    const int col0 = blockIdx.x * 128;

    float acc[2][8][4];
    #pragma unroll
    for (int i = 0; i < 2; i++)
        #pragma unroll
        for (int j = 0; j < 8; j++)
            #pragma unroll
            for (int v = 0; v < 4; v++) acc[i][j][v] = 0.f;

    const uint32_t a_off = (uint32_t)(lane & 15) * PITCH + (lane >> 4) * 16;
    const uint32_t b_off = (uint32_t)((lane & 7) + ((lane >> 4) & 1) * 8) * PITCH
                         + ((lane >> 3) & 1) * 16;

    const int pr   = tid >> 1;
    const int pseg = tid & 1;
    const int nch  = K / 16;

    #define PRODUCE(c)                                                        \
    do {                                                                      \
        uint32_t base = sb + (uint32_t)((c) & 3) * STAGEB;                    \
        size_t gA = (size_t)(row0 + pr) * K + (c) * 16 + pseg * 8;            \
        size_t gB = (size_t)(col0 + pr) * K + (c) * 16 + pseg * 8;            \
        uint32_t so = (uint32_t)pr * PITCH + pseg * 16;                       \
        cp16(base + ARR_A + so, A + gA);                                      \
        cp16(base + ARR_B + so, B + gB);                                      \
    } while (0)

    PRODUCE(0); CP_COMMIT();
    PRODUCE(1); CP_COMMIT();
    PRODUCE(2); CP_COMMIT();

    for (int c = 0; c < nch; c++) {
        asm volatile("cp.async.wait_group 2;" ::: "memory");
        __syncthreads();

        if (c + 3 < nch) PRODUCE(c + 3);
        CP_COMMIT();

        const uint32_t st = sb + (uint32_t)(c & 3) * STAGEB;
        const uint32_t brow = (uint32_t)(wn * 64) * PITCH + b_off;

        uint32_t ah[2][4], bfr[2][4];
        ldsm4(bfr[0], st + ARR_B + brow);
        #pragma unroll
        for (int mt = 0; mt < 2; mt++) {
            uint32_t ra = (uint32_t)(wm * 32 + mt * 16) * PITCH + a_off;
            ldsm4(ah[mt], st + ARR_A + ra);
        }
        #pragma unroll
        for (int nt = 0; nt < 4; nt++) {
            if (nt < 3)
                ldsm4(bfr[(nt + 1) & 1],
                      st + ARR_B + brow + (uint32_t)((nt + 1) * 16) * PITCH);
            const uint32_t* b4 = bfr[nt & 1];
            mma16816h(acc[0][2 * nt],     ah[0], b4);
            mma16816h(acc[1][2 * nt],     ah[1], b4);
            mma16816h(acc[0][2 * nt + 1], ah[0], b4 + 2);
            mma16816h(acc[1][2 * nt + 1], ah[1], b4 + 2);
        }
    }

    const int tr = lane >> 2;
    const int tc = (lane & 3) * 2;
    const int comp = col0 >> 10;
    #pragma unroll
    for (int mt = 0; mt < 2; mt++) {
        #pragma unroll
        for (int n8 = 0; n8 < 8; n8++) {
            int r  = row0 + wm * 32 + mt * 16 + tr;
            int cc = col0 + wn * 64 + n8 * 8 + tc;
            float b0 = bias[cc], b1 = bias[cc + 1];
            float v0 = acc[mt][n8][0] + b0;
            float v1 = acc[mt][n8][1] + b1;
            float v2 = acc[mt][n8][2] + b0;
            float v3 = acc[mt][n8][3] + b1;
            if (qkvmode) {
                int ccl = cc - (comp << 10);
                size_t o0 = (size_t)r * EMB + ccl;
                size_t o1 = (size_t)(r + 8) * EMB + ccl;
                if (comp == 0) {
                    *(uint32_t*)(g_qf + o0) = pack2h(v0 * QSCALE, v1 * QSCALE);
                    *(uint32_t*)(g_qf + o1) = pack2h(v2 * QSCALE, v3 * QSCALE);
                } else if (comp == 1) {
                    *(uint32_t*)(g_kf + o0) = pack2h(v0, v1);
                    *(uint32_t*)(g_kf + o1) = pack2h(v2, v3);
                } else {
                    uint32_t h, l;
                    split2h(v0, v1, h, l);
                    *(uint32_t*)(g_vh0 + o0) = h;
                    *(uint32_t*)(g_vl0 + o0) = l;
                    split2h(v2, v3, h, l);
                    *(uint32_t*)(g_vh0 + o1) = h;
                    *(uint32_t*)(g_vl0 + o1) = l;
                }
            } else {
                *(float2*)(C + (size_t)r * N + cc)       = make_float2(v0, v1);
                *(float2*)(C + (size_t)(r + 8) * N + cc) = make_float2(v2, v3);
            }
        }
    }
}

// -------------------- V transpose: g_vh0/g_vl0 -> vt[bh][d][tok] -------------
__global__ void __launch_bounds__(128) vtrans_kernel()
{
    __shared__ ushort sh[64][72];
    __shared__ ushort sl[64][72];
    const int tid = threadIdx.x;
    const int bh  = blockIdx.y;
    const int b   = bh & 1;
    const int h   = bh >> 1;
    const int tok0 = blockIdx.x * 64;

    {
        int tl = tid >> 1;
        int row = (tok0 + tl) * 2 + b;
        size_t base = (size_t)row * EMB + h * HD;
        #pragma unroll
        for (int j = 0; j < 4; j++) {
            int seg = (tid & 1) * 4 + j;
            uint4 vh = *(const uint4*)((const ushort*)g_vh0 + base + seg * 8);
            uint4 vl = *(const uint4*)((const ushort*)g_vl0 + base + seg * 8);
            *(uint4*)(&sh[tl][seg * 8]) = vh;
            *(uint4*)(&sl[tl][seg * 8]) = vl;
        }
    }
    __syncthreads();
    {
        int d = tid >> 1;
        int th = (tid & 1) * 32;
        size_t obase = ((size_t)bh * 64 + d) * NTOK + tok0 + th;
        #pragma unroll
        for (int q = 0; q < 4; q++) {
            ushort th8[8], tl8[8];
            #pragma unroll
            for (int i = 0; i < 8; i++) {
                th8[i] = sh[th + q * 8 + i][d];
                tl8[i] = sl[th + q * 8 + i][d];
            }
            *(uint4*)((ushort*)g_vthf + obase + q * 8) = *(uint4*)th8;
            *(uint4*)((ushort*)g_vtlf + obase + q * 8) = *(uint4*)tl8;
        }
    }
}

// -------------------- flash attention (fp16 mma, split V) -------------------
#define AQ    0
#define ABUF  16384
#define ASTG  24576
#define A_K   0
#define A_VH  8192
#define A_VL  16384
#define ASTAGES 3
#define ATTN_SMEM (ABUF + ASTAGES * ASTG)   // 90112 -> 2 CTAs/SM

#define ASWZ(row, seg) ((uint32_t)(row) * 128 + ((uint32_t)((seg) ^ ((row) & 7)) * 16))

__global__ void __launch_bounds__(256, 2) attn_mma_kernel()
{
    extern __shared__ char smem[];
    const uint32_t sb = s2u(smem);
    const int tid  = threadIdx.x;
    const int lane = tid & 31;
    const int warp = tid >> 5;
    const int qt = blockIdx.x;
    const int bh = blockIdx.y;
    const int b  = bh & 1;
    const int h  = bh >> 1;

    {
        int prow = tid >> 1;
        int psb  = (tid & 1) * 4;
        int qtok = qt * 128 + prow;
        size_t gq = (size_t)(qtok * 2 + b) * EMB + h * HD + psb * 8;
        #pragma unroll
        for (int j = 0; j < 4; j++)
            cp16(sb + AQ + ASWZ(prow, psb + j), g_qf + gq + j * 8);
    }

    const int prow = tid >> 2;
    const int ps2  = (tid & 3) * 2;

    #define APROD(kt)                                                         \
    do {                                                                      \
        uint32_t bufb = sb + ABUF + (uint32_t)((kt) % ASTAGES) * ASTG;        \
        int tok = (kt) * 64 + prow;                                           \
        size_t gk = (size_t)(tok * 2 + b) * EMB + h * HD;                     \
        size_t gv = ((size_t)bh * 64 + prow) * NTOK + (kt) * 64;              \
        _Pragma("unroll")                                                     \
        for (int j = 0; j < 2; j++) {                                         \
            int seg = ps2 + j;                                                \
            uint32_t o = ASWZ(prow, seg);                                     \
            cp16(bufb + A_K  + o, g_kf   + gk + seg * 8);                     \
            cp16(bufb + A_VH + o, g_vthf + gv + seg * 8);                     \
            cp16(bufb + A_VL + o, g_vtlf + gv + seg * 8);                     \
        }                                                                     \
    } while (0)

    APROD(0); CP_COMMIT();
    APROD(1); CP_COMMIT();

    float o[8][4];
    #pragma unroll
    for (int j = 0; j < 8; j++)
        #pragma unroll
        for (int v = 0; v < 4; v++) o[j][v] = 0.f;
    float m0 = -CUDART_INF_F, m1 = -CUDART_INF_F, l0 = 0.f, l1 = 0.f;
    uint32_t qf[4][4];

    const int brow_l = (lane & 7) + ((lane >> 4) & 1) * 8;
    const int bseg_l = (lane >> 3) & 1;

    const int NKT = NTOK / 64;
    for (int kt = 0; kt < NKT; kt++) {
        asm volatile("cp.async.wait_group 1;" ::: "memory");
        __syncthreads();

        if (kt + 2 < NKT) APROD(kt + 2);
        CP_COMMIT();

        const uint32_t kb = sb + ABUF + (uint32_t)(kt % ASTAGES) * ASTG;

        if (kt == 0) {
            #pragma unroll
            for (int ks = 0; ks < 4; ks++) {
                int row = warp * 16 + (lane & 15);
                int seg = ks * 2 + (lane >> 4);
                ldsm4(qf[ks], sb + AQ + ASWZ(row, seg));
            }
        }

        float s[8][4];
        #pragma unroll
        for (int j = 0; j < 8; j++)
            #pragma unroll
            for (int v = 0; v < 4; v++) s[j][v] = 0.f;

        {
            uint32_t kbf[2][4];
            ldsm4(kbf[0], kb + A_K + ASWZ(brow_l, bseg_l));
            #pragma unroll
            for (int it = 0; it < 16; it++) {
                const int ks = it >> 2, nt = it & 3;
                if (it < 15) {
                    const int ks2 = (it + 1) >> 2, nt2 = (it + 1) & 3;
                    ldsm4(kbf[(it + 1) & 1],
                          kb + A_K + ASWZ(nt2 * 16 + brow_l, ks2 * 2 + bseg_l));
                }
                const uint32_t* k4 = kbf[it & 1];
                mma16816h(s[2 * nt],     qf[ks], k4);
                mma16816h(s[2 * nt + 1], qf[ks], k4 + 2);
            }
        }

        float cm0 = -CUDART_INF_F, cm1 = -CUDART_INF_F;
        #pragma unroll
        for (int j = 0; j < 8; j++) {
            cm0 = fmaxf(cm0, fmaxf(s[j][0], s[j][1]));
            cm1 = fmaxf(cm1, fmaxf(s[j][2], s[j][3]));
        }
        cm0 = fmaxf(cm0, __shfl_xor_sync(0xffffffffu, cm0, 1));
        cm0 = fmaxf(cm0, __shfl_xor_sync(0xffffffffu, cm0, 2));
        cm1 = fmaxf(cm1, __shfl_xor_sync(0xffffffffu, cm1, 1));
        cm1 = fmaxf(cm1, __shfl_xor_sync(0xffffffffu, cm1, 2));
        float nm0 = fmaxf(m0, cm0), nm1 = fmaxf(m1, cm1);
        float al0 = ex2(m0 - nm0),  al1 = ex2(m1 - nm1);
        float rs0 = 0.f, rs1 = 0.f;
        #pragma unroll
        for (int j = 0; j < 8; j++) {
            s[j][0] = ex2(s[j][0] - nm0);
            s[j][1] = ex2(s[j][1] - nm0);
            s[j][2] = ex2(s[j][2] - nm1);
            s[j][3] = ex2(s[j][3] - nm1);
            rs0 += s[j][0] + s[j][1];
            rs1 += s[j][2] + s[j][3];
        }
        rs0 += __shfl_xor_sync(0xffffffffu, rs0, 1);
        rs0 += __shfl_xor_sync(0xffffffffu, rs0, 2);
        rs1 += __shfl_xor_sync(0xffffffffu, rs1, 1);
        rs1 += __shfl_xor_sync(0xffffffffu, rs1, 2);
        l0 = l0 * al0 + rs0; m0 = nm0;
        l1 = l1 * al1 + rs1; m1 = nm1;
        #pragma unroll
        for (int j = 0; j < 8; j++) {
            o[j][0] *= al0; o[j][1] *= al0;
            o[j][2] *= al1; o[j][3] *= al1;
        }

        uint32_t pf[4][4];
        #pragma unroll
        for (int ks = 0; ks < 4; ks++) {
            pf[ks][0] = pack2h(s[2 * ks][0],     s[2 * ks][1]);
            pf[ks][1] = pack2h(s[2 * ks][2],     s[2 * ks][3]);
            pf[ks][2] = pack2h(s[2 * ks + 1][0], s[2 * ks + 1][1]);
            pf[ks][3] = pack2h(s[2 * ks + 1][2], s[2 * ks + 1][3]);
        }

        {
            uint32_t vhb[2][4], vlb[2][4];
            ldsm4(vhb[0], kb + A_VH + ASWZ(brow_l, bseg_l));
            ldsm4(vlb[0], kb + A_VL + ASWZ(brow_l, bseg_l));
            #pragma unroll
            for (int it = 0; it < 16; it++) {
                const int ks = it >> 2, nt = it & 3;
                if (it < 15) {
                    const int ks2 = (it + 1) >> 2, nt2 = (it + 1) & 3;
                    uint32_t ad = ASWZ(nt2 * 16 + brow_l, ks2 * 2 + bseg_l);
                    ldsm4(vhb[(it + 1) & 1], kb + A_VH + ad);
                    ldsm4(vlb[(it + 1) & 1], kb + A_VL + ad);
                }
                const uint32_t* vh4 = vhb[it & 1];
                const uint32_t* vl4 = vlb[it & 1];
                mma16816h(o[2 * nt],     pf[ks], vh4);
                mma16816h(o[2 * nt + 1], pf[ks], vh4 + 2);
                mma16816h(o[2 * nt],     pf[ks], vl4);
                mma16816h(o[2 * nt + 1], pf[ks], vl4 + 2);
            }
        }
    }

    // epilogue: normalize, fp16 1-pass ctx
    float inv0 = 1.0f / l0, inv1 = 1.0f / l1;
    int r0   = warp * 16 + (lane >> 2);
    int tok0 = qt * 128 + r0;
    int colb = h * HD + (lane & 3) * 2;
    size_t row0a = (size_t)(tok0 * 2 + b) * EMB;
    size_t row1a = (size_t)((tok0 + 8) * 2 + b) * EMB;
    #pragma unroll
    for (int j = 0; j < 8; j++) {
        int col = colb + 8 * j;
        *(uint32_t*)(g_ch + row0a + col) = pack2h(o[j][0] * inv0, o[j][1] * inv0);
        *(uint32_t*)(g_ch + row1a + col) = pack2h(o[j][2] * inv1, o[j][3] * inv1);
    }
}

// ---------------------------------------------------------------------------
// Launch
// ---------------------------------------------------------------------------
extern "C" void kernel_launch(void* const* d_in, const int* in_sizes, int n_in,
                              void* d_out, int out_size)
{
    const float* seq   = (const float*)d_in[0];
    const float* w_qkv = (const float*)d_in[1];
    const float* b_qkv = (const float*)d_in[2];
    const float* w_out = (const float*)d_in[3];
    const float* b_out = (const float*)d_in[4];
    float* out = (float*)d_out;

    __half *sh, *wq, *wo, *ch;
    cudaGetSymbolAddress((void**)&sh, g_sh);
    cudaGetSymbolAddress((void**)&wq, g_wq);
    cudaGetSymbolAddress((void**)&wo, g_wo);
    cudaGetSymbolAddress((void**)&ch, g_ch);

    cudaFuncSetAttribute(gemm_mma_kernel,
                         cudaFuncAttributeMaxDynamicSharedMemorySize, GSMEM);
    cudaFuncSetAttribute(attn_mma_kernel,
                         cudaFuncAttributeMaxDynamicSharedMemorySize, ATTN_SMEM);

    // 0) converts: everything 1-pass fp16
    {
        int n4 = MROWS * EMB / 4;
        convert_h_kernel<<<(n4 + 255) / 256, 256>>>((const float4*)seq,
                                                    (uint2*)sh, n4);
        n4 = F3 * EMB / 4;
        convert_h_kernel<<<(n4 + 255) / 256, 256>>>((const float4*)w_qkv,
                                                    (uint2*)wq, n4);
        n4 = EMB * EMB / 4;
        convert_h_kernel<<<(n4 + 255) / 256, 256>>>((const float4*)w_out,
                                                    (uint2*)wo, n4);
    }

    // 1) QKV projection -> fp16 Q (scaled), fp16 K, fp16 hi/lo V
    gemm_mma_kernel<<<dim3(F3 / 128, MROWS / 128), 256, GSMEM>>>(
        sh, wq, b_qkv, nullptr, F3, EMB, 1);

    // 2) transpose V into [bh][d][tok]
    vtrans_kernel<<<dim3(NTOK / 64, BSZ * NH), 128>>>();

    // 3) fused flash attention (fp16 mma) -> fp16 ctx
    attn_mma_kernel<<<dim3(NTOK / 128, BSZ * NH), 256, ATTN_SMEM>>>();

    // 4) output projection -> fp32 out
    gemm_mma_kernel<<<dim3(EMB / 128, MROWS / 128), 256, GSMEM>>>(
        ch, wo, b_out, out, EMB, EMB, 0);
}

// round 10
// speedup vs baseline: 6.2477x; 1.1400x over previous
#include <cuda_runtime.h>
#include <cuda_bf16.h>
#include <cuda_fp16.h>
#include <math_constants.h>
#include <cstdint>

// Problem constants
#define NTOK 2048
#define BSZ  2
#define EMB  1024
#define NH   16
#define HD   64
#define MROWS (NTOK*BSZ)      // 4096
#define F3   (3*EMB)          // 3072
#define QSCALE 0.1803368801111204f   // 0.125 * log2(e)

// -------------------- device scratch (allocation-free) ----------------------
__device__ __half g_sh[(size_t)MROWS * EMB];   // seq fp16 (1-pass)
__device__ __half g_wq[(size_t)F3 * EMB];      // w_qkv fp16 (1-pass)
__device__ __half g_wo[(size_t)EMB * EMB];     // w_out fp16 (1-pass)
__device__ __half g_qf[(size_t)MROWS * EMB];   // Q fp16 (pre-scaled)
__device__ __half g_kf[(size_t)MROWS * EMB];   // K fp16
__device__ __half g_vh0[(size_t)MROWS * EMB];  // V fp16 (token-major)
__device__ __half g_vthf[(size_t)BSZ * NH * HD * NTOK]; // V^T [bh][d][tok]
__device__ __half g_ch[(size_t)MROWS * EMB];   // attn out fp16 (1-pass)

// -------------------- PTX helpers -------------------------------------------
__device__ __forceinline__ uint32_t s2u(const void* p) {
    uint32_t a;
    asm("{ .reg .u64 t; cvta.to.shared.u64 t, %1; cvt.u32.u64 %0, t; }"
        : "=r"(a) : "l"(p));
    return a;
}

__device__ __forceinline__ void cp16(uint32_t dst, const void* src) {
    asm volatile("cp.async.cg.shared.global [%0], [%1], 16;"
                 :: "r"(dst), "l"(src) : "memory");
}
#define CP_COMMIT() asm volatile("cp.async.commit_group;" ::: "memory")

__device__ __forceinline__ void ldsm4(uint32_t* r, uint32_t a) {
    asm volatile("ldmatrix.sync.aligned.m8n8.x4.shared.b16 {%0,%1,%2,%3}, [%4];"
                 : "=r"(r[0]), "=r"(r[1]), "=r"(r[2]), "=r"(r[3]) : "r"(a));
}

__device__ __forceinline__ void mma16816h(float* c, const uint32_t* a,
                                           const uint32_t* b) {
    asm volatile(
        "mma.sync.aligned.m16n8k16.row.col.f32.f16.f16.f32 "
        "{%0,%1,%2,%3}, {%4,%5,%6,%7}, {%8,%9}, {%0,%1,%2,%3};"
        : "+f"(c[0]), "+f"(c[1]), "+f"(c[2]), "+f"(c[3])
        : "r"(a[0]), "r"(a[1]), "r"(a[2]), "r"(a[3]), "r"(b[0]), "r"(b[1]));
}

__device__ __forceinline__ float ex2(float x) {
    float y;
    asm("ex2.approx.f32 %0, %1;" : "=f"(y) : "f"(x));
    return y;
}

__device__ __forceinline__ uint32_t pack2h(float a, float b) {
    __half2 t = __floats2half2_rn(a, b);
    return *reinterpret_cast<uint32_t*>(&t);
}

// -------------------- converts ----------------------------------------------
__global__ void convert_h_kernel(const float4* __restrict__ in,
                                 uint2* __restrict__ out4, int n4) {
    int i = blockIdx.x * blockDim.x + threadIdx.x;
    if (i >= n4) return;
    float4 x = in[i];
    uint2 o;
    o.x = pack2h(x.x, x.y);
    o.y = pack2h(x.z, x.w);
    out4[i] = o;
}

// -------------------- fp16 1-pass GEMM (mma.sync), 64x64 warp tiles ---------
// C = A[M][K] * B[N][K]^T + bias[N]
// CTA tile 256x128, 8 warps (wm=warp&3 -> 64 M-rows, wn=warp>>2 -> 64 N-cols).
// qkvmode=0: C fp32.  qkvmode=1: N=3072; comp0->g_qf(xQSCALE), comp1->g_kf,
// comp2->g_vh0 (fp16).
#define PITCH  48
#define ATILEB (256 * PITCH)       // 12288
#define BTILEB (128 * PITCH)       // 6144
#define STAGEB (ATILEB + BTILEB)   // 18432
#define GSTG   4
#define GSMEM  (GSTG * STAGEB)     // 73728 -> 1 CTA/SM (reg-limited)

__global__ void __launch_bounds__(256, 1) gemm_mma_kernel(
    const __half* __restrict__ A, const __half* __restrict__ B,
    const float* __restrict__ bias, float* __restrict__ C,
    int N, int K, int qkvmode)
{
    extern __shared__ char smem[];
    const uint32_t sb = s2u(smem);
    const int tid  = threadIdx.x;
    const int lane = tid & 31;
    const int warp = tid >> 5;
    const int wm   = warp & 3;     // 64-row group
    const int wn   = warp >> 2;    // 64-col group
    const int row0 = blockIdx.y * 256;
    const int col0 = blockIdx.x * 128;

    float acc[4][8][4];
    #pragma unroll
    for (int i = 0; i < 4; i++)
        #pragma unroll
        for (int j = 0; j < 8; j++)
            #pragma unroll
            for (int v = 0; v < 4; v++) acc[i][j][v] = 0.f;

    const uint32_t a_off = (uint32_t)(lane & 15) * PITCH + (lane >> 4) * 16;
    const uint32_t b_off = (uint32_t)((lane & 7) + ((lane >> 4) & 1) * 8) * PITCH
                         + ((lane >> 3) & 1) * 16;

    const int pr   = tid >> 1;     // 0..127
    const int pseg = tid & 1;      // 16B segment
    const int nch  = K / 16;

    #define PRODUCE(c)                                                        \
    do {                                                                      \
        uint32_t base = sb + (uint32_t)((c) & 3) * STAGEB;                    \
        uint32_t so = (uint32_t)pr * PITCH + pseg * 16;                       \
        size_t gA0 = (size_t)(row0 + pr) * K + (c) * 16 + pseg * 8;           \
        size_t gA1 = (size_t)(row0 + pr + 128) * K + (c) * 16 + pseg * 8;     \
        size_t gB  = (size_t)(col0 + pr) * K + (c) * 16 + pseg * 8;           \
        cp16(base + so, A + gA0);                                             \
        cp16(base + so + (uint32_t)(128 * PITCH), A + gA1);                   \
        cp16(base + ATILEB + so, B + gB);                                     \
    } while (0)

    PRODUCE(0); CP_COMMIT();
    PRODUCE(1); CP_COMMIT();
    PRODUCE(2); CP_COMMIT();

    for (int c = 0; c < nch; c++) {
        asm volatile("cp.async.wait_group 2;" ::: "memory");
        __syncthreads();

        if (c + 3 < nch) PRODUCE(c + 3);
        CP_COMMIT();

        const uint32_t st = sb + (uint32_t)(c & 3) * STAGEB;
        const uint32_t brow = ATILEB + (uint32_t)(wn * 64) * PITCH + b_off;

        uint32_t ah[4][4], bfr[2][4];
        ldsm4(bfr[0], st + brow);
        #pragma unroll
        for (int mt = 0; mt < 4; mt++) {
            uint32_t ra = (uint32_t)(wm * 64 + mt * 16) * PITCH + a_off;
            ldsm4(ah[mt], st + ra);
        }
        #pragma unroll
        for (int nt = 0; nt < 4; nt++) {
            if (nt < 3)
                ldsm4(bfr[(nt + 1) & 1],
                      st + brow + (uint32_t)((nt + 1) * 16) * PITCH);
            const uint32_t* b4 = bfr[nt & 1];
            mma16816h(acc[0][2 * nt],     ah[0], b4);
            mma16816h(acc[1][2 * nt],     ah[1], b4);
            mma16816h(acc[2][2 * nt],     ah[2], b4);
            mma16816h(acc[3][2 * nt],     ah[3], b4);
            mma16816h(acc[0][2 * nt + 1], ah[0], b4 + 2);
            mma16816h(acc[1][2 * nt + 1], ah[1], b4 + 2);
            mma16816h(acc[2][2 * nt + 1], ah[2], b4 + 2);
            mma16816h(acc[3][2 * nt + 1], ah[3], b4 + 2);
        }
    }

    const int tr = lane >> 2;
    const int tc = (lane & 3) * 2;
    const int comp = col0 >> 10;
    #pragma unroll
    for (int mt = 0; mt < 4; mt++) {
        #pragma unroll
        for (int n8 = 0; n8 < 8; n8++) {
            int r  = row0 + wm * 64 + mt * 16 + tr;
            int cc = col0 + wn * 64 + n8 * 8 + tc;
            float b0 = bias[cc], b1 = bias[cc + 1];
            float v0 = acc[mt][n8][0] + b0;
            float v1 = acc[mt][n8][1] + b1;
            float v2 = acc[mt][n8][2] + b0;
            float v3 = acc[mt][n8][3] + b1;
            if (qkvmode) {
                int ccl = cc - (comp << 10);
                size_t o0 = (size_t)r * EMB + ccl;
                size_t o1 = (size_t)(r + 8) * EMB + ccl;
                if (comp == 0) {
                    *(uint32_t*)(g_qf + o0) = pack2h(v0 * QSCALE, v1 * QSCALE);
                    *(uint32_t*)(g_qf + o1) = pack2h(v2 * QSCALE, v3 * QSCALE);
                } else if (comp == 1) {
                    *(uint32_t*)(g_kf + o0) = pack2h(v0, v1);
                    *(uint32_t*)(g_kf + o1) = pack2h(v2, v3);
                } else {
                    *(uint32_t*)(g_vh0 + o0) = pack2h(v0, v1);
                    *(uint32_t*)(g_vh0 + o1) = pack2h(v2, v3);
                }
            } else {
                *(float2*)(C + (size_t)r * N + cc)       = make_float2(v0, v1);
                *(float2*)(C + (size_t)(r + 8) * N + cc) = make_float2(v2, v3);
            }
        }
    }
}

// -------------------- V transpose: g_vh0 -> vt[bh][d][tok] -------------------
__global__ void __launch_bounds__(128) vtrans_kernel()
{
    __shared__ ushort sh[64][72];
    const int tid = threadIdx.x;
    const int bh  = blockIdx.y;
    const int b   = bh & 1;
    const int h   = bh >> 1;
    const int tok0 = blockIdx.x * 64;

    {
        int tl = tid >> 1;
        int row = (tok0 + tl) * 2 + b;
        size_t base = (size_t)row * EMB + h * HD;
        #pragma unroll
        for (int j = 0; j < 4; j++) {
            int seg = (tid & 1) * 4 + j;
            uint4 vh = *(const uint4*)((const ushort*)g_vh0 + base + seg * 8);
            *(uint4*)(&sh[tl][seg * 8]) = vh;
        }
    }
    __syncthreads();
    {
        int d = tid >> 1;
        int th = (tid & 1) * 32;
        size_t obase = ((size_t)bh * 64 + d) * NTOK + tok0 + th;
        #pragma unroll
        for (int q = 0; q < 4; q++) {
            ushort th8[8];
            #pragma unroll
            for (int i = 0; i < 8; i++)
                th8[i] = sh[th + q * 8 + i][d];
            *(uint4*)((ushort*)g_vthf + obase + q * 8) = *(uint4*)th8;
        }
    }
}

// -------------------- flash attention (fp16 mma, 1-pass V) ------------------
#define AQ    0
#define ABUF  16384
#define ASTG  16384                 // K 8KB + V 8KB
#define A_K   0
#define A_VH  8192
#define ASTAGES 3
#define ATTN_SMEM (ABUF + ASTAGES * ASTG)   // 65536 -> 2 CTAs/SM

#define ASWZ(row, seg) ((uint32_t)(row) * 128 + ((uint32_t)((seg) ^ ((row) & 7)) * 16))

__global__ void __launch_bounds__(256, 2) attn_mma_kernel()
{
    extern __shared__ char smem[];
    const uint32_t sb = s2u(smem);
    const int tid  = threadIdx.x;
    const int lane = tid & 31;
    const int warp = tid >> 5;
    const int qt = blockIdx.x;
    const int bh = blockIdx.y;
    const int b  = bh & 1;
    const int h  = bh >> 1;

    {
        int prow = tid >> 1;
        int psb  = (tid & 1) * 4;
        int qtok = qt * 128 + prow;
        size_t gq = (size_t)(qtok * 2 + b) * EMB + h * HD + psb * 8;
        #pragma unroll
        for (int j = 0; j < 4; j++)
            cp16(sb + AQ + ASWZ(prow, psb + j), g_qf + gq + j * 8);
    }

    const int prow = tid >> 2;
    const int ps2  = (tid & 3) * 2;

    #define APROD(kt)                                                         \
    do {                                                                      \
        uint32_t bufb = sb + ABUF + (uint32_t)((kt) % ASTAGES) * ASTG;        \
        int tok = (kt) * 64 + prow;                                           \
        size_t gk = (size_t)(tok * 2 + b) * EMB + h * HD;                     \
        size_t gv = ((size_t)bh * 64 + prow) * NTOK + (kt) * 64;              \
        _Pragma("unroll")                                                     \
        for (int j = 0; j < 2; j++) {                                         \
            int seg = ps2 + j;                                                \
            uint32_t o = ASWZ(prow, seg);                                     \
            cp16(bufb + A_K  + o, g_kf   + gk + seg * 8);                     \
            cp16(bufb + A_VH + o, g_vthf + gv + seg * 8);                     \
        }                                                                     \
    } while (0)

    APROD(0); CP_COMMIT();
    APROD(1); CP_COMMIT();

    float o[8][4];
    #pragma unroll
    for (int j = 0; j < 8; j++)
        #pragma unroll
        for (int v = 0; v < 4; v++) o[j][v] = 0.f;
    float m0 = -CUDART_INF_F, m1 = -CUDART_INF_F, l0 = 0.f, l1 = 0.f;
    uint32_t qf[4][4];

    const int brow_l = (lane & 7) + ((lane >> 4) & 1) * 8;
    const int bseg_l = (lane >> 3) & 1;

    const int NKT = NTOK / 64;
    for (int kt = 0; kt < NKT; kt++) {
        asm volatile("cp.async.wait_group 1;" ::: "memory");
        __syncthreads();

        if (kt + 2 < NKT) APROD(kt + 2);
        CP_COMMIT();

        const uint32_t kb = sb + ABUF + (uint32_t)(kt % ASTAGES) * ASTG;

        if (kt == 0) {
            #pragma unroll
            for (int ks = 0; ks < 4; ks++) {
                int row = warp * 16 + (lane & 15);
                int seg = ks * 2 + (lane >> 4);
                ldsm4(qf[ks], sb + AQ + ASWZ(row, seg));
            }
        }

        float s[8][4];
        #pragma unroll
        for (int j = 0; j < 8; j++)
            #pragma unroll
            for (int v = 0; v < 4; v++) s[j][v] = 0.f;

        {
            uint32_t kbf[2][4];
            ldsm4(kbf[0], kb + A_K + ASWZ(brow_l, bseg_l));
            #pragma unroll
            for (int it = 0; it < 16; it++) {
                const int ks = it >> 2, nt = it & 3;
                if (it < 15) {
                    const int ks2 = (it + 1) >> 2, nt2 = (it + 1) & 3;
                    ldsm4(kbf[(it + 1) & 1],
                          kb + A_K + ASWZ(nt2 * 16 + brow_l, ks2 * 2 + bseg_l));
                }
                const uint32_t* k4 = kbf[it & 1];
                mma16816h(s[2 * nt],     qf[ks], k4);
                mma16816h(s[2 * nt + 1], qf[ks], k4 + 2);
            }
        }

        float cm0 = -CUDART_INF_F, cm1 = -CUDART_INF_F;
        #pragma unroll
        for (int j = 0; j < 8; j++) {
            cm0 = fmaxf(cm0, fmaxf(s[j][0], s[j][1]));
            cm1 = fmaxf(cm1, fmaxf(s[j][2], s[j][3]));
        }
        cm0 = fmaxf(cm0, __shfl_xor_sync(0xffffffffu, cm0, 1));
        cm0 = fmaxf(cm0, __shfl_xor_sync(0xffffffffu, cm0, 2));
        cm1 = fmaxf(cm1, __shfl_xor_sync(0xffffffffu, cm1, 1));
        cm1 = fmaxf(cm1, __shfl_xor_sync(0xffffffffu, cm1, 2));
        float nm0 = fmaxf(m0, cm0), nm1 = fmaxf(m1, cm1);
        float al0 = ex2(m0 - nm0),  al1 = ex2(m1 - nm1);
        float rs0 = 0.f, rs1 = 0.f;
        #pragma unroll
        for (int j = 0; j < 8; j++) {
            s[j][0] = ex2(s[j][0] - nm0);
            s[j][1] = ex2(s[j][1] - nm0);
            s[j][2] = ex2(s[j][2] - nm1);
            s[j][3] = ex2(s[j][3] - nm1);
            rs0 += s[j][0] + s[j][1];
            rs1 += s[j][2] + s[j][3];
        }
        rs0 += __shfl_xor_sync(0xffffffffu, rs0, 1);
        rs0 += __shfl_xor_sync(0xffffffffu, rs0, 2);
        rs1 += __shfl_xor_sync(0xffffffffu, rs1, 1);
        rs1 += __shfl_xor_sync(0xffffffffu, rs1, 2);
        l0 = l0 * al0 + rs0; m0 = nm0;
        l1 = l1 * al1 + rs1; m1 = nm1;
        #pragma unroll
        for (int j = 0; j < 8; j++) {
            o[j][0] *= al0; o[j][1] *= al0;
            o[j][2] *= al1; o[j][3] *= al1;
        }

        uint32_t pf[4][4];
        #pragma unroll
        for (int ks = 0; ks < 4; ks++) {
            pf[ks][0] = pack2h(s[2 * ks][0],     s[2 * ks][1]);
            pf[ks][1] = pack2h(s[2 * ks][2],     s[2 * ks][3]);
            pf[ks][2] = pack2h(s[2 * ks + 1][0], s[2 * ks + 1][1]);
            pf[ks][3] = pack2h(s[2 * ks + 1][2], s[2 * ks + 1][3]);
        }

        {
            uint32_t vhb[2][4];
            ldsm4(vhb[0], kb + A_VH + ASWZ(brow_l, bseg_l));
            #pragma unroll
            for (int it = 0; it < 16; it++) {
                const int ks = it >> 2, nt = it & 3;
                if (it < 15) {
                    const int ks2 = (it + 1) >> 2, nt2 = (it + 1) & 3;
                    ldsm4(vhb[(it + 1) & 1],
                          kb + A_VH + ASWZ(nt2 * 16 + brow_l, ks2 * 2 + bseg_l));
                }
                const uint32_t* vh4 = vhb[it & 1];
                mma16816h(o[2 * nt],     pf[ks], vh4);
                mma16816h(o[2 * nt + 1], pf[ks], vh4 + 2);
            }
        }
    }

    float inv0 = 1.0f / l0, inv1 = 1.0f / l1;
    int r0   = warp * 16 + (lane >> 2);
    int tok0 = qt * 128 + r0;
    int colb = h * HD + (lane & 3) * 2;
    size_t row0a = (size_t)(tok0 * 2 + b) * EMB;
    size_t row1a = (size_t)((tok0 + 8) * 2 + b) * EMB;
    #pragma unroll
    for (int j = 0; j < 8; j++) {
        int col = colb + 8 * j;
        *(uint32_t*)(g_ch + row0a + col) = pack2h(o[j][0] * inv0, o[j][1] * inv0);
        *(uint32_t*)(g_ch + row1a + col) = pack2h(o[j][2] * inv1, o[j][3] * inv1);
    }
}

// ---------------------------------------------------------------------------
// Launch
// ---------------------------------------------------------------------------
extern "C" void kernel_launch(void* const* d_in, const int* in_sizes, int n_in,
                              void* d_out, int out_size)
{
    const float* seq   = (const float*)d_in[0];
    const float* w_qkv = (const float*)d_in[1];
    const float* b_qkv = (const float*)d_in[2];
    const float* w_out = (const float*)d_in[3];
    const float* b_out = (const float*)d_in[4];
    float* out = (float*)d_out;

    __half *sh, *wq, *wo, *ch;
    cudaGetSymbolAddress((void**)&sh, g_sh);
    cudaGetSymbolAddress((void**)&wq, g_wq);
    cudaGetSymbolAddress((void**)&wo, g_wo);
    cudaGetSymbolAddress((void**)&ch, g_ch);

    cudaFuncSetAttribute(gemm_mma_kernel,
                         cudaFuncAttributeMaxDynamicSharedMemorySize, GSMEM);
    cudaFuncSetAttribute(attn_mma_kernel,
                         cudaFuncAttributeMaxDynamicSharedMemorySize, ATTN_SMEM);

    // 0) converts: everything 1-pass fp16
    {
        int n4 = MROWS * EMB / 4;
        convert_h_kernel<<<(n4 + 255) / 256, 256>>>((const float4*)seq,
                                                    (uint2*)sh, n4);
        n4 = F3 * EMB / 4;
        convert_h_kernel<<<(n4 + 255) / 256, 256>>>((const float4*)w_qkv,
                                                    (uint2*)wq, n4);
        n4 = EMB * EMB / 4;
        convert_h_kernel<<<(n4 + 255) / 256, 256>>>((const float4*)w_out,
                                                    (uint2*)wo, n4);
    }

    // 1) QKV projection -> fp16 Q (scaled), fp16 K, fp16 V
    gemm_mma_kernel<<<dim3(F3 / 128, MROWS / 256), 256, GSMEM>>>(
        sh, wq, b_qkv, nullptr, F3, EMB, 1);

    // 2) transpose V into [bh][d][tok]
    vtrans_kernel<<<dim3(NTOK / 64, BSZ * NH), 128>>>();

    // 3) fused flash attention (fp16 mma) -> fp16 ctx
    attn_mma_kernel<<<dim3(NTOK / 128, BSZ * NH), 256, ATTN_SMEM>>>();

    // 4) output projection -> fp32 out
    gemm_mma_kernel<<<dim3(EMB / 128, MROWS / 256), 256, GSMEM>>>(
        ch, wo, b_out, out, EMB, EMB, 0);
}

// round 11
// speedup vs baseline: 6.3019x; 1.0087x over previous
#include <cuda_runtime.h>
#include <cuda_bf16.h>
#include <cuda_fp16.h>
#include <math_constants.h>
#include <cstdint>

// Problem constants
#define NTOK 2048
#define BSZ  2
#define EMB  1024
#define NH   16
#define HD   64
#define MROWS (NTOK*BSZ)      // 4096
#define F3   (3*EMB)          // 3072
#define QSCALE 0.1803368801111204f   // 0.125 * log2(e)

// -------------------- device scratch (allocation-free) ----------------------
__device__ __half g_sh[(size_t)MROWS * EMB];   // seq fp16 (1-pass)
__device__ __half g_wq[(size_t)F3 * EMB];      // w_qkv fp16 (1-pass)
__device__ __half g_wo[(size_t)EMB * EMB];     // w_out fp16 (1-pass)
__device__ __half g_qf[(size_t)MROWS * EMB];   // Q fp16 (pre-scaled)
__device__ __half g_kf[(size_t)MROWS * EMB];   // K fp16
__device__ __half g_vh0[(size_t)MROWS * EMB];  // V fp16 (token-major)
__device__ __half g_vthf[(size_t)BSZ * NH * HD * NTOK]; // V^T [bh][d][tok]
__device__ __half g_ch[(size_t)MROWS * EMB];   // attn out fp16 (1-pass)

// -------------------- PTX helpers -------------------------------------------
__device__ __forceinline__ uint32_t s2u(const void* p) {
    uint32_t a;
    asm("{ .reg .u64 t; cvta.to.shared.u64 t, %1; cvt.u32.u64 %0, t; }"
        : "=r"(a) : "l"(p));
    return a;
}

__device__ __forceinline__ void cp16(uint32_t dst, const void* src) {
    asm volatile("cp.async.cg.shared.global [%0], [%1], 16;"
                 :: "r"(dst), "l"(src) : "memory");
}
#define CP_COMMIT() asm volatile("cp.async.commit_group;" ::: "memory")

__device__ __forceinline__ void ldsm4(uint32_t* r, uint32_t a) {
    asm volatile("ldmatrix.sync.aligned.m8n8.x4.shared.b16 {%0,%1,%2,%3}, [%4];"
                 : "=r"(r[0]), "=r"(r[1]), "=r"(r[2]), "=r"(r[3]) : "r"(a));
}

// fp32-accumulate HMMA
__device__ __forceinline__ void mma16816h(float* c, const uint32_t* a,
                                           const uint32_t* b) {
    asm volatile(
        "mma.sync.aligned.m16n8k16.row.col.f32.f16.f16.f32 "
        "{%0,%1,%2,%3}, {%4,%5,%6,%7}, {%8,%9}, {%0,%1,%2,%3};"
        : "+f"(c[0]), "+f"(c[1]), "+f"(c[2]), "+f"(c[3])
        : "r"(a[0]), "r"(a[1]), "r"(a[2]), "r"(a[3]), "r"(b[0]), "r"(b[1]));
}

// fp16-accumulate HMMA (2x rate; used for QK logits only)
__device__ __forceinline__ void mma16816hh(uint32_t* c, const uint32_t* a,
                                            const uint32_t* b) {
    asm volatile(
        "mma.sync.aligned.m16n8k16.row.col.f16.f16.f16.f16 "
        "{%0,%1}, {%2,%3,%4,%5}, {%6,%7}, {%0,%1};"
        : "+r"(c[0]), "+r"(c[1])
        : "r"(a[0]), "r"(a[1]), "r"(a[2]), "r"(a[3]), "r"(b[0]), "r"(b[1]));
}

__device__ __forceinline__ float ex2(float x) {
    float y;
    asm("ex2.approx.f32 %0, %1;" : "=f"(y) : "f"(x));
    return y;
}

__device__ __forceinline__ uint32_t pack2h(float a, float b) {
    __half2 t = __floats2half2_rn(a, b);
    return *reinterpret_cast<uint32_t*>(&t);
}

__device__ __forceinline__ float2 unpack2h(uint32_t u) {
    __half2 t = *reinterpret_cast<__half2*>(&u);
    return __half22float2(t);
}

// -------------------- converts ----------------------------------------------
__global__ void convert_h_kernel(const float4* __restrict__ in,
                                 uint2* __restrict__ out4, int n4) {
    int i = blockIdx.x * blockDim.x + threadIdx.x;
    if (i >= n4) return;
    float4 x = in[i];
    uint2 o;
    o.x = pack2h(x.x, x.y);
    o.y = pack2h(x.z, x.w);
    out4[i] = o;
}

// -------------------- fp16 1-pass GEMM (mma.sync), R9 tiling -----------------
// C = A[M][K] * B[N][K]^T + bias[N]; CTA 128x128, 8 warps (32x64 warp tile).
// qkvmode=0: C fp32.  qkvmode=1: N=3072; comp0->g_qf(xQSCALE), comp1->g_kf,
// comp2->g_vh0 (fp16).
#define PITCH  48
#define TILEB  (128 * PITCH)       // 6144
#define STAGEB (2 * TILEB)         // 12288: A, B
#define GSTG   4
#define GSMEM  (GSTG * STAGEB)     // 49152 -> 2 CTAs/SM

#define ARR_A  0
#define ARR_B  TILEB

__global__ void __launch_bounds__(256, 2) gemm_mma_kernel(
    const __half* __restrict__ A, const __half* __restrict__ B,
    const float* __restrict__ bias, float* __restrict__ C,
    int N, int K, int qkvmode)
{
    extern __shared__ char smem[];
    const uint32_t sb = s2u(smem);
    const int tid  = threadIdx.x;
    const int lane = tid & 31;
    const int warp = tid >> 5;
    const int wm   = warp & 3;
    const int wn   = warp >> 2;
    const int row0 = blockIdx.y * 128;
    const int col0 = blockIdx.x * 128;

    float acc[2][8][4];
    #pragma unroll
    for (int i = 0; i < 2; i++)
        #pragma unroll
        for (int j = 0; j < 8; j++)
            #pragma unroll
            for (int v = 0; v < 4; v++) acc[i][j][v] = 0.f;

    const uint32_t a_off = (uint32_t)(lane & 15) * PITCH + (lane >> 4) * 16;
    const uint32_t b_off = (uint32_t)((lane & 7) + ((lane >> 4) & 1) * 8) * PITCH
                         + ((lane >> 3) & 1) * 16;

    const int pr   = tid >> 1;
    const int pseg = tid & 1;
    const int nch  = K / 16;

    #define PRODUCE(c)                                                        \
    do {                                                                      \
        uint32_t base = sb + (uint32_t)((c) & 3) * STAGEB;                    \
        size_t gA = (size_t)(row0 + pr) * K + (c) * 16 + pseg * 8;            \
        size_t gB = (size_t)(col0 + pr) * K + (c) * 16 + pseg * 8;            \
        uint32_t so = (uint32_t)pr * PITCH + pseg * 16;                       \
        cp16(base + ARR_A + so, A + gA);                                      \
        cp16(base + ARR_B + so, B + gB);                                      \
    } while (0)

    PRODUCE(0); CP_COMMIT();
    PRODUCE(1); CP_COMMIT();
    PRODUCE(2); CP_COMMIT();

    for (int c = 0; c < nch; c++) {
        asm volatile("cp.async.wait_group 2;" ::: "memory");
        __syncthreads();

        if (c + 3 < nch) PRODUCE(c + 3);
        CP_COMMIT();

        const uint32_t st = sb + (uint32_t)(c & 3) * STAGEB;
        const uint32_t brow = (uint32_t)(wn * 64) * PITCH + b_off;

        uint32_t ah[2][4], bfr[2][4];
        ldsm4(bfr[0], st + ARR_B + brow);
        #pragma unroll
        for (int mt = 0; mt < 2; mt++) {
            uint32_t ra = (uint32_t)(wm * 32 + mt * 16) * PITCH + a_off;
            ldsm4(ah[mt], st + ARR_A + ra);
        }
        #pragma unroll
        for (int nt = 0; nt < 4; nt++) {
            if (nt < 3)
                ldsm4(bfr[(nt + 1) & 1],
                      st + ARR_B + brow + (uint32_t)((nt + 1) * 16) * PITCH);
            const uint32_t* b4 = bfr[nt & 1];
            mma16816h(acc[0][2 * nt],     ah[0], b4);
            mma16816h(acc[1][2 * nt],     ah[1], b4);
            mma16816h(acc[0][2 * nt + 1], ah[0], b4 + 2);
            mma16816h(acc[1][2 * nt + 1], ah[1], b4 + 2);
        }
    }

    const int tr = lane >> 2;
    const int tc = (lane & 3) * 2;
    const int comp = col0 >> 10;
    #pragma unroll
    for (int mt = 0; mt < 2; mt++) {
        #pragma unroll
        for (int n8 = 0; n8 < 8; n8++) {
            int r  = row0 + wm * 32 + mt * 16 + tr;
            int cc = col0 + wn * 64 + n8 * 8 + tc;
            float b0 = bias[cc], b1 = bias[cc + 1];
            float v0 = acc[mt][n8][0] + b0;
            float v1 = acc[mt][n8][1] + b1;
            float v2 = acc[mt][n8][2] + b0;
            float v3 = acc[mt][n8][3] + b1;
            if (qkvmode) {
                int ccl = cc - (comp << 10);
                size_t o0 = (size_t)r * EMB + ccl;
                size_t o1 = (size_t)(r + 8) * EMB + ccl;
                if (comp == 0) {
                    *(uint32_t*)(g_qf + o0) = pack2h(v0 * QSCALE, v1 * QSCALE);
                    *(uint32_t*)(g_qf + o1) = pack2h(v2 * QSCALE, v3 * QSCALE);
                } else if (comp == 1) {
                    *(uint32_t*)(g_kf + o0) = pack2h(v0, v1);
                    *(uint32_t*)(g_kf + o1) = pack2h(v2, v3);
                } else {
                    *(uint32_t*)(g_vh0 + o0) = pack2h(v0, v1);
                    *(uint32_t*)(g_vh0 + o1) = pack2h(v2, v3);
                }
            } else {
                *(float2*)(C + (size_t)r * N + cc)       = make_float2(v0, v1);
                *(float2*)(C + (size_t)(r + 8) * N + cc) = make_float2(v2, v3);
            }
        }
    }
}

// -------------------- V transpose: g_vh0 -> vt[bh][d][tok] -------------------
__global__ void __launch_bounds__(128) vtrans_kernel()
{
    __shared__ ushort sh[64][72];
    const int tid = threadIdx.x;
    const int bh  = blockIdx.y;
    const int b   = bh & 1;
    const int h   = bh >> 1;
    const int tok0 = blockIdx.x * 64;

    {
        int tl = tid >> 1;
        int row = (tok0 + tl) * 2 + b;
        size_t base = (size_t)row * EMB + h * HD;
        #pragma unroll
        for (int j = 0; j < 4; j++) {
            int seg = (tid & 1) * 4 + j;
            uint4 vh = *(const uint4*)((const ushort*)g_vh0 + base + seg * 8);
            *(uint4*)(&sh[tl][seg * 8]) = vh;
        }
    }
    __syncthreads();
    {
        int d = tid >> 1;
        int th = (tid & 1) * 32;
        size_t obase = ((size_t)bh * 64 + d) * NTOK + tok0 + th;
        #pragma unroll
        for (int q = 0; q < 4; q++) {
            ushort th8[8];
            #pragma unroll
            for (int i = 0; i < 8; i++)
                th8[i] = sh[th + q * 8 + i][d];
            *(uint4*)((ushort*)g_vthf + obase + q * 8) = *(uint4*)th8;
        }
    }
}

// -------------------- flash attention (QK fp16-acc, PV fp32-acc) ------------
#define AQ    0
#define ABUF  16384
#define ASTG  16384                 // K 8KB + V 8KB
#define A_K   0
#define A_VH  8192
#define ASTAGES 3
#define ATTN_SMEM (ABUF + ASTAGES * ASTG)   // 65536 -> 2 CTAs/SM

#define ASWZ(row, seg) ((uint32_t)(row) * 128 + ((uint32_t)((seg) ^ ((row) & 7)) * 16))

__global__ void __launch_bounds__(256, 2) attn_mma_kernel()
{
    extern __shared__ char smem[];
    const uint32_t sb = s2u(smem);
    const int tid  = threadIdx.x;
    const int lane = tid & 31;
    const int warp = tid >> 5;
    const int qt = blockIdx.x;
    const int bh = blockIdx.y;
    const int b  = bh & 1;
    const int h  = bh >> 1;

    {
        int prow = tid >> 1;
        int psb  = (tid & 1) * 4;
        int qtok = qt * 128 + prow;
        size_t gq = (size_t)(qtok * 2 + b) * EMB + h * HD + psb * 8;
        #pragma unroll
        for (int j = 0; j < 4; j++)
            cp16(sb + AQ + ASWZ(prow, psb + j), g_qf + gq + j * 8);
    }

    const int prow = tid >> 2;
    const int ps2  = (tid & 3) * 2;

    #define APROD(kt)                                                         \
    do {                                                                      \
        uint32_t bufb = sb + ABUF + (uint32_t)((kt) % ASTAGES) * ASTG;        \
        int tok = (kt) * 64 + prow;                                           \
        size_t gk = (size_t)(tok * 2 + b) * EMB + h * HD;                     \
        size_t gv = ((size_t)bh * 64 + prow) * NTOK + (kt) * 64;              \
        _Pragma("unroll")                                                     \
        for (int j = 0; j < 2; j++) {                                         \
            int seg = ps2 + j;                                                \
            uint32_t o = ASWZ(prow, seg);                                     \
            cp16(bufb + A_K  + o, g_kf   + gk + seg * 8);                     \
            cp16(bufb + A_VH + o, g_vthf + gv + seg * 8);                     \
        }                                                                     \
    } while (0)

    APROD(0); CP_COMMIT();
    APROD(1); CP_COMMIT();

    float o[8][4];
    #pragma unroll
    for (int j = 0; j < 8; j++)
        #pragma unroll
        for (int v = 0; v < 4; v++) o[j][v] = 0.f;
    float m0 = -CUDART_INF_F, m1 = -CUDART_INF_F, l0 = 0.f, l1 = 0.f;
    uint32_t qf[4][4];

    const int brow_l = (lane & 7) + ((lane >> 4) & 1) * 8;
    const int bseg_l = (lane >> 3) & 1;

    const int NKT = NTOK / 64;
    for (int kt = 0; kt < NKT; kt++) {
        asm volatile("cp.async.wait_group 1;" ::: "memory");
        __syncthreads();

        if (kt + 2 < NKT) APROD(kt + 2);
        CP_COMMIT();

        const uint32_t kb = sb + ABUF + (uint32_t)(kt % ASTAGES) * ASTG;

        if (kt == 0) {
            #pragma unroll
            for (int ks = 0; ks < 4; ks++) {
                int row = warp * 16 + (lane & 15);
                int seg = ks * 2 + (lane >> 4);
                ldsm4(qf[ks], sb + AQ + ASWZ(row, seg));
            }
        }

        // S = Q K^T with fp16 accumulators (2x HMMA rate)
        uint32_t sh2[8][2];
        #pragma unroll
        for (int j = 0; j < 8; j++) { sh2[j][0] = 0u; sh2[j][1] = 0u; }

        {
            uint32_t kbf[2][4];
            ldsm4(kbf[0], kb + A_K + ASWZ(brow_l, bseg_l));
            #pragma unroll
            for (int it = 0; it < 16; it++) {
                const int ks = it >> 2, nt = it & 3;
                if (it < 15) {
                    const int ks2 = (it + 1) >> 2, nt2 = (it + 1) & 3;
                    ldsm4(kbf[(it + 1) & 1],
                          kb + A_K + ASWZ(nt2 * 16 + brow_l, ks2 * 2 + bseg_l));
                }
                const uint32_t* k4 = kbf[it & 1];
                mma16816hh(sh2[2 * nt],     qf[ks], k4);
                mma16816hh(sh2[2 * nt + 1], qf[ks], k4 + 2);
            }
        }

        // unpack logits to fp32
        float s[8][4];
        #pragma unroll
        for (int j = 0; j < 8; j++) {
            float2 f01 = unpack2h(sh2[j][0]);
            float2 f23 = unpack2h(sh2[j][1]);
            s[j][0] = f01.x; s[j][1] = f01.y;
            s[j][2] = f23.x; s[j][3] = f23.y;
        }

        float cm0 = -CUDART_INF_F, cm1 = -CUDART_INF_F;
        #pragma unroll
        for (int j = 0; j < 8; j++) {
            cm0 = fmaxf(cm0, fmaxf(s[j][0], s[j][1]));
            cm1 = fmaxf(cm1, fmaxf(s[j][2], s[j][3]));
        }
        cm0 = fmaxf(cm0, __shfl_xor_sync(0xffffffffu, cm0, 1));
        cm0 = fmaxf(cm0, __shfl_xor_sync(0xffffffffu, cm0, 2));
        cm1 = fmaxf(cm1, __shfl_xor_sync(0xffffffffu, cm1, 1));
        cm1 = fmaxf(cm1, __shfl_xor_sync(0xffffffffu, cm1, 2));
        float nm0 = fmaxf(m0, cm0), nm1 = fmaxf(m1, cm1);
        float al0 = ex2(m0 - nm0),  al1 = ex2(m1 - nm1);
        float rs0 = 0.f, rs1 = 0.f;
        #pragma unroll
        for (int j = 0; j < 8; j++) {
            s[j][0] = ex2(s[j][0] - nm0);
            s[j][1] = ex2(s[j][1] - nm0);
            s[j][2] = ex2(s[j][2] - nm1);
            s[j][3] = ex2(s[j][3] - nm1);
            rs0 += s[j][0] + s[j][1];
            rs1 += s[j][2] + s[j][3];
        }
        rs0 += __shfl_xor_sync(0xffffffffu, rs0, 1);
        rs0 += __shfl_xor_sync(0xffffffffu, rs0, 2);
        rs1 += __shfl_xor_sync(0xffffffffu, rs1, 1);
        rs1 += __shfl_xor_sync(0xffffffffu, rs1, 2);
        l0 = l0 * al0 + rs0; m0 = nm0;
        l1 = l1 * al1 + rs1; m1 = nm1;
        #pragma unroll
        for (int j = 0; j < 8; j++) {
            o[j][0] *= al0; o[j][1] *= al0;
            o[j][2] *= al1; o[j][3] *= al1;
        }

        uint32_t pf[4][4];
        #pragma unroll
        for (int ks = 0; ks < 4; ks++) {
            pf[ks][0] = pack2h(s[2 * ks][0],     s[2 * ks][1]);
            pf[ks][1] = pack2h(s[2 * ks][2],     s[2 * ks][3]);
            pf[ks][2] = pack2h(s[2 * ks + 1][0], s[2 * ks + 1][1]);
            pf[ks][3] = pack2h(s[2 * ks + 1][2], s[2 * ks + 1][3]);
        }

        {
            uint32_t vhb[2][4];
            ldsm4(vhb[0], kb + A_VH + ASWZ(brow_l, bseg_l));
            #pragma unroll
            for (int it = 0; it < 16; it++) {
                const int ks = it >> 2, nt = it & 3;
                if (it < 15) {
                    const int ks2 = (it + 1) >> 2, nt2 = (it + 1) & 3;
                    ldsm4(vhb[(it + 1) & 1],
                          kb + A_VH + ASWZ(nt2 * 16 + brow_l, ks2 * 2 + bseg_l));
                }
                const uint32_t* vh4 = vhb[it & 1];
                mma16816h(o[2 * nt],     pf[ks], vh4);
                mma16816h(o[2 * nt + 1], pf[ks], vh4 + 2);
            }
        }
    }

    float inv0 = 1.0f / l0, inv1 = 1.0f / l1;
    int r0   = warp * 16 + (lane >> 2);
    int tok0 = qt * 128 + r0;
    int colb = h * HD + (lane & 3) * 2;
    size_t row0a = (size_t)(tok0 * 2 + b) * EMB;
    size_t row1a = (size_t)((tok0 + 8) * 2 + b) * EMB;
    #pragma unroll
    for (int j = 0; j < 8; j++) {
        int col = colb + 8 * j;
        *(uint32_t*)(g_ch + row0a + col) = pack2h(o[j][0] * inv0, o[j][1] * inv0);
        *(uint32_t*)(g_ch + row1a + col) = pack2h(o[j][2] * inv1, o[j][3] * inv1);
    }
}

// ---------------------------------------------------------------------------
// Launch
// ---------------------------------------------------------------------------
extern "C" void kernel_launch(void* const* d_in, const int* in_sizes, int n_in,
                              void* d_out, int out_size)
{
    const float* seq   = (const float*)d_in[0];
    const float* w_qkv = (const float*)d_in[1];
    const float* b_qkv = (const float*)d_in[2];
    const float* w_out = (const float*)d_in[3];
    const float* b_out = (const float*)d_in[4];
    float* out = (float*)d_out;

    __half *sh, *wq, *wo, *ch;
    cudaGetSymbolAddress((void**)&sh, g_sh);
    cudaGetSymbolAddress((void**)&wq, g_wq);
    cudaGetSymbolAddress((void**)&wo, g_wo);
    cudaGetSymbolAddress((void**)&ch, g_ch);

    cudaFuncSetAttribute(gemm_mma_kernel,
                         cudaFuncAttributeMaxDynamicSharedMemorySize, GSMEM);
    cudaFuncSetAttribute(attn_mma_kernel,
                         cudaFuncAttributeMaxDynamicSharedMemorySize, ATTN_SMEM);

    // 0) converts: everything 1-pass fp16
    {
        int n4 = MROWS * EMB / 4;
        convert_h_kernel<<<(n4 + 255) / 256, 256>>>((const float4*)seq,
                                                    (uint2*)sh, n4);
        n4 = F3 * EMB / 4;
        convert_h_kernel<<<(n4 + 255) / 256, 256>>>((const float4*)w_qkv,
                                                    (uint2*)wq, n4);
        n4 = EMB * EMB / 4;
        convert_h_kernel<<<(n4 + 255) / 256, 256>>>((const float4*)w_out,
                                                    (uint2*)wo, n4);
    }

    // 1) QKV projection -> fp16 Q (scaled), fp16 K, fp16 V
    gemm_mma_kernel<<<dim3(F3 / 128, MROWS / 128), 256, GSMEM>>>(
        sh, wq, b_qkv, nullptr, F3, EMB, 1);

    // 2) transpose V into [bh][d][tok]
    vtrans_kernel<<<dim3(NTOK / 64, BSZ * NH), 128>>>();

    // 3) fused flash attention -> fp16 ctx
    attn_mma_kernel<<<dim3(NTOK / 128, BSZ * NH), 256, ATTN_SMEM>>>();

    // 4) output projection -> fp32 out
    gemm_mma_kernel<<<dim3(EMB / 128, MROWS / 128), 256, GSMEM>>>(
        ch, wo, b_out, out, EMB, EMB, 0);
}

// round 12
// speedup vs baseline: 6.6330x; 1.0525x over previous
#include <cuda_runtime.h>
#include <cuda_bf16.h>
#include <cuda_fp16.h>
#include <math_constants.h>
#include <cstdint>

// Problem constants
#define NTOK 2048
#define BSZ  2
#define EMB  1024
#define NH   16
#define HD   64
#define MROWS (NTOK*BSZ)      // 4096
#define F3   (3*EMB)          // 3072
#define QSCALE 0.1803368801111204f   // 0.125 * log2(e)

// -------------------- device scratch (allocation-free) ----------------------
__device__ __half g_sh[(size_t)MROWS * EMB];   // seq fp16 (1-pass)
__device__ __half g_wq[(size_t)F3 * EMB];      // w_qkv fp16 (1-pass)
__device__ __half g_wo[(size_t)EMB * EMB];     // w_out fp16 (1-pass)
__device__ __half g_qf[(size_t)MROWS * EMB];   // Q fp16 (pre-scaled)
__device__ __half g_kf[(size_t)MROWS * EMB];   // K fp16
__device__ __half g_vh0[(size_t)MROWS * EMB];  // V fp16 (token-major)
__device__ __half g_vthf[(size_t)BSZ * NH * HD * NTOK]; // V^T [bh][d][tok]
__device__ __half g_ch[(size_t)MROWS * EMB];   // attn out fp16 (1-pass)

// -------------------- PTX helpers -------------------------------------------
__device__ __forceinline__ uint32_t s2u(const void* p) {
    uint32_t a;
    asm("{ .reg .u64 t; cvta.to.shared.u64 t, %1; cvt.u32.u64 %0, t; }"
        : "=r"(a) : "l"(p));
    return a;
}

__device__ __forceinline__ void cp16(uint32_t dst, const void* src) {
    asm volatile("cp.async.cg.shared.global [%0], [%1], 16;"
                 :: "r"(dst), "l"(src) : "memory");
}
#define CP_COMMIT() asm volatile("cp.async.commit_group;" ::: "memory")

__device__ __forceinline__ void ldsm4(uint32_t* r, uint32_t a) {
    asm volatile("ldmatrix.sync.aligned.m8n8.x4.shared.b16 {%0,%1,%2,%3}, [%4];"
                 : "=r"(r[0]), "=r"(r[1]), "=r"(r[2]), "=r"(r[3]) : "r"(a));
}

// fp32-accumulate HMMA
__device__ __forceinline__ void mma16816h(float* c, const uint32_t* a,
                                           const uint32_t* b) {
    asm volatile(
        "mma.sync.aligned.m16n8k16.row.col.f32.f16.f16.f32 "
        "{%0,%1,%2,%3}, {%4,%5,%6,%7}, {%8,%9}, {%0,%1,%2,%3};"
        : "+f"(c[0]), "+f"(c[1]), "+f"(c[2]), "+f"(c[3])
        : "r"(a[0]), "r"(a[1]), "r"(a[2]), "r"(a[3]), "r"(b[0]), "r"(b[1]));
}

// fp16-accumulate HMMA (QK logits)
__device__ __forceinline__ void mma16816hh(uint32_t* c, const uint32_t* a,
                                            const uint32_t* b) {
    asm volatile(
        "mma.sync.aligned.m16n8k16.row.col.f16.f16.f16.f16 "
        "{%0,%1}, {%2,%3,%4,%5}, {%6,%7}, {%0,%1};"
        : "+r"(c[0]), "+r"(c[1])
        : "r"(a[0]), "r"(a[1]), "r"(a[2]), "r"(a[3]), "r"(b[0]), "r"(b[1]));
}

__device__ __forceinline__ float ex2(float x) {
    float y;
    asm("ex2.approx.f32 %0, %1;" : "=f"(y) : "f"(x));
    return y;
}

__device__ __forceinline__ uint32_t hmax2u(uint32_t a, uint32_t b) {
    uint32_t d;
    asm("max.f16x2 %0, %1, %2;" : "=r"(d) : "r"(a), "r"(b));
    return d;
}

__device__ __forceinline__ uint32_t hsub2u(uint32_t a, uint32_t b) {
    uint32_t d;
    asm("sub.f16x2 %0, %1, %2;" : "=r"(d) : "r"(a), "r"(b));
    return d;
}

__device__ __forceinline__ uint32_t ex2h2(uint32_t a) {
    uint32_t d;
    asm("ex2.approx.f16x2 %0, %1;" : "=r"(d) : "r"(a));
    return d;
}

__device__ __forceinline__ uint32_t pack2h(float a, float b) {
    __half2 t = __floats2half2_rn(a, b);
    return *reinterpret_cast<uint32_t*>(&t);
}

__device__ __forceinline__ float2 unpack2h(uint32_t u) {
    __half2 t = *reinterpret_cast<__half2*>(&u);
    return __half22float2(t);
}

// -------------------- fused convert: 3 arrays fp32 -> fp16 ------------------
#define N4_SEQ (MROWS * EMB / 4)
#define N4_WQ  (F3 * EMB / 4)
#define N4_WO  (EMB * EMB / 4)

__global__ void convert_all_kernel(const float4* __restrict__ seq,
                                   const float4* __restrict__ wq,
                                   const float4* __restrict__ wo) {
    int i = blockIdx.x * blockDim.x + threadIdx.x;
    const float4* src;
    uint2* dst;
    int k;
    if (i < N4_SEQ) {
        src = seq; dst = (uint2*)g_sh; k = i;
    } else if (i < N4_SEQ + N4_WQ) {
        src = wq; dst = (uint2*)g_wq; k = i - N4_SEQ;
    } else if (i < N4_SEQ + N4_WQ + N4_WO) {
        src = wo; dst = (uint2*)g_wo; k = i - N4_SEQ - N4_WQ;
    } else return;
    float4 x = src[k];
    uint2 o;
    o.x = pack2h(x.x, x.y);
    o.y = pack2h(x.z, x.w);
    dst[k] = o;
}

// -------------------- fp16 1-pass GEMM, K-chunk 32 ---------------------------
// C = A[M][K] * B[N][K]^T + bias[N]; CTA 128x128, 8 warps (32x64 warp tile).
// qkvmode=0: C fp32.  qkvmode=1: N=3072; comp0->g_qf(xQSCALE), comp1->g_kf,
// comp2->g_vh0 (fp16).
#define PITCH  80                  // 64B data + 16B pad per 32-fp16 row
#define TILEB  (128 * PITCH)       // 10240
#define STAGEB (2 * TILEB)         // 20480: A, B
#define GSTG   4
#define GSMEM  (GSTG * STAGEB)     // 81920 -> 2 CTAs/SM

#define ARR_A  0
#define ARR_B  TILEB

__global__ void __launch_bounds__(256, 2) gemm_mma_kernel(
    const __half* __restrict__ A, const __half* __restrict__ B,
    const float* __restrict__ bias, float* __restrict__ C,
    int N, int K, int qkvmode)
{
    extern __shared__ char smem[];
    const uint32_t sb = s2u(smem);
    const int tid  = threadIdx.x;
    const int lane = tid & 31;
    const int warp = tid >> 5;
    const int wm   = warp & 3;
    const int wn   = warp >> 2;
    const int row0 = blockIdx.y * 128;
    const int col0 = blockIdx.x * 128;

    float acc[2][8][4];
    #pragma unroll
    for (int i = 0; i < 2; i++)
        #pragma unroll
        for (int j = 0; j < 8; j++)
            #pragma unroll
            for (int v = 0; v < 4; v++) acc[i][j][v] = 0.f;

    const uint32_t a_off = (uint32_t)(lane & 15) * PITCH + (lane >> 4) * 16;
    const uint32_t b_off = (uint32_t)((lane & 7) + ((lane >> 4) & 1) * 8) * PITCH
                         + ((lane >> 3) & 1) * 16;

    const int pr   = tid >> 1;          // row 0..127
    const int pseg = (tid & 1) * 2;     // segments {0,1} or {2,3}
    const int nch  = K / 32;

    #define PRODUCE(c)                                                        \
    do {                                                                      \
        uint32_t base = sb + (uint32_t)((c) & 3) * STAGEB;                    \
        size_t gA = (size_t)(row0 + pr) * K + (c) * 32 + pseg * 8;            \
        size_t gB = (size_t)(col0 + pr) * K + (c) * 32 + pseg * 8;            \
        uint32_t so = (uint32_t)pr * PITCH + pseg * 16;                       \
        cp16(base + ARR_A + so,      A + gA);                                 \
        cp16(base + ARR_A + so + 16, A + gA + 8);                             \
        cp16(base + ARR_B + so,      B + gB);                                 \
        cp16(base + ARR_B + so + 16, B + gB + 8);                             \
    } while (0)

    PRODUCE(0); CP_COMMIT();
    PRODUCE(1); CP_COMMIT();
    PRODUCE(2); CP_COMMIT();

    for (int c = 0; c < nch; c++) {
        asm volatile("cp.async.wait_group 2;" ::: "memory");
        __syncthreads();

        if (c + 3 < nch) PRODUCE(c + 3);
        CP_COMMIT();

        const uint32_t st = sb + (uint32_t)(c & 3) * STAGEB;

        #pragma unroll
        for (int ks = 0; ks < 2; ks++) {
            const uint32_t brow = ARR_B + (uint32_t)(wn * 64) * PITCH
                                + ks * 32 + b_off;
            uint32_t ah[2][4], bfr[2][4];
            ldsm4(bfr[0], st + brow);
            #pragma unroll
            for (int mt = 0; mt < 2; mt++) {
                uint32_t ra = (uint32_t)(wm * 32 + mt * 16) * PITCH
                            + ks * 32 + a_off;
                ldsm4(ah[mt], st + ARR_A + ra);
            }
            #pragma unroll
            for (int nt = 0; nt < 4; nt++) {
                if (nt < 3)
                    ldsm4(bfr[(nt + 1) & 1],
                          st + brow + (uint32_t)((nt + 1) * 16) * PITCH);
                const uint32_t* b4 = bfr[nt & 1];
                mma16816h(acc[0][2 * nt],     ah[0], b4);
                mma16816h(acc[1][2 * nt],     ah[1], b4);
                mma16816h(acc[0][2 * nt + 1], ah[0], b4 + 2);
                mma16816h(acc[1][2 * nt + 1], ah[1], b4 + 2);
            }
        }
    }

    const int tr = lane >> 2;
    const int tc = (lane & 3) * 2;
    const int comp = col0 >> 10;
    #pragma unroll
    for (int mt = 0; mt < 2; mt++) {
        #pragma unroll
        for (int n8 = 0; n8 < 8; n8++) {
            int r  = row0 + wm * 32 + mt * 16 + tr;
            int cc = col0 + wn * 64 + n8 * 8 + tc;
            float b0 = bias[cc], b1 = bias[cc + 1];
            float v0 = acc[mt][n8][0] + b0;
            float v1 = acc[mt][n8][1] + b1;
            float v2 = acc[mt][n8][2] + b0;
            float v3 = acc[mt][n8][3] + b1;
            if (qkvmode) {
                int ccl = cc - (comp << 10);
                size_t o0 = (size_t)r * EMB + ccl;
                size_t o1 = (size_t)(r + 8) * EMB + ccl;
                if (comp == 0) {
                    *(uint32_t*)(g_qf + o0) = pack2h(v0 * QSCALE, v1 * QSCALE);
                    *(uint32_t*)(g_qf + o1) = pack2h(v2 * QSCALE, v3 * QSCALE);
                } else if (comp == 1) {
                    *(uint32_t*)(g_kf + o0) = pack2h(v0, v1);
                    *(uint32_t*)(g_kf + o1) = pack2h(v2, v3);
                } else {
                    *(uint32_t*)(g_vh0 + o0) = pack2h(v0, v1);
                    *(uint32_t*)(g_vh0 + o1) = pack2h(v2, v3);
                }
            } else {
                *(float2*)(C + (size_t)r * N + cc)       = make_float2(v0, v1);
                *(float2*)(C + (size_t)(r + 8) * N + cc) = make_float2(v2, v3);
            }
        }
    }
}

// -------------------- V transpose: g_vh0 -> vt[bh][d][tok] -------------------
__global__ void __launch_bounds__(128) vtrans_kernel()
{
    __shared__ ushort sh[64][72];
    const int tid = threadIdx.x;
    const int bh  = blockIdx.y;
    const int b   = bh & 1;
    const int h   = bh >> 1;
    const int tok0 = blockIdx.x * 64;

    {
        int tl = tid >> 1;
        int row = (tok0 + tl) * 2 + b;
        size_t base = (size_t)row * EMB + h * HD;
        #pragma unroll
        for (int j = 0; j < 4; j++) {
            int seg = (tid & 1) * 4 + j;
            uint4 vh = *(const uint4*)((const ushort*)g_vh0 + base + seg * 8);
            *(uint4*)(&sh[tl][seg * 8]) = vh;
        }
    }
    __syncthreads();
    {
        int d = tid >> 1;
        int th = (tid & 1) * 32;
        size_t obase = ((size_t)bh * 64 + d) * NTOK + tok0 + th;
        #pragma unroll
        for (int q = 0; q < 4; q++) {
            ushort th8[8];
            #pragma unroll
            for (int i = 0; i < 8; i++)
                th8[i] = sh[th + q * 8 + i][d];
            *(uint4*)((ushort*)g_vthf + obase + q * 8) = *(uint4*)th8;
        }
    }
}

// -------------------- flash attention (f16x2 softmax, ones-MMA sums) --------
#define AQ    0
#define ABUF  16384
#define ASTG  16384                 // K 8KB + V 8KB
#define A_K   0
#define A_VH  8192
#define ASTAGES 3
#define ATTN_SMEM (ABUF + ASTAGES * ASTG)   // 65536 -> 2 CTAs/SM

#define ASWZ(row, seg) ((uint32_t)(row) * 128 + ((uint32_t)((seg) ^ ((row) & 7)) * 16))

__global__ void __launch_bounds__(256, 2) attn_mma_kernel()
{
    extern __shared__ char smem[];
    const uint32_t sb = s2u(smem);
    const int tid  = threadIdx.x;
    const int lane = tid & 31;
    const int warp = tid >> 5;
    const int qt = blockIdx.x;
    const int bh = blockIdx.y;
    const int b  = bh & 1;
    const int h  = bh >> 1;

    {
        int prow = tid >> 1;
        int psb  = (tid & 1) * 4;
        int qtok = qt * 128 + prow;
        size_t gq = (size_t)(qtok * 2 + b) * EMB + h * HD + psb * 8;
        #pragma unroll
        for (int j = 0; j < 4; j++)
            cp16(sb + AQ + ASWZ(prow, psb + j), g_qf + gq + j * 8);
    }

    const int prow = tid >> 2;
    const int ps2  = (tid & 3) * 2;

    #define APROD(kt)                                                         \
    do {                                                                      \
        uint32_t bufb = sb + ABUF + (uint32_t)((kt) % ASTAGES) * ASTG;        \
        int tok = (kt) * 64 + prow;                                           \
        size_t gk = (size_t)(tok * 2 + b) * EMB + h * HD;                     \
        size_t gv = ((size_t)bh * 64 + prow) * NTOK + (kt) * 64;              \
        _Pragma("unroll")                                                     \
        for (int j = 0; j < 2; j++) {                                         \
            int seg = ps2 + j;                                                \
            uint32_t o = ASWZ(prow, seg);                                     \
            cp16(bufb + A_K  + o, g_kf   + gk + seg * 8);                     \
            cp16(bufb + A_VH + o, g_vthf + gv + seg * 8);                     \
        }                                                                     \
    } while (0)

    APROD(0); CP_COMMIT();
    APROD(1); CP_COMMIT();

    float o[8][4];
    #pragma unroll
    for (int j = 0; j < 8; j++)
        #pragma unroll
        for (int v = 0; v < 4; v++) o[j][v] = 0.f;
    float m0 = -CUDART_INF_F, m1 = -CUDART_INF_F, l0 = 0.f, l1 = 0.f;
    uint32_t qf[4][4];

    const int brow_l = (lane & 7) + ((lane >> 4) & 1) * 8;
    const int bseg_l = (lane >> 3) & 1;
    const uint32_t ones_b[2] = {0x3C003C00u, 0x3C003C00u};

    const int NKT = NTOK / 64;
    for (int kt = 0; kt < NKT; kt++) {
        asm volatile("cp.async.wait_group 1;" ::: "memory");
        __syncthreads();

        if (kt + 2 < NKT) APROD(kt + 2);
        CP_COMMIT();

        const uint32_t kb = sb + ABUF + (uint32_t)(kt % ASTAGES) * ASTG;

        if (kt == 0) {
            #pragma unroll
            for (int ks = 0; ks < 4; ks++) {
                int row = warp * 16 + (lane & 15);
                int seg = ks * 2 + (lane >> 4);
                ldsm4(qf[ks], sb + AQ + ASWZ(row, seg));
            }
        }

        // S = Q K^T with fp16 accumulators; sh2[j][0]=row0 pair, [1]=row1 pair
        uint32_t sh2[8][2];
        #pragma unroll
        for (int j = 0; j < 8; j++) { sh2[j][0] = 0u; sh2[j][1] = 0u; }

        {
            uint32_t kbf[2][4];
            ldsm4(kbf[0], kb + A_K + ASWZ(brow_l, bseg_l));
            #pragma unroll
            for (int it = 0; it < 16; it++) {
                const int ks = it >> 2, nt = it & 3;
                if (it < 15) {
                    const int ks2 = (it + 1) >> 2, nt2 = (it + 1) & 3;
                    ldsm4(kbf[(it + 1) & 1],
                          kb + A_K + ASWZ(nt2 * 16 + brow_l, ks2 * 2 + bseg_l));
                }
                const uint32_t* k4 = kbf[it & 1];
                mma16816hh(sh2[2 * nt],     qf[ks], k4);
                mma16816hh(sh2[2 * nt + 1], qf[ks], k4 + 2);
            }
        }

        // row maxes (packed f16x2 tree + cross-lane)
        uint32_t mx0 = sh2[0][0], mx1 = sh2[0][1];
        #pragma unroll
        for (int j = 1; j < 8; j++) {
            mx0 = hmax2u(mx0, sh2[j][0]);
            mx1 = hmax2u(mx1, sh2[j][1]);
        }
        mx0 = hmax2u(mx0, __shfl_xor_sync(0xffffffffu, mx0, 1));
        mx0 = hmax2u(mx0, __shfl_xor_sync(0xffffffffu, mx0, 2));
        mx1 = hmax2u(mx1, __shfl_xor_sync(0xffffffffu, mx1, 1));
        mx1 = hmax2u(mx1, __shfl_xor_sync(0xffffffffu, mx1, 2));
        float2 f0 = unpack2h(mx0);
        float2 f1 = unpack2h(mx1);
        float cm0 = fmaxf(f0.x, f0.y);
        float cm1 = fmaxf(f1.x, f1.y);

        float nm0 = fmaxf(m0, cm0), nm1 = fmaxf(m1, cm1);
        float al0 = ex2(m0 - nm0),  al1 = ex2(m1 - nm1);
        m0 = nm0; m1 = nm1;

        uint32_t nm0h, nm1h;
        {
            __half2 t0 = __float2half2_rn(nm0);
            __half2 t1 = __float2half2_rn(nm1);
            nm0h = *reinterpret_cast<uint32_t*>(&t0);
            nm1h = *reinterpret_cast<uint32_t*>(&t1);
        }

        // P fragments directly in packed half2 (a-fragment layout)
        uint32_t pf[4][4];
        #pragma unroll
        for (int ks = 0; ks < 4; ks++) {
            pf[ks][0] = ex2h2(hsub2u(sh2[2 * ks][0],     nm0h));
            pf[ks][1] = ex2h2(hsub2u(sh2[2 * ks][1],     nm1h));
            pf[ks][2] = ex2h2(hsub2u(sh2[2 * ks + 1][0], nm0h));
            pf[ks][3] = ex2h2(hsub2u(sh2[2 * ks + 1][1], nm1h));
        }

        // row sums via ones-MMA (exact fp32, cross-lane built in)
        float rsacc[4] = {0.f, 0.f, 0.f, 0.f};
        #pragma unroll
        for (int ks = 0; ks < 4; ks++)
            mma16816h(rsacc, pf[ks], ones_b);
        l0 = l0 * al0 + rsacc[0];
        l1 = l1 * al1 + rsacc[2];

        #pragma unroll
        for (int j = 0; j < 8; j++) {
            o[j][0] *= al0; o[j][1] *= al0;
            o[j][2] *= al1; o[j][3] *= al1;
        }

        // O += P V
        {
            uint32_t vhb[2][4];
            ldsm4(vhb[0], kb + A_VH + ASWZ(brow_l, bseg_l));
            #pragma unroll
            for (int it = 0; it < 16; it++) {
                const int ks = it >> 2, nt = it & 3;
                if (it < 15) {
                    const int ks2 = (it + 1) >> 2, nt2 = (it + 1) & 3;
                    ldsm4(vhb[(it + 1) & 1],
                          kb + A_VH + ASWZ(nt2 * 16 + brow_l, ks2 * 2 + bseg_l));
                }
                const uint32_t* vh4 = vhb[it & 1];
                mma16816h(o[2 * nt],     pf[ks], vh4);
                mma16816h(o[2 * nt + 1], pf[ks], vh4 + 2);
            }
        }
    }

    float inv0 = 1.0f / l0, inv1 = 1.0f / l1;
    int r0   = warp * 16 + (lane >> 2);
    int tok0 = qt * 128 + r0;
    int colb = h * HD + (lane & 3) * 2;
    size_t row0a = (size_t)(tok0 * 2 + b) * EMB;
    size_t row1a = (size_t)((tok0 + 8) * 2 + b) * EMB;
    #pragma unroll
    for (int j = 0; j < 8; j++) {
        int col = colb + 8 * j;
        *(uint32_t*)(g_ch + row0a + col) = pack2h(o[j][0] * inv0, o[j][1] * inv0);
        *(uint32_t*)(g_ch + row1a + col) = pack2h(o[j][2] * inv1, o[j][3] * inv1);
    }
}

// ---------------------------------------------------------------------------
// Launch
// ---------------------------------------------------------------------------
extern "C" void kernel_launch(void* const* d_in, const int* in_sizes, int n_in,
                              void* d_out, int out_size)
{
    const float* seq   = (const float*)d_in[0];
    const float* w_qkv = (const float*)d_in[1];
    const float* b_qkv = (const float*)d_in[2];
    const float* w_out = (const float*)d_in[3];
    const float* b_out = (const float*)d_in[4];
    float* out = (float*)d_out;

    __half *sh, *wq, *wo, *ch;
    cudaGetSymbolAddress((void**)&sh, g_sh);
    cudaGetSymbolAddress((void**)&wq, g_wq);
    cudaGetSymbolAddress((void**)&wo, g_wo);
    cudaGetSymbolAddress((void**)&ch, g_ch);

    cudaFuncSetAttribute(gemm_mma_kernel,
                         cudaFuncAttributeMaxDynamicSharedMemorySize, GSMEM);
    cudaFuncSetAttribute(attn_mma_kernel,
                         cudaFuncAttributeMaxDynamicSharedMemorySize, ATTN_SMEM);

    // 0) fused convert: seq + w_qkv + w_out -> fp16 (1 kernel)
    {
        int ntot = N4_SEQ + N4_WQ + N4_WO;
        convert_all_kernel<<<(ntot + 255) / 256, 256>>>(
            (const float4*)seq, (const float4*)w_qkv, (const float4*)w_out);
    }

    // 1) QKV projection -> fp16 Q (scaled), fp16 K, fp16 V
    gemm_mma_kernel<<<dim3(F3 / 128, MROWS / 128), 256, GSMEM>>>(
        sh, wq, b_qkv, nullptr, F3, EMB, 1);

    // 2) transpose V into [bh][d][tok]
    vtrans_kernel<<<dim3(NTOK / 64, BSZ * NH), 128>>>();

    // 3) fused flash attention -> fp16 ctx
    attn_mma_kernel<<<dim3(NTOK / 128, BSZ * NH), 256, ATTN_SMEM>>>();

    // 4) output projection -> fp32 out
    gemm_mma_kernel<<<dim3(EMB / 128, MROWS / 128), 256, GSMEM>>>(
        ch, wo, b_out, out, EMB, EMB, 0);
}

// round 13
// speedup vs baseline: 6.7850x; 1.0229x over previous
#include <cuda_runtime.h>
#include <cuda_bf16.h>
#include <cuda_fp16.h>
#include <math_constants.h>
#include <cstdint>

// Problem constants
#define NTOK 2048
#define BSZ  2
#define EMB  1024
#define NH   16
#define HD   64
#define MROWS (NTOK*BSZ)      // 4096
#define F3   (3*EMB)          // 3072
#define QSCALE 0.1803368801111204f   // 0.125 * log2(e)

// -------------------- device scratch (allocation-free) ----------------------
__device__ __half g_sh[(size_t)MROWS * EMB];   // seq fp16 (1-pass)
__device__ __half g_wq[(size_t)F3 * EMB];      // w_qkv fp16 (1-pass)
__device__ __half g_wo[(size_t)EMB * EMB];     // w_out fp16 (1-pass)
__device__ __half g_qf[(size_t)MROWS * EMB];   // Q fp16 (pre-scaled)
__device__ __half g_kf[(size_t)MROWS * EMB];   // K fp16
__device__ __half g_vh0[(size_t)MROWS * EMB];  // V fp16 (token-major)
__device__ __half g_ch[(size_t)MROWS * EMB];   // attn out fp16 (1-pass)

// -------------------- PTX helpers -------------------------------------------
__device__ __forceinline__ uint32_t s2u(const void* p) {
    uint32_t a;
    asm("{ .reg .u64 t; cvta.to.shared.u64 t, %1; cvt.u32.u64 %0, t; }"
        : "=r"(a) : "l"(p));
    return a;
}

__device__ __forceinline__ void cp16(uint32_t dst, const void* src) {
    asm volatile("cp.async.cg.shared.global [%0], [%1], 16;"
                 :: "r"(dst), "l"(src) : "memory");
}
#define CP_COMMIT() asm volatile("cp.async.commit_group;" ::: "memory")

__device__ __forceinline__ void ldsm4(uint32_t* r, uint32_t a) {
    asm volatile("ldmatrix.sync.aligned.m8n8.x4.shared.b16 {%0,%1,%2,%3}, [%4];"
                 : "=r"(r[0]), "=r"(r[1]), "=r"(r[2]), "=r"(r[3]) : "r"(a));
}

// transposing variant (V: token-major smem -> B fragments)
__device__ __forceinline__ void ldsm4t(uint32_t* r, uint32_t a) {
    asm volatile("ldmatrix.sync.aligned.m8n8.x4.trans.shared.b16 {%0,%1,%2,%3}, [%4];"
                 : "=r"(r[0]), "=r"(r[1]), "=r"(r[2]), "=r"(r[3]) : "r"(a));
}

// fp32-accumulate HMMA
__device__ __forceinline__ void mma16816h(float* c, const uint32_t* a,
                                           const uint32_t* b) {
    asm volatile(
        "mma.sync.aligned.m16n8k16.row.col.f32.f16.f16.f32 "
        "{%0,%1,%2,%3}, {%4,%5,%6,%7}, {%8,%9}, {%0,%1,%2,%3};"
        : "+f"(c[0]), "+f"(c[1]), "+f"(c[2]), "+f"(c[3])
        : "r"(a[0]), "r"(a[1]), "r"(a[2]), "r"(a[3]), "r"(b[0]), "r"(b[1]));
}

// fp16-accumulate HMMA (QK logits)
__device__ __forceinline__ void mma16816hh(uint32_t* c, const uint32_t* a,
                                            const uint32_t* b) {
    asm volatile(
        "mma.sync.aligned.m16n8k16.row.col.f16.f16.f16.f16 "
        "{%0,%1}, {%2,%3,%4,%5}, {%6,%7}, {%0,%1};"
        : "+r"(c[0]), "+r"(c[1])
        : "r"(a[0]), "r"(a[1]), "r"(a[2]), "r"(a[3]), "r"(b[0]), "r"(b[1]));
}

__device__ __forceinline__ float ex2(float x) {
    float y;
    asm("ex2.approx.f32 %0, %1;" : "=f"(y) : "f"(x));
    return y;
}

__device__ __forceinline__ uint32_t hmax2u(uint32_t a, uint32_t b) {
    uint32_t d;
    asm("max.f16x2 %0, %1, %2;" : "=r"(d) : "r"(a), "r"(b));
    return d;
}

__device__ __forceinline__ uint32_t hsub2u(uint32_t a, uint32_t b) {
    uint32_t d;
    asm("sub.f16x2 %0, %1, %2;" : "=r"(d) : "r"(a), "r"(b));
    return d;
}

__device__ __forceinline__ uint32_t ex2h2(uint32_t a) {
    uint32_t d;
    asm("ex2.approx.f16x2 %0, %1;" : "=r"(d) : "r"(a));
    return d;
}

__device__ __forceinline__ uint32_t pack2h(float a, float b) {
    __half2 t = __floats2half2_rn(a, b);
    return *reinterpret_cast<uint32_t*>(&t);
}

__device__ __forceinline__ float2 unpack2h(uint32_t u) {
    __half2 t = *reinterpret_cast<__half2*>(&u);
    return __half22float2(t);
}

// -------------------- fused convert: 3 arrays fp32 -> fp16 ------------------
#define N4_SEQ (MROWS * EMB / 4)
#define N4_WQ  (F3 * EMB / 4)
#define N4_WO  (EMB * EMB / 4)

__global__ void convert_all_kernel(const float4* __restrict__ seq,
                                   const float4* __restrict__ wq,
                                   const float4* __restrict__ wo) {
    int i = blockIdx.x * blockDim.x + threadIdx.x;
    const float4* src;
    uint2* dst;
    int k;
    if (i < N4_SEQ) {
        src = seq; dst = (uint2*)g_sh; k = i;
    } else if (i < N4_SEQ + N4_WQ) {
        src = wq; dst = (uint2*)g_wq; k = i - N4_SEQ;
    } else if (i < N4_SEQ + N4_WQ + N4_WO) {
        src = wo; dst = (uint2*)g_wo; k = i - N4_SEQ - N4_WQ;
    } else return;
    float4 x = src[k];
    uint2 o;
    o.x = pack2h(x.x, x.y);
    o.y = pack2h(x.z, x.w);
    dst[k] = o;
}

// -------------------- fp16 1-pass GEMM, K-chunk 32 ---------------------------
// C = A[M][K] * B[N][K]^T + bias[N]; CTA 128x128, 8 warps (32x64 warp tile).
// qkvmode=0: C fp32.  qkvmode=1: N=3072; comp0->g_qf(xQSCALE), comp1->g_kf,
// comp2->g_vh0 (fp16).
#define PITCH  80
#define TILEB  (128 * PITCH)       // 10240
#define STAGEB (2 * TILEB)         // 20480: A, B
#define GSTG   4
#define GSMEM  (GSTG * STAGEB)     // 81920 -> 2 CTAs/SM

#define ARR_A  0
#define ARR_B  TILEB

__global__ void __launch_bounds__(256, 2) gemm_mma_kernel(
    const __half* __restrict__ A, const __half* __restrict__ B,
    const float* __restrict__ bias, float* __restrict__ C,
    int N, int K, int qkvmode)
{
    extern __shared__ char smem[];
    const uint32_t sb = s2u(smem);
    const int tid  = threadIdx.x;
    const int lane = tid & 31;
    const int warp = tid >> 5;
    const int wm   = warp & 3;
    const int wn   = warp >> 2;
    const int row0 = blockIdx.y * 128;
    const int col0 = blockIdx.x * 128;

    float acc[2][8][4];
    #pragma unroll
    for (int i = 0; i < 2; i++)
        #pragma unroll
        for (int j = 0; j < 8; j++)
            #pragma unroll
            for (int v = 0; v < 4; v++) acc[i][j][v] = 0.f;

    const uint32_t a_off = (uint32_t)(lane & 15) * PITCH + (lane >> 4) * 16;
    const uint32_t b_off = (uint32_t)((lane & 7) + ((lane >> 4) & 1) * 8) * PITCH
                         + ((lane >> 3) & 1) * 16;

    const int pr   = tid >> 1;
    const int pseg = (tid & 1) * 2;
    const int nch  = K / 32;

    #define PRODUCE(c)                                                        \
    do {                                                                      \
        uint32_t base = sb + (uint32_t)((c) & 3) * STAGEB;                    \
        size_t gA = (size_t)(row0 + pr) * K + (c) * 32 + pseg * 8;            \
        size_t gB = (size_t)(col0 + pr) * K + (c) * 32 + pseg * 8;            \
        uint32_t so = (uint32_t)pr * PITCH + pseg * 16;                       \
        cp16(base + ARR_A + so,      A + gA);                                 \
        cp16(base + ARR_A + so + 16, A + gA + 8);                             \
        cp16(base + ARR_B + so,      B + gB);                                 \
        cp16(base + ARR_B + so + 16, B + gB + 8);                             \
    } while (0)

    PRODUCE(0); CP_COMMIT();
    PRODUCE(1); CP_COMMIT();
    PRODUCE(2); CP_COMMIT();

    for (int c = 0; c < nch; c++) {
        asm volatile("cp.async.wait_group 2;" ::: "memory");
        __syncthreads();

        if (c + 3 < nch) PRODUCE(c + 3);
        CP_COMMIT();

        const uint32_t st = sb + (uint32_t)(c & 3) * STAGEB;

        #pragma unroll
        for (int ks = 0; ks < 2; ks++) {
            const uint32_t brow = ARR_B + (uint32_t)(wn * 64) * PITCH
                                + ks * 32 + b_off;
            uint32_t ah[2][4], bfr[2][4];
            ldsm4(bfr[0], st + brow);
            #pragma unroll
            for (int mt = 0; mt < 2; mt++) {
                uint32_t ra = (uint32_t)(wm * 32 + mt * 16) * PITCH
                            + ks * 32 + a_off;
                ldsm4(ah[mt], st + ARR_A + ra);
            }
            #pragma unroll
            for (int nt = 0; nt < 4; nt++) {
                if (nt < 3)
                    ldsm4(bfr[(nt + 1) & 1],
                          st + brow + (uint32_t)((nt + 1) * 16) * PITCH);
                const uint32_t* b4 = bfr[nt & 1];
                mma16816h(acc[0][2 * nt],     ah[0], b4);
                mma16816h(acc[1][2 * nt],     ah[1], b4);
                mma16816h(acc[0][2 * nt + 1], ah[0], b4 + 2);
                mma16816h(acc[1][2 * nt + 1], ah[1], b4 + 2);
            }
        }
    }

    const int tr = lane >> 2;
    const int tc = (lane & 3) * 2;
    const int comp = col0 >> 10;
    #pragma unroll
    for (int mt = 0; mt < 2; mt++) {
        #pragma unroll
        for (int n8 = 0; n8 < 8; n8++) {
            int r  = row0 + wm * 32 + mt * 16 + tr;
            int cc = col0 + wn * 64 + n8 * 8 + tc;
            float b0 = bias[cc], b1 = bias[cc + 1];
            float v0 = acc[mt][n8][0] + b0;
            float v1 = acc[mt][n8][1] + b1;
            float v2 = acc[mt][n8][2] + b0;
            float v3 = acc[mt][n8][3] + b1;
            if (qkvmode) {
                int ccl = cc - (comp << 10);
                size_t o0 = (size_t)r * EMB + ccl;
                size_t o1 = (size_t)(r + 8) * EMB + ccl;
                if (comp == 0) {
                    *(uint32_t*)(g_qf + o0) = pack2h(v0 * QSCALE, v1 * QSCALE);
                    *(uint32_t*)(g_qf + o1) = pack2h(v2 * QSCALE, v3 * QSCALE);
                } else if (comp == 1) {
                    *(uint32_t*)(g_kf + o0) = pack2h(v0, v1);
                    *(uint32_t*)(g_kf + o1) = pack2h(v2, v3);
                } else {
                    *(uint32_t*)(g_vh0 + o0) = pack2h(v0, v1);
                    *(uint32_t*)(g_vh0 + o1) = pack2h(v2, v3);
                }
            } else {
                *(float2*)(C + (size_t)r * N + cc)       = make_float2(v0, v1);
                *(float2*)(C + (size_t)(r + 8) * N + cc) = make_float2(v2, v3);
            }
        }
    }
}

// -------------------- flash attention (ldsm.trans V, fp32 row sums) ---------
#define AQ    0
#define ABUF  16384
#define ASTG  16384                 // K 8KB + V 8KB
#define A_K   0
#define A_VH  8192
#define ASTAGES 3
#define ATTN_SMEM (ABUF + ASTAGES * ASTG)   // 65536 -> 2 CTAs/SM

#define ASWZ(row, seg) ((uint32_t)(row) * 128 + ((uint32_t)((seg) ^ ((row) & 7)) * 16))

__global__ void __launch_bounds__(256, 2) attn_mma_kernel()
{
    extern __shared__ char smem[];
    const uint32_t sb = s2u(smem);
    const int tid  = threadIdx.x;
    const int lane = tid & 31;
    const int warp = tid >> 5;
    const int qt = blockIdx.x;
    const int bh = blockIdx.y;
    const int b  = bh & 1;
    const int h  = bh >> 1;

    {
        int prow = tid >> 1;
        int psb  = (tid & 1) * 4;
        int qtok = qt * 128 + prow;
        size_t gq = (size_t)(qtok * 2 + b) * EMB + h * HD + psb * 8;
        #pragma unroll
        for (int j = 0; j < 4; j++)
            cp16(sb + AQ + ASWZ(prow, psb + j), g_qf + gq + j * 8);
    }

    const int prow = tid >> 2;
    const int ps2  = (tid & 3) * 2;

    // K and V both token-major in smem (V transposed at ldsm time)
    #define APROD(kt)                                                         \
    do {                                                                      \
        uint32_t bufb = sb + ABUF + (uint32_t)((kt) % ASTAGES) * ASTG;        \
        int tok = (kt) * 64 + prow;                                           \
        size_t g = (size_t)(tok * 2 + b) * EMB + h * HD;                      \
        _Pragma("unroll")                                                     \
        for (int j = 0; j < 2; j++) {                                         \
            int seg = ps2 + j;                                                \
            uint32_t o = ASWZ(prow, seg);                                     \
            cp16(bufb + A_K  + o, g_kf  + g + seg * 8);                       \
            cp16(bufb + A_VH + o, g_vh0 + g + seg * 8);                       \
        }                                                                     \
    } while (0)

    APROD(0); CP_COMMIT();
    APROD(1); CP_COMMIT();

    float o[8][4];
    #pragma unroll
    for (int j = 0; j < 8; j++)
        #pragma unroll
        for (int v = 0; v < 4; v++) o[j][v] = 0.f;
    float m0 = -CUDART_INF_F, m1 = -CUDART_INF_F, l0 = 0.f, l1 = 0.f;
    uint32_t qf[4][4];

    const int brow_l = (lane & 7) + ((lane >> 4) & 1) * 8;  // K (non-trans)
    const int bseg_l = (lane >> 3) & 1;
    const int trow_l = lane & 15;                            // V (trans)
    const int tseg_l = lane >> 4;

    const int NKT = NTOK / 64;
    for (int kt = 0; kt < NKT; kt++) {
        asm volatile("cp.async.wait_group 1;" ::: "memory");
        __syncthreads();

        if (kt + 2 < NKT) APROD(kt + 2);
        CP_COMMIT();

        const uint32_t kb = sb + ABUF + (uint32_t)(kt % ASTAGES) * ASTG;

        if (kt == 0) {
            #pragma unroll
            for (int ks = 0; ks < 4; ks++) {
                int row = warp * 16 + (lane & 15);
                int seg = ks * 2 + (lane >> 4);
                ldsm4(qf[ks], sb + AQ + ASWZ(row, seg));
            }
        }

        // S = Q K^T with fp16 accumulators
        uint32_t sh2[8][2];
        #pragma unroll
        for (int j = 0; j < 8; j++) { sh2[j][0] = 0u; sh2[j][1] = 0u; }

        {
            uint32_t kbf[2][4];
            ldsm4(kbf[0], kb + A_K + ASWZ(brow_l, bseg_l));
            #pragma unroll
            for (int it = 0; it < 16; it++) {
                const int ks = it >> 2, nt = it & 3;
                if (it < 15) {
                    const int ks2 = (it + 1) >> 2, nt2 = (it + 1) & 3;
                    ldsm4(kbf[(it + 1) & 1],
                          kb + A_K + ASWZ(nt2 * 16 + brow_l, ks2 * 2 + bseg_l));
                }
                const uint32_t* k4 = kbf[it & 1];
                mma16816hh(sh2[2 * nt],     qf[ks], k4);
                mma16816hh(sh2[2 * nt + 1], qf[ks], k4 + 2);
            }
        }

        // row maxes (packed f16x2 tree + cross-lane)
        uint32_t mx0 = sh2[0][0], mx1 = sh2[0][1];
        #pragma unroll
        for (int j = 1; j < 8; j++) {
            mx0 = hmax2u(mx0, sh2[j][0]);
            mx1 = hmax2u(mx1, sh2[j][1]);
        }
        mx0 = hmax2u(mx0, __shfl_xor_sync(0xffffffffu, mx0, 1));
        mx0 = hmax2u(mx0, __shfl_xor_sync(0xffffffffu, mx0, 2));
        mx1 = hmax2u(mx1, __shfl_xor_sync(0xffffffffu, mx1, 1));
        mx1 = hmax2u(mx1, __shfl_xor_sync(0xffffffffu, mx1, 2));
        float2 f0 = unpack2h(mx0);
        float2 f1 = unpack2h(mx1);
        float cm0 = fmaxf(f0.x, f0.y);
        float cm1 = fmaxf(f1.x, f1.y);

        float nm0 = fmaxf(m0, cm0), nm1 = fmaxf(m1, cm1);
        float al0 = ex2(m0 - nm0),  al1 = ex2(m1 - nm1);
        m0 = nm0; m1 = nm1;

        uint32_t nm0h, nm1h;
        {
            __half2 t0 = __float2half2_rn(nm0);
            __half2 t1 = __float2half2_rn(nm1);
            nm0h = *reinterpret_cast<uint32_t*>(&t0);
            nm1h = *reinterpret_cast<uint32_t*>(&t1);
        }

        // P fragments in packed half2 (a-fragment layout)
        uint32_t pf[4][4];
        #pragma unroll
        for (int ks = 0; ks < 4; ks++) {
            pf[ks][0] = ex2h2(hsub2u(sh2[2 * ks][0],     nm0h));
            pf[ks][1] = ex2h2(hsub2u(sh2[2 * ks][1],     nm1h));
            pf[ks][2] = ex2h2(hsub2u(sh2[2 * ks + 1][0], nm0h));
            pf[ks][3] = ex2h2(hsub2u(sh2[2 * ks + 1][1], nm1h));
        }

        // row sums: unpack to fp32 (exact; runs on FMA pipe, overlaps MMA)
        float rs0 = 0.f, rs1 = 0.f;
        #pragma unroll
        for (int ks = 0; ks < 4; ks++) {
            float2 a0 = unpack2h(pf[ks][0]);
            float2 a2 = unpack2h(pf[ks][2]);
            rs0 += (a0.x + a0.y) + (a2.x + a2.y);
            float2 a1 = unpack2h(pf[ks][1]);
            float2 a3 = unpack2h(pf[ks][3]);
            rs1 += (a1.x + a1.y) + (a3.x + a3.y);
        }
        rs0 += __shfl_xor_sync(0xffffffffu, rs0, 1);
        rs0 += __shfl_xor_sync(0xffffffffu, rs0, 2);
        rs1 += __shfl_xor_sync(0xffffffffu, rs1, 1);
        rs1 += __shfl_xor_sync(0xffffffffu, rs1, 2);
        l0 = l0 * al0 + rs0;
        l1 = l1 * al1 + rs1;

        #pragma unroll
        for (int j = 0; j < 8; j++) {
            o[j][0] *= al0; o[j][1] *= al0;
            o[j][2] *= al1; o[j][3] *= al1;
        }

        // O += P V  (V loaded token-major, transposed by ldsm.trans)
        {
            uint32_t vhb[2][4];
            ldsm4t(vhb[0], kb + A_VH + ASWZ(trow_l, tseg_l));
            #pragma unroll
            for (int it = 0; it < 16; it++) {
                const int ks = it >> 2, nt = it & 3;
                if (it < 15) {
                    const int ks2 = (it + 1) >> 2, nt2 = (it + 1) & 3;
                    ldsm4t(vhb[(it + 1) & 1],
                           kb + A_VH + ASWZ(ks2 * 16 + trow_l, nt2 * 2 + tseg_l));
                }
                const uint32_t* vh4 = vhb[it & 1];
                mma16816h(o[2 * nt],     pf[ks], vh4);
                mma16816h(o[2 * nt + 1], pf[ks], vh4 + 2);
            }
        }
    }

    float inv0 = 1.0f / l0, inv1 = 1.0f / l1;
    int r0   = warp * 16 + (lane >> 2);
    int tok0 = qt * 128 + r0;
    int colb = h * HD + (lane & 3) * 2;
    size_t row0a = (size_t)(tok0 * 2 + b) * EMB;
    size_t row1a = (size_t)((tok0 + 8) * 2 + b) * EMB;
    #pragma unroll
    for (int j = 0; j < 8; j++) {
        int col = colb + 8 * j;
        *(uint32_t*)(g_ch + row0a + col) = pack2h(o[j][0] * inv0, o[j][1] * inv0);
        *(uint32_t*)(g_ch + row1a + col) = pack2h(o[j][2] * inv1, o[j][3] * inv1);
    }
}

// ---------------------------------------------------------------------------
// Launch
// ---------------------------------------------------------------------------
extern "C" void kernel_launch(void* const* d_in, const int* in_sizes, int n_in,
                              void* d_out, int out_size)
{
    const float* seq   = (const float*)d_in[0];
    const float* w_qkv = (const float*)d_in[1];
    const float* b_qkv = (const float*)d_in[2];
    const float* w_out = (const float*)d_in[3];
    const float* b_out = (const float*)d_in[4];
    float* out = (float*)d_out;

    __half *sh, *wq, *wo, *ch;
    cudaGetSymbolAddress((void**)&sh, g_sh);
    cudaGetSymbolAddress((void**)&wq, g_wq);
    cudaGetSymbolAddress((void**)&wo, g_wo);
    cudaGetSymbolAddress((void**)&ch, g_ch);

    cudaFuncSetAttribute(gemm_mma_kernel,
                         cudaFuncAttributeMaxDynamicSharedMemorySize, GSMEM);
    cudaFuncSetAttribute(attn_mma_kernel,
                         cudaFuncAttributeMaxDynamicSharedMemorySize, ATTN_SMEM);

    // 0) fused convert: seq + w_qkv + w_out -> fp16 (1 kernel)
    {
        int ntot = N4_SEQ + N4_WQ + N4_WO;
        convert_all_kernel<<<(ntot + 255) / 256, 256>>>(
            (const float4*)seq, (const float4*)w_qkv, (const float4*)w_out);
    }

    // 1) QKV projection -> fp16 Q (scaled), fp16 K, fp16 V (all token-major)
    gemm_mma_kernel<<<dim3(F3 / 128, MROWS / 128), 256, GSMEM>>>(
        sh, wq, b_qkv, nullptr, F3, EMB, 1);

    // 2) fused flash attention -> fp16 ctx (V transposed in-kernel via ldsm.trans)
    attn_mma_kernel<<<dim3(NTOK / 128, BSZ * NH), 256, ATTN_SMEM>>>();

    // 3) output projection -> fp32 out
    gemm_mma_kernel<<<dim3(EMB / 128, MROWS / 128), 256, GSMEM>>>(
        ch, wo, b_out, out, EMB, EMB, 0);
}